// round 2
// baseline (speedup 1.0000x reference)
#include <cuda_runtime.h>
#include <math.h>

// Problem-fixed maxima (setup_inputs: N=50000, E=800000)
#define NMAXC 50000
#define EMAXC 800000

// ---------------- scratch (static __device__ — no allocs allowed) ----------------
__device__ float g_concat[NMAXC * 192];
__device__ float g_h[NMAXC * 128];
__device__ float g_res[NMAXC * 128];
__device__ float g_el[NMAXC * 2];
__device__ float g_er[NMAXC * 2];
__device__ float g_alpha[EMAXC * 2];
__device__ float g_s1[NMAXC * 128];
__device__ float g_s2[NMAXC * 128];
__device__ float g_p1[NMAXC * 64];
__device__ float g_sfin[NMAXC * 128];
__device__ int g_deg[NMAXC];
__device__ int g_off[NMAXC + 1];
__device__ int g_fill[NMAXC];
__device__ int g_csrsrc[EMAXC];

// ---------------- CSR build ----------------
__global__ void zero_kernel(int* p, int n) {
    int i = blockIdx.x * blockDim.x + threadIdx.x;
    if (i < n) p[i] = 0;
}

__global__ void count_kernel(const int* __restrict__ dst, int* __restrict__ deg, int e) {
    for (int i = blockIdx.x * blockDim.x + threadIdx.x; i < e; i += gridDim.x * blockDim.x)
        atomicAdd(&deg[dst[i]], 1);
}

__global__ __launch_bounds__(1024) void scan_kernel(const int* __restrict__ deg,
                                                    int* __restrict__ off,
                                                    int* __restrict__ fill, int n) {
    __shared__ int sums[1024];
    int t = threadIdx.x;
    int chunk = (n + 1023) / 1024;
    int begin = t * chunk;
    int end = begin + chunk;
    if (end > n) end = n;
    if (begin > n) begin = n;
    int s = 0;
    for (int i = begin; i < end; i++) s += deg[i];
    sums[t] = s;
    __syncthreads();
    // inclusive Hillis-Steele scan
    for (int d = 1; d < 1024; d <<= 1) {
        int v = (t >= d) ? sums[t - d] : 0;
        __syncthreads();
        sums[t] += v;
        __syncthreads();
    }
    int run = (t == 0) ? 0 : sums[t - 1];
    for (int i = begin; i < end; i++) {
        off[i] = run;
        fill[i] = run;
        run += deg[i];
    }
    if (t == 1023) off[n] = sums[1023];
}

__global__ void scatter_kernel(const int* __restrict__ src, const int* __restrict__ dst,
                               int* __restrict__ fill, int* __restrict__ csrsrc, int e) {
    for (int i = blockIdx.x * blockDim.x + threadIdx.x; i < e; i += gridDim.x * blockDim.x) {
        int pos = atomicAdd(&fill[dst[i]], 1);
        csrsrc[pos] = src[i];
    }
}

// ---------------- concat ----------------
__global__ void concat_kernel(const float* __restrict__ a, int Fa,
                              const float* __restrict__ b, int Fb,
                              float* __restrict__ out, int n) {
    int F = Fa + Fb;
    long total = (long)n * F;
    for (long i = blockIdx.x * (long)blockDim.x + threadIdx.x; i < total;
         i += (long)gridDim.x * blockDim.x) {
        int node = (int)(i / F);
        int j = (int)(i - (long)node * F);
        out[i] = (j < Fa) ? a[(long)node * Fa + j] : b[(long)node * Fb + (j - Fa)];
    }
}

// ---------------- tiled fp32 GEMM: C[n,M] = A[n,K] @ W[K,M] ----------------
__global__ __launch_bounds__(256) void gemm_kernel(const float* __restrict__ A,
                                                   const float* __restrict__ W,
                                                   float* __restrict__ C,
                                                   int nrows, int K, int M) {
    const int BM = 64, BN = 64, BK = 16;
    __shared__ float As[BK][BM + 1];
    __shared__ float Ws[BK][BN + 1];
    int tid = threadIdx.x;
    int bm = blockIdx.x * BM, bn = blockIdx.y * BN;
    int tx = tid & 15, ty = tid >> 4;
    float acc[4][4] = {};
    for (int k0 = 0; k0 < K; k0 += BK) {
#pragma unroll
        for (int i = 0; i < (BM * BK) / 256; i++) {
            int idx = i * 256 + tid;
            int m = idx / BK, kk = idx % BK;
            int row = bm + m;
            As[kk][m] = (row < nrows) ? A[(size_t)row * K + k0 + kk] : 0.f;
        }
#pragma unroll
        for (int i = 0; i < (BK * BN) / 256; i++) {
            int idx = i * 256 + tid;
            int kk = idx / BN, nn = idx % BN;
            Ws[kk][nn] = W[(size_t)(k0 + kk) * M + bn + nn];
        }
        __syncthreads();
#pragma unroll
        for (int kk = 0; kk < BK; kk++) {
            float a[4], b[4];
#pragma unroll
            for (int i = 0; i < 4; i++) a[i] = As[kk][ty * 4 + i];
#pragma unroll
            for (int j = 0; j < 4; j++) b[j] = Ws[kk][tx * 4 + j];
#pragma unroll
            for (int i = 0; i < 4; i++)
#pragma unroll
                for (int j = 0; j < 4; j++) acc[i][j] = fmaf(a[i], b[j], acc[i][j]);
        }
        __syncthreads();
    }
#pragma unroll
    for (int i = 0; i < 4; i++) {
        int row = bm + ty * 4 + i;
        if (row < nrows) {
#pragma unroll
            for (int j = 0; j < 4; j++)
                C[(size_t)row * M + bn + tx * 4 + j] = acc[i][j];
        }
    }
}

// ---------------- attention logits per node: el/er [N,2] ----------------
__global__ void eler_kernel(const float* __restrict__ h, const float* __restrict__ al,
                            const float* __restrict__ ar, float* __restrict__ el,
                            float* __restrict__ er, int n, int D) {
    int i = blockIdx.x * blockDim.x + threadIdx.x;
    if (i >= n * 2) return;
    int node = i >> 1, hh = i & 1;
    const float* row = h + (size_t)node * (2 * D) + hh * D;
    const float* a = al + hh * D;
    const float* b = ar + hh * D;
    float s1 = 0.f, s2 = 0.f;
    for (int d = 0; d < D; d++) {
        float v = row[d];
        s1 = fmaf(v, a[d], s1);
        s2 = fmaf(v, b[d], s2);
    }
    el[i] = s1;
    er[i] = s2;
}

// ---------------- per-dst edge softmax (warp per node, both heads) ----------------
__global__ __launch_bounds__(256) void alpha_kernel(const float* __restrict__ el,
                                                    const float* __restrict__ er,
                                                    const int* __restrict__ off,
                                                    const int* __restrict__ csr,
                                                    float* __restrict__ alpha, int n) {
    int warp = (blockIdx.x * blockDim.x + threadIdx.x) >> 5;
    int lane = threadIdx.x & 31;
    if (warp >= n) return;
    int start = off[warp], end = off[warp + 1];
    float er0 = er[warp * 2 + 0], er1 = er[warp * 2 + 1];
    float m0 = -1e30f, m1 = -1e30f;
    for (int i = start + lane; i < end; i += 32) {
        int s = csr[i];
        float e0 = el[s * 2 + 0] + er0;
        e0 = e0 > 0.f ? e0 : 0.2f * e0;
        float e1 = el[s * 2 + 1] + er1;
        e1 = e1 > 0.f ? e1 : 0.2f * e1;
        m0 = fmaxf(m0, e0);
        m1 = fmaxf(m1, e1);
    }
#pragma unroll
    for (int o = 16; o; o >>= 1) {
        m0 = fmaxf(m0, __shfl_xor_sync(0xffffffffu, m0, o));
        m1 = fmaxf(m1, __shfl_xor_sync(0xffffffffu, m1, o));
    }
    float s0 = 0.f, s1 = 0.f;
    for (int i = start + lane; i < end; i += 32) {
        int s = csr[i];
        float e0 = el[s * 2 + 0] + er0;
        e0 = e0 > 0.f ? e0 : 0.2f * e0;
        float e1 = el[s * 2 + 1] + er1;
        e1 = e1 > 0.f ? e1 : 0.2f * e1;
        s0 += expf(e0 - m0);
        s1 += expf(e1 - m1);
    }
#pragma unroll
    for (int o = 16; o; o >>= 1) {
        s0 += __shfl_xor_sync(0xffffffffu, s0, o);
        s1 += __shfl_xor_sync(0xffffffffu, s1, o);
    }
    float inv0 = (s0 > 0.f) ? 1.f / s0 : 0.f;
    float inv1 = (s1 > 0.f) ? 1.f / s1 : 0.f;
    for (int i = start + lane; i < end; i += 32) {
        int s = csr[i];
        float e0 = el[s * 2 + 0] + er0;
        e0 = e0 > 0.f ? e0 : 0.2f * e0;
        float e1 = el[s * 2 + 1] + er1;
        e1 = e1 > 0.f ? e1 : 0.2f * e1;
        alpha[i * 2 + 0] = expf(e0 - m0) * inv0;
        alpha[i * 2 + 1] = expf(e1 - m1) * inv1;
    }
}

// ---------------- weighted aggregation + residual + activation ----------------
// warp per (node, head). ACT: 0=ELU, 1=tanh.
template <int HD, int D, int ACT>
__global__ __launch_bounds__(256) void agg_kernel(const float* __restrict__ hbuf,
                                                  const float* __restrict__ alpha,
                                                  const int* __restrict__ off,
                                                  const int* __restrict__ csr,
                                                  const float* __restrict__ resbuf,
                                                  float* __restrict__ out, int n) {
    int warp = (blockIdx.x * blockDim.x + threadIdx.x) >> 5;
    int lane = threadIdx.x & 31;
    int node = warp >> 1, head = warp & 1;
    if (node >= n) return;
    int start = off[node], end = off[node + 1];
    float acc0 = 0.f, acc1 = 0.f;
    for (int i = start; i < end; i++) {
        int s = csr[i];
        float a = alpha[i * 2 + head];
        const float* row = hbuf + (size_t)s * HD + head * D;
        acc0 = fmaf(row[lane], a, acc0);
        if (D == 64) acc1 = fmaf(row[lane + 32], a, acc1);
    }
    size_t base = (size_t)node * HD + head * D;
    float v0 = acc0 + resbuf[base + lane];
    v0 = (ACT == 0) ? (v0 > 0.f ? v0 : expm1f(v0)) : tanhf(v0);
    out[base + lane] = v0;
    if (D == 64) {
        float v1 = acc1 + resbuf[base + lane + 32];
        v1 = (ACT == 0) ? (v1 > 0.f ? v1 : expm1f(v1)) : tanhf(v1);
        out[base + lane + 32] = v1;
    }
}

// final: mean over heads of [N,2,64] -> [N,64]
__global__ void mean_kernel(const float* __restrict__ in, float* __restrict__ out, int n) {
    int i = blockIdx.x * blockDim.x + threadIdx.x;
    if (i >= n * 64) return;
    int node = i >> 6, d = i & 63;
    out[i] = 0.5f * (in[(size_t)node * 128 + d] + in[(size_t)node * 128 + 64 + d]);
}

// ---------------- host ----------------
template <typename T>
static T* symaddr(const void* sym) {
    void* p = nullptr;
    cudaGetSymbolAddress(&p, sym);
    return (T*)p;
}

extern "C" void kernel_launch(void* const* d_in, const int* in_sizes, int n_in,
                              void* d_out, int out_size) {
    const float* fvs = (const float*)d_in[0];
    const float* pos = (const float*)d_in[1];
    const int* src = (const int*)d_in[2];
    const int* dst = (const int*)d_in[3];
    const float* gW[3] = {(const float*)d_in[4], (const float*)d_in[8], (const float*)d_in[12]};
    const float* gal[3] = {(const float*)d_in[5], (const float*)d_in[9], (const float*)d_in[13]};
    const float* gar[3] = {(const float*)d_in[6], (const float*)d_in[10], (const float*)d_in[14]};
    const float* grW[3] = {(const float*)d_in[7], (const float*)d_in[11], (const float*)d_in[15]};
    const float* pW[2] = {(const float*)d_in[16], (const float*)d_in[19]};
    const float* pal[2] = {(const float*)d_in[17], (const float*)d_in[20]};
    const float* par[2] = {(const float*)d_in[18], (const float*)d_in[21]};

    int n = in_sizes[0] / 128;
    int e = in_sizes[2];
    float* out = (float*)d_out;
    float* out_hs = out;            // [N,64]
    float* out_hp = out + (size_t)n * 64;  // [N,64]

    float* concatB = symaddr<float>(g_concat);
    float* hB = symaddr<float>(g_h);
    float* resB = symaddr<float>(g_res);
    float* elB = symaddr<float>(g_el);
    float* erB = symaddr<float>(g_er);
    float* alB = symaddr<float>(g_alpha);
    float* s1B = symaddr<float>(g_s1);
    float* s2B = symaddr<float>(g_s2);
    float* p1B = symaddr<float>(g_p1);
    float* sfB = symaddr<float>(g_sfin);
    int* degB = symaddr<int>(g_deg);
    int* offB = symaddr<int>(g_off);
    int* fillB = symaddr<int>(g_fill);
    int* csrB = symaddr<int>(g_csrsrc);

    const int TB = 256;
    // ---- CSR build (by dst) ----
    zero_kernel<<<(n + TB - 1) / TB, TB>>>(degB, n);
    count_kernel<<<(e + TB - 1) / TB, TB>>>(dst, degB, e);
    scan_kernel<<<1, 1024>>>(degB, offB, fillB, n);
    scatter_kernel<<<(e + TB - 1) / TB, TB>>>(src, dst, fillB, csrB, e);

    int alpha_blocks = (n * 32 + TB - 1) / TB;
    int agg_blocks = (n * 64 + TB - 1) / TB;
    dim3 ggrid((n + 63) / 64, 2);  // M=128 GEMMs
    dim3 pgrid((n + 63) / 64, 1);  // M=64 GEMMs
    int cc_blocks = 2048;

    // ---- layer 0: gat0 on concat(fvs, pos) ----
    concat_kernel<<<cc_blocks, TB>>>(fvs, 128, pos, 64, concatB, n);
    gemm_kernel<<<ggrid, 256>>>(concatB, gW[0], hB, n, 192, 128);
    gemm_kernel<<<ggrid, 256>>>(concatB, grW[0], resB, n, 192, 128);
    eler_kernel<<<(n * 2 + TB - 1) / TB, TB>>>(hB, gal[0], gar[0], elB, erB, n, 64);
    alpha_kernel<<<alpha_blocks, TB>>>(elB, erB, offB, csrB, alB, n);
    agg_kernel<128, 64, 0><<<agg_blocks, TB>>>(hB, alB, offB, csrB, resB, s1B, n);

    // ---- pg0 on pos (identity residual, tanh) ----
    gemm_kernel<<<pgrid, 256>>>(pos, pW[0], hB, n, 64, 64);
    eler_kernel<<<(n * 2 + TB - 1) / TB, TB>>>(hB, pal[0], par[0], elB, erB, n, 32);
    alpha_kernel<<<alpha_blocks, TB>>>(elB, erB, offB, csrB, alB, n);
    agg_kernel<64, 32, 1><<<agg_blocks, TB>>>(hB, alB, offB, csrB, pos, p1B, n);

    // ---- layer 1: gat1 on concat(s1, p1) ----
    concat_kernel<<<cc_blocks, TB>>>(s1B, 128, p1B, 64, concatB, n);
    gemm_kernel<<<ggrid, 256>>>(concatB, gW[1], hB, n, 192, 128);
    gemm_kernel<<<ggrid, 256>>>(concatB, grW[1], resB, n, 192, 128);
    eler_kernel<<<(n * 2 + TB - 1) / TB, TB>>>(hB, gal[1], gar[1], elB, erB, n, 64);
    alpha_kernel<<<alpha_blocks, TB>>>(elB, erB, offB, csrB, alB, n);
    agg_kernel<128, 64, 0><<<agg_blocks, TB>>>(hB, alB, offB, csrB, resB, s2B, n);

    // ---- pg1 on p1 (identity residual, tanh) -> final h_p directly into d_out ----
    gemm_kernel<<<pgrid, 256>>>(p1B, pW[1], hB, n, 64, 64);
    eler_kernel<<<(n * 2 + TB - 1) / TB, TB>>>(hB, pal[1], par[1], elB, erB, n, 32);
    alpha_kernel<<<alpha_blocks, TB>>>(elB, erB, offB, csrB, alB, n);
    agg_kernel<64, 32, 1><<<agg_blocks, TB>>>(hB, alB, offB, csrB, p1B, out_hp, n);

    // ---- layer 2: gat2 on concat(s2, h_p) -> elu -> mean heads ----
    concat_kernel<<<cc_blocks, TB>>>(s2B, 128, out_hp, 64, concatB, n);
    gemm_kernel<<<ggrid, 256>>>(concatB, gW[2], hB, n, 192, 128);
    gemm_kernel<<<ggrid, 256>>>(concatB, grW[2], resB, n, 192, 128);
    eler_kernel<<<(n * 2 + TB - 1) / TB, TB>>>(hB, gal[2], gar[2], elB, erB, n, 64);
    alpha_kernel<<<alpha_blocks, TB>>>(elB, erB, offB, csrB, alB, n);
    agg_kernel<128, 64, 0><<<agg_blocks, TB>>>(hB, alB, offB, csrB, resB, sfB, n);
    mean_kernel<<<(n * 64 + TB - 1) / TB, TB>>>(sfB, out_hs, n);
}

// round 4
// speedup vs baseline: 1.2204x; 1.2204x over previous
#include <cuda_runtime.h>
#include <cuda_bf16.h>
#include <math.h>
#include <cstdint>

// Problem-fixed maxima (setup_inputs: N=50000, E=800000)
#define NMAXC 50000
#define EMAXC 800000

// ---------------- scratch (static __device__ — no allocs allowed) ----------------
__device__ float g_concat[NMAXC * 192];
__device__ float g_h[NMAXC * 128];
__device__ float g_res[NMAXC * 128];
__device__ float g_el[NMAXC * 2];
__device__ float g_er[NMAXC * 2];
__device__ float g_alpha[EMAXC * 2];
__device__ float g_s1[NMAXC * 128];
__device__ float g_s2[NMAXC * 128];
__device__ float g_p1[NMAXC * 64];
__device__ float g_sfin[NMAXC * 128];
__device__ int g_deg[NMAXC];
__device__ int g_off[NMAXC + 1];
__device__ int g_fill[NMAXC];
__device__ int g_csrsrc[EMAXC];

// ---------------- HMMA bf16 split-precision GEMM ----------------
// C[nrows,BN] = A[nrows,K] @ W[K,BN], fp32 in/out, bf16 hi/lo 3-product for accuracy.
// mma.sync m16n8k16 (baseline PTX, works on plain sm_103 target).

__device__ __forceinline__ void mma16816(float* c, const uint32_t* a, uint32_t b0, uint32_t b1) {
    asm volatile(
        "mma.sync.aligned.m16n8k16.row.col.f32.bf16.bf16.f32 "
        "{%0,%1,%2,%3}, {%4,%5,%6,%7}, {%8,%9}, {%0,%1,%2,%3};"
        : "+f"(c[0]), "+f"(c[1]), "+f"(c[2]), "+f"(c[3])
        : "r"(a[0]), "r"(a[1]), "r"(a[2]), "r"(a[3]), "r"(b0), "r"(b1));
}

template <int BN>
__global__ __launch_bounds__(256) void gemm_hmma_kernel(const float* __restrict__ A,
                                                        const float* __restrict__ W,
                                                        float* __restrict__ C,
                                                        int nrows, int K) {
    constexpr int BM = 128, BK = 64, LDK = 72;  // +8 bf16 pad -> conflict-free frag loads
    constexpr int NT = BN / 16;                 // n8 tiles per warp (warp tile = 32 x BN/2)
    extern __shared__ __nv_bfloat16 sm[];
    __nv_bfloat16* sAh = sm;
    __nv_bfloat16* sAl = sAh + BM * LDK;
    __nv_bfloat16* sBh = sAl + BM * LDK;
    __nv_bfloat16* sBl = sBh + BN * LDK;

    int tid = threadIdx.x, wid = tid >> 5, lane = tid & 31;
    int g = lane >> 2, tg = lane & 3;
    int m0 = blockIdx.x * BM;
    int wm = (wid & 3) * 32;
    int wn = (wid >> 2) * (BN / 2);

    float acc[2][NT][4];
#pragma unroll
    for (int i = 0; i < 2; i++)
#pragma unroll
        for (int j = 0; j < NT; j++)
#pragma unroll
            for (int r = 0; r < 4; r++) acc[i][j][r] = 0.f;

    for (int k0 = 0; k0 < K; k0 += BK) {
        if (k0) __syncthreads();
        // A chunk: 128 rows x 64 k (fp32 -> bf16 hi/lo)
        for (int idx = tid; idx < BM * BK; idx += 256) {
            int m = idx >> 6, k = idx & 63;
            int row = m0 + m;
            float v = (row < nrows) ? A[(size_t)row * K + k0 + k] : 0.f;
            __nv_bfloat16 hi = __float2bfloat16(v);
            __nv_bfloat16 lo = __float2bfloat16(v - __bfloat162float(hi));
            sAh[m * LDK + k] = hi;
            sAl[m * LDK + k] = lo;
        }
        // W chunk transposed: sB[n][k] = W[(k0+k)*BN + n]
        for (int idx = tid; idx < BN * BK; idx += 256) {
            int k = idx / BN, n = idx % BN;
            float v = W[(size_t)(k0 + k) * BN + n];
            __nv_bfloat16 hi = __float2bfloat16(v);
            __nv_bfloat16 lo = __float2bfloat16(v - __bfloat162float(hi));
            sBh[n * LDK + k] = hi;
            sBl[n * LDK + k] = lo;
        }
        __syncthreads();

#pragma unroll
        for (int kk = 0; kk < BK / 16; kk++) {
            int kb = kk * 16 + 2 * tg;
            uint32_t ah[2][4], al[2][4];
#pragma unroll
            for (int mt = 0; mt < 2; mt++) {
                int r = wm + mt * 16 + g;
                ah[mt][0] = *(const uint32_t*)(sAh + r * LDK + kb);
                ah[mt][1] = *(const uint32_t*)(sAh + (r + 8) * LDK + kb);
                ah[mt][2] = *(const uint32_t*)(sAh + r * LDK + kb + 8);
                ah[mt][3] = *(const uint32_t*)(sAh + (r + 8) * LDK + kb + 8);
                al[mt][0] = *(const uint32_t*)(sAl + r * LDK + kb);
                al[mt][1] = *(const uint32_t*)(sAl + (r + 8) * LDK + kb);
                al[mt][2] = *(const uint32_t*)(sAl + r * LDK + kb + 8);
                al[mt][3] = *(const uint32_t*)(sAl + (r + 8) * LDK + kb + 8);
            }
#pragma unroll
            for (int nt = 0; nt < NT; nt++) {
                int nb = (wn + nt * 8 + g) * LDK + kb;
                uint32_t bh0 = *(const uint32_t*)(sBh + nb);
                uint32_t bh1 = *(const uint32_t*)(sBh + nb + 8);
                uint32_t bl0 = *(const uint32_t*)(sBl + nb);
                uint32_t bl1 = *(const uint32_t*)(sBl + nb + 8);
#pragma unroll
                for (int mt = 0; mt < 2; mt++) {
                    mma16816(acc[mt][nt], ah[mt], bh0, bh1);
                    mma16816(acc[mt][nt], al[mt], bh0, bh1);
                    mma16816(acc[mt][nt], ah[mt], bl0, bl1);
                }
            }
        }
    }

    // epilogue
#pragma unroll
    for (int mt = 0; mt < 2; mt++) {
        int row0 = m0 + wm + mt * 16 + g;
        int row1 = row0 + 8;
#pragma unroll
        for (int nt = 0; nt < NT; nt++) {
            int col = wn + nt * 8 + 2 * tg;
            if (row0 < nrows) {
                C[(size_t)row0 * BN + col] = acc[mt][nt][0];
                C[(size_t)row0 * BN + col + 1] = acc[mt][nt][1];
            }
            if (row1 < nrows) {
                C[(size_t)row1 * BN + col] = acc[mt][nt][2];
                C[(size_t)row1 * BN + col + 1] = acc[mt][nt][3];
            }
        }
    }
}

// ---------------- CSR build ----------------
__global__ void zero_kernel(int* p, int n) {
    int i = blockIdx.x * blockDim.x + threadIdx.x;
    if (i < n) p[i] = 0;
}

__global__ void count_kernel(const int* __restrict__ dst, int* __restrict__ deg, int e) {
    for (int i = blockIdx.x * blockDim.x + threadIdx.x; i < e; i += gridDim.x * blockDim.x)
        atomicAdd(&deg[dst[i]], 1);
}

__global__ __launch_bounds__(1024) void scan_kernel(const int* __restrict__ deg,
                                                    int* __restrict__ off,
                                                    int* __restrict__ fill, int n) {
    __shared__ int sums[1024];
    int t = threadIdx.x;
    int chunk = (n + 1023) / 1024;
    int begin = t * chunk;
    int end = begin + chunk;
    if (end > n) end = n;
    if (begin > n) begin = n;
    int s = 0;
    for (int i = begin; i < end; i++) s += deg[i];
    sums[t] = s;
    __syncthreads();
    for (int d = 1; d < 1024; d <<= 1) {
        int v = (t >= d) ? sums[t - d] : 0;
        __syncthreads();
        sums[t] += v;
        __syncthreads();
    }
    int run = (t == 0) ? 0 : sums[t - 1];
    for (int i = begin; i < end; i++) {
        off[i] = run;
        fill[i] = run;
        run += deg[i];
    }
    if (t == 1023) off[n] = sums[1023];
}

__global__ void scatter_kernel(const int* __restrict__ src, const int* __restrict__ dst,
                               int* __restrict__ fill, int* __restrict__ csrsrc, int e) {
    for (int i = blockIdx.x * blockDim.x + threadIdx.x; i < e; i += gridDim.x * blockDim.x) {
        int pos = atomicAdd(&fill[dst[i]], 1);
        csrsrc[pos] = src[i];
    }
}

// ---------------- concat ----------------
__global__ void concat_kernel(const float* __restrict__ a, int Fa,
                              const float* __restrict__ b, int Fb,
                              float* __restrict__ out, int n) {
    int F = Fa + Fb;
    long total = (long)n * F;
    for (long i = blockIdx.x * (long)blockDim.x + threadIdx.x; i < total;
         i += (long)gridDim.x * blockDim.x) {
        int node = (int)(i / F);
        int j = (int)(i - (long)node * F);
        out[i] = (j < Fa) ? a[(long)node * Fa + j] : b[(long)node * Fb + (j - Fa)];
    }
}

// ---------------- attention logits per node: el/er [N,2] ----------------
__global__ void eler_kernel(const float* __restrict__ h, const float* __restrict__ al,
                            const float* __restrict__ ar, float* __restrict__ el,
                            float* __restrict__ er, int n, int D) {
    int i = blockIdx.x * blockDim.x + threadIdx.x;
    if (i >= n * 2) return;
    int node = i >> 1, hh = i & 1;
    const float* row = h + (size_t)node * (2 * D) + hh * D;
    const float* a = al + hh * D;
    const float* b = ar + hh * D;
    float s1 = 0.f, s2 = 0.f;
    for (int d = 0; d < D; d++) {
        float v = row[d];
        s1 = fmaf(v, a[d], s1);
        s2 = fmaf(v, b[d], s2);
    }
    el[i] = s1;
    er[i] = s2;
}

// ---------------- per-dst edge softmax (warp per node, both heads) ----------------
__global__ __launch_bounds__(256) void alpha_kernel(const float* __restrict__ el,
                                                    const float* __restrict__ er,
                                                    const int* __restrict__ off,
                                                    const int* __restrict__ csr,
                                                    float* __restrict__ alpha, int n) {
    int warp = (blockIdx.x * blockDim.x + threadIdx.x) >> 5;
    int lane = threadIdx.x & 31;
    if (warp >= n) return;
    int start = off[warp], end = off[warp + 1];
    float er0 = er[warp * 2 + 0], er1 = er[warp * 2 + 1];
    float m0 = -1e30f, m1 = -1e30f;
    for (int i = start + lane; i < end; i += 32) {
        int s = csr[i];
        float e0 = el[s * 2 + 0] + er0;
        e0 = e0 > 0.f ? e0 : 0.2f * e0;
        float e1 = el[s * 2 + 1] + er1;
        e1 = e1 > 0.f ? e1 : 0.2f * e1;
        m0 = fmaxf(m0, e0);
        m1 = fmaxf(m1, e1);
    }
#pragma unroll
    for (int o = 16; o; o >>= 1) {
        m0 = fmaxf(m0, __shfl_xor_sync(0xffffffffu, m0, o));
        m1 = fmaxf(m1, __shfl_xor_sync(0xffffffffu, m1, o));
    }
    float s0 = 0.f, s1 = 0.f;
    for (int i = start + lane; i < end; i += 32) {
        int s = csr[i];
        float e0 = el[s * 2 + 0] + er0;
        e0 = e0 > 0.f ? e0 : 0.2f * e0;
        float e1 = el[s * 2 + 1] + er1;
        e1 = e1 > 0.f ? e1 : 0.2f * e1;
        s0 += expf(e0 - m0);
        s1 += expf(e1 - m1);
    }
#pragma unroll
    for (int o = 16; o; o >>= 1) {
        s0 += __shfl_xor_sync(0xffffffffu, s0, o);
        s1 += __shfl_xor_sync(0xffffffffu, s1, o);
    }
    float inv0 = (s0 > 0.f) ? 1.f / s0 : 0.f;
    float inv1 = (s1 > 0.f) ? 1.f / s1 : 0.f;
    for (int i = start + lane; i < end; i += 32) {
        int s = csr[i];
        float e0 = el[s * 2 + 0] + er0;
        e0 = e0 > 0.f ? e0 : 0.2f * e0;
        float e1 = el[s * 2 + 1] + er1;
        e1 = e1 > 0.f ? e1 : 0.2f * e1;
        alpha[i * 2 + 0] = expf(e0 - m0) * inv0;
        alpha[i * 2 + 1] = expf(e1 - m1) * inv1;
    }
}

// ---------------- weighted aggregation + residual + activation ----------------
// warp per (node, head). ACT: 0=ELU, 1=tanh.
template <int HD, int D, int ACT>
__global__ __launch_bounds__(256) void agg_kernel(const float* __restrict__ hbuf,
                                                  const float* __restrict__ alpha,
                                                  const int* __restrict__ off,
                                                  const int* __restrict__ csr,
                                                  const float* __restrict__ resbuf,
                                                  float* __restrict__ out, int n) {
    int warp = (blockIdx.x * blockDim.x + threadIdx.x) >> 5;
    int lane = threadIdx.x & 31;
    int node = warp >> 1, head = warp & 1;
    if (node >= n) return;
    int start = off[node], end = off[node + 1];
    float acc0 = 0.f, acc1 = 0.f;
    for (int i = start; i < end; i++) {
        int s = csr[i];
        float a = alpha[i * 2 + head];
        const float* row = hbuf + (size_t)s * HD + head * D;
        acc0 = fmaf(row[lane], a, acc0);
        if (D == 64) acc1 = fmaf(row[lane + 32], a, acc1);
    }
    size_t base = (size_t)node * HD + head * D;
    float v0 = acc0 + resbuf[base + lane];
    v0 = (ACT == 0) ? (v0 > 0.f ? v0 : expm1f(v0)) : tanhf(v0);
    out[base + lane] = v0;
    if (D == 64) {
        float v1 = acc1 + resbuf[base + lane + 32];
        v1 = (ACT == 0) ? (v1 > 0.f ? v1 : expm1f(v1)) : tanhf(v1);
        out[base + lane + 32] = v1;
    }
}

// final: mean over heads of [N,2,64] -> [N,64]
__global__ void mean_kernel(const float* __restrict__ in, float* __restrict__ out, int n) {
    int i = blockIdx.x * blockDim.x + threadIdx.x;
    if (i >= n * 64) return;
    int node = i >> 6, d = i & 63;
    out[i] = 0.5f * (in[(size_t)node * 128 + d] + in[(size_t)node * 128 + 64 + d]);
}

// ---------------- host ----------------
template <typename T>
static T* symaddr(const void* sym) {
    void* p = nullptr;
    cudaGetSymbolAddress(&p, sym);
    return (T*)p;
}

extern "C" void kernel_launch(void* const* d_in, const int* in_sizes, int n_in,
                              void* d_out, int out_size) {
    const float* fvs = (const float*)d_in[0];
    const float* pos = (const float*)d_in[1];
    const int* src = (const int*)d_in[2];
    const int* dst = (const int*)d_in[3];
    const float* gW[3] = {(const float*)d_in[4], (const float*)d_in[8], (const float*)d_in[12]};
    const float* gal[3] = {(const float*)d_in[5], (const float*)d_in[9], (const float*)d_in[13]};
    const float* gar[3] = {(const float*)d_in[6], (const float*)d_in[10], (const float*)d_in[14]};
    const float* grW[3] = {(const float*)d_in[7], (const float*)d_in[11], (const float*)d_in[15]};
    const float* pW[2] = {(const float*)d_in[16], (const float*)d_in[19]};
    const float* pal[2] = {(const float*)d_in[17], (const float*)d_in[20]};
    const float* par[2] = {(const float*)d_in[18], (const float*)d_in[21]};

    int n = in_sizes[0] / 128;
    int e = in_sizes[2];
    float* out = (float*)d_out;
    float* out_hs = out;                   // [N,64]
    float* out_hp = out + (size_t)n * 64;  // [N,64]

    float* concatB = symaddr<float>(g_concat);
    float* hB = symaddr<float>(g_h);
    float* resB = symaddr<float>(g_res);
    float* elB = symaddr<float>(g_el);
    float* erB = symaddr<float>(g_er);
    float* alB = symaddr<float>(g_alpha);
    float* s1B = symaddr<float>(g_s1);
    float* s2B = symaddr<float>(g_s2);
    float* p1B = symaddr<float>(g_p1);
    float* sfB = symaddr<float>(g_sfin);
    int* degB = symaddr<int>(g_deg);
    int* offB = symaddr<int>(g_off);
    int* fillB = symaddr<int>(g_fill);
    int* csrB = symaddr<int>(g_csrsrc);

    // dynamic smem: (2*128*72 + 2*BN*72) bf16
    const int SMEM_G128 = (2 * 128 * 72 + 2 * 128 * 72) * 2;  // 73728
    const int SMEM_G64 = (2 * 128 * 72 + 2 * 64 * 72) * 2;    // 55296
    static bool attr_done = false;
    if (!attr_done) {
        cudaFuncSetAttribute(gemm_hmma_kernel<128>, cudaFuncAttributeMaxDynamicSharedMemorySize,
                             SMEM_G128);
        cudaFuncSetAttribute(gemm_hmma_kernel<64>, cudaFuncAttributeMaxDynamicSharedMemorySize,
                             SMEM_G64);
        attr_done = true;
    }

    const int TB = 256;
    // ---- CSR build (by dst) ----
    zero_kernel<<<(n + TB - 1) / TB, TB>>>(degB, n);
    count_kernel<<<(e + TB - 1) / TB, TB>>>(dst, degB, e);
    scan_kernel<<<1, 1024>>>(degB, offB, fillB, n);
    scatter_kernel<<<(e + TB - 1) / TB, TB>>>(src, dst, fillB, csrB, e);

    int alpha_blocks = (n * 32 + TB - 1) / TB;
    int agg_blocks = (n * 64 + TB - 1) / TB;
    int gemm_blocks = (n + 127) / 128;
    int cc_blocks = 2048;

    // ---- layer 0: gat0 on concat(fvs, pos) ----
    concat_kernel<<<cc_blocks, TB>>>(fvs, 128, pos, 64, concatB, n);
    gemm_hmma_kernel<128><<<gemm_blocks, 256, SMEM_G128>>>(concatB, gW[0], hB, n, 192);
    gemm_hmma_kernel<128><<<gemm_blocks, 256, SMEM_G128>>>(concatB, grW[0], resB, n, 192);
    eler_kernel<<<(n * 2 + TB - 1) / TB, TB>>>(hB, gal[0], gar[0], elB, erB, n, 64);
    alpha_kernel<<<alpha_blocks, TB>>>(elB, erB, offB, csrB, alB, n);
    agg_kernel<128, 64, 0><<<agg_blocks, TB>>>(hB, alB, offB, csrB, resB, s1B, n);

    // ---- pg0 on pos (identity residual, tanh) ----
    gemm_hmma_kernel<64><<<gemm_blocks, 256, SMEM_G64>>>(pos, pW[0], hB, n, 64);
    eler_kernel<<<(n * 2 + TB - 1) / TB, TB>>>(hB, pal[0], par[0], elB, erB, n, 32);
    alpha_kernel<<<alpha_blocks, TB>>>(elB, erB, offB, csrB, alB, n);
    agg_kernel<64, 32, 1><<<agg_blocks, TB>>>(hB, alB, offB, csrB, pos, p1B, n);

    // ---- layer 1: gat1 on concat(s1, p1) ----
    concat_kernel<<<cc_blocks, TB>>>(s1B, 128, p1B, 64, concatB, n);
    gemm_hmma_kernel<128><<<gemm_blocks, 256, SMEM_G128>>>(concatB, gW[1], hB, n, 192);
    gemm_hmma_kernel<128><<<gemm_blocks, 256, SMEM_G128>>>(concatB, grW[1], resB, n, 192);
    eler_kernel<<<(n * 2 + TB - 1) / TB, TB>>>(hB, gal[1], gar[1], elB, erB, n, 64);
    alpha_kernel<<<alpha_blocks, TB>>>(elB, erB, offB, csrB, alB, n);
    agg_kernel<128, 64, 0><<<agg_blocks, TB>>>(hB, alB, offB, csrB, resB, s2B, n);

    // ---- pg1 on p1 (identity residual, tanh) -> final h_p directly into d_out ----
    gemm_hmma_kernel<64><<<gemm_blocks, 256, SMEM_G64>>>(p1B, pW[1], hB, n, 64);
    eler_kernel<<<(n * 2 + TB - 1) / TB, TB>>>(hB, pal[1], par[1], elB, erB, n, 32);
    alpha_kernel<<<alpha_blocks, TB>>>(elB, erB, offB, csrB, alB, n);
    agg_kernel<64, 32, 1><<<agg_blocks, TB>>>(hB, alB, offB, csrB, p1B, out_hp, n);

    // ---- layer 2: gat2 on concat(s2, h_p) -> elu -> mean heads ----
    concat_kernel<<<cc_blocks, TB>>>(s2B, 128, out_hp, 64, concatB, n);
    gemm_hmma_kernel<128><<<gemm_blocks, 256, SMEM_G128>>>(concatB, gW[2], hB, n, 192);
    gemm_hmma_kernel<128><<<gemm_blocks, 256, SMEM_G128>>>(concatB, grW[2], resB, n, 192);
    eler_kernel<<<(n * 2 + TB - 1) / TB, TB>>>(hB, gal[2], gar[2], elB, erB, n, 64);
    alpha_kernel<<<alpha_blocks, TB>>>(elB, erB, offB, csrB, alB, n);
    agg_kernel<128, 64, 0><<<agg_blocks, TB>>>(hB, alB, offB, csrB, resB, sfB, n);
    mean_kernel<<<(n * 64 + TB - 1) / TB, TB>>>(sfB, out_hs, n);
}

// round 6
// speedup vs baseline: 1.5618x; 1.2797x over previous
#include <cuda_runtime.h>
#include <cuda_bf16.h>
#include <math.h>
#include <cstdint>

// Problem-fixed maxima (setup_inputs: N=50000, E=800000)
#define NMAXC 50000
#define EMAXC 800000

// ---------------- scratch (static __device__ — no allocs allowed) ----------------
__device__ float g_h[NMAXC * 128];
__device__ float g_res[NMAXC * 128];
__device__ float g_el[NMAXC * 2];
__device__ float g_er[NMAXC * 2];
__device__ float g_s1[NMAXC * 128];
__device__ float g_s2[NMAXC * 128];
__device__ float g_p1[NMAXC * 64];
__device__ float g_sfin[NMAXC * 128];
__device__ int g_deg[NMAXC];
__device__ int g_off[NMAXC + 1];
__device__ int g_fill[NMAXC];
__device__ int g_csrsrc[EMAXC];

// ---------------- HMMA helpers ----------------
__device__ __forceinline__ void mma16816(float* c, const uint32_t* a, uint32_t b0, uint32_t b1) {
    asm volatile(
        "mma.sync.aligned.m16n8k16.row.col.f32.bf16.bf16.f32 "
        "{%0,%1,%2,%3}, {%4,%5,%6,%7}, {%8,%9}, {%0,%1,%2,%3};"
        : "+f"(c[0]), "+f"(c[1]), "+f"(c[2]), "+f"(c[3])
        : "r"(a[0]), "r"(a[1]), "r"(a[2]), "r"(a[3]), "r"(b0), "r"(b1));
}

__device__ __forceinline__ void cvt_hilo(float v, __nv_bfloat16& hi, __nv_bfloat16& lo) {
    hi = __float2bfloat16(v);
    lo = __float2bfloat16(v - __bfloat162float(hi));
}

// ---------------- fused dual GEMM (gat layers): ----------------
// C1 = A@W1, C2 = A@W2; A = concat(A1[:,0:128], A2[:,0:64]) virtual, K=192, BN=128.
__global__ __launch_bounds__(512) void gemm_dual_kernel(const float* __restrict__ A1,
                                                        const float* __restrict__ A2,
                                                        const float* __restrict__ W1,
                                                        const float* __restrict__ W2,
                                                        float* __restrict__ C1,
                                                        float* __restrict__ C2, int nrows) {
    constexpr int BM = 128, BN = 128, BK = 64, LDA = 72, LDB = 70;
    extern __shared__ __nv_bfloat16 sm[];
    __nv_bfloat16* sAh = sm;
    __nv_bfloat16* sAl = sAh + BM * LDA;
    __nv_bfloat16* sB1h = sAl + BM * LDA;
    __nv_bfloat16* sB1l = sB1h + BN * LDB;
    __nv_bfloat16* sB2h = sB1l + BN * LDB;
    __nv_bfloat16* sB2l = sB2h + BN * LDB;

    int tid = threadIdx.x, wid = tid >> 5, lane = tid & 31;
    int g = lane >> 2, tg = lane & 3;
    int m0 = blockIdx.x * BM;
    int wm = (wid & 3) * 32;
    int wn = (wid >> 2) * 32;  // 4 col groups of 32

    float acc[2][2][4][4];
#pragma unroll
    for (int c = 0; c < 2; c++)
#pragma unroll
        for (int mt = 0; mt < 2; mt++)
#pragma unroll
            for (int nt = 0; nt < 4; nt++)
#pragma unroll
                for (int r = 0; r < 4; r++) acc[c][mt][nt][r] = 0.f;

#pragma unroll
    for (int c = 0; c < 3; c++) {
        if (c) __syncthreads();
        int k0 = c * 64;
        // ---- A chunk (from split sources), vectorized float4 ----
        const float* Asrc = (c < 2) ? A1 : A2;
        int astride = (c < 2) ? 128 : 64;
        int kbase = (c < 2) ? k0 : 0;
#pragma unroll
        for (int t = 0; t < 4; t++) {
            int slot = tid + t * 512;  // 2048 float4 slots
            int m = slot >> 4, k = (slot & 15) * 4;
            int row = m0 + m;
            float4 v = (row < nrows)
                           ? *(const float4*)(Asrc + (size_t)row * astride + kbase + k)
                           : make_float4(0.f, 0.f, 0.f, 0.f);
            __nv_bfloat16 h0, h1, h2, h3, l0, l1, l2, l3;
            cvt_hilo(v.x, h0, l0);
            cvt_hilo(v.y, h1, l1);
            cvt_hilo(v.z, h2, l2);
            cvt_hilo(v.w, h3, l3);
            __nv_bfloat162* ph = (__nv_bfloat162*)(sAh + m * LDA + k);
            ph[0] = __halves2bfloat162(h0, h1);
            ph[1] = __halves2bfloat162(h2, h3);
            __nv_bfloat162* pl = (__nv_bfloat162*)(sAl + m * LDA + k);
            pl[0] = __halves2bfloat162(l0, l1);
            pl[1] = __halves2bfloat162(l2, l3);
        }
        // ---- B chunks for both weight matrices ----
#pragma unroll
        for (int mat = 0; mat < 2; mat++) {
            const float* W = mat ? W2 : W1;
            __nv_bfloat16* sBh = mat ? sB2h : sB1h;
            __nv_bfloat16* sBl = mat ? sB2l : sB1l;
#pragma unroll
            for (int t = 0; t < 4; t++) {
                int slot = tid + t * 512;  // 2048 float4 slots
                int k = slot >> 5, n = (slot & 31) * 4;
                float4 v = *(const float4*)(W + (size_t)(k0 + k) * BN + n);
                __nv_bfloat16 hi, lo;
                cvt_hilo(v.x, hi, lo);
                sBh[(n + 0) * LDB + k] = hi;
                sBl[(n + 0) * LDB + k] = lo;
                cvt_hilo(v.y, hi, lo);
                sBh[(n + 1) * LDB + k] = hi;
                sBl[(n + 1) * LDB + k] = lo;
                cvt_hilo(v.z, hi, lo);
                sBh[(n + 2) * LDB + k] = hi;
                sBl[(n + 2) * LDB + k] = lo;
                cvt_hilo(v.w, hi, lo);
                sBh[(n + 3) * LDB + k] = hi;
                sBl[(n + 3) * LDB + k] = lo;
            }
        }
        __syncthreads();

#pragma unroll
        for (int kk = 0; kk < 4; kk++) {
            int kb = kk * 16 + 2 * tg;
            uint32_t ah[2][4], al[2][4];
#pragma unroll
            for (int mt = 0; mt < 2; mt++) {
                int r = wm + mt * 16 + g;
                ah[mt][0] = *(const uint32_t*)(sAh + r * LDA + kb);
                ah[mt][1] = *(const uint32_t*)(sAh + (r + 8) * LDA + kb);
                ah[mt][2] = *(const uint32_t*)(sAh + r * LDA + kb + 8);
                ah[mt][3] = *(const uint32_t*)(sAh + (r + 8) * LDA + kb + 8);
                al[mt][0] = *(const uint32_t*)(sAl + r * LDA + kb);
                al[mt][1] = *(const uint32_t*)(sAl + (r + 8) * LDA + kb);
                al[mt][2] = *(const uint32_t*)(sAl + r * LDA + kb + 8);
                al[mt][3] = *(const uint32_t*)(sAl + (r + 8) * LDA + kb + 8);
            }
#pragma unroll
            for (int nt = 0; nt < 4; nt++) {
                int nb = (wn + nt * 8 + g) * LDB + kb;
                uint32_t b1h0 = *(const uint32_t*)(sB1h + nb);
                uint32_t b1h1 = *(const uint32_t*)(sB1h + nb + 8);
                uint32_t b1l0 = *(const uint32_t*)(sB1l + nb);
                uint32_t b1l1 = *(const uint32_t*)(sB1l + nb + 8);
                uint32_t b2h0 = *(const uint32_t*)(sB2h + nb);
                uint32_t b2h1 = *(const uint32_t*)(sB2h + nb + 8);
                uint32_t b2l0 = *(const uint32_t*)(sB2l + nb);
                uint32_t b2l1 = *(const uint32_t*)(sB2l + nb + 8);
#pragma unroll
                for (int mt = 0; mt < 2; mt++) {
                    mma16816(acc[0][mt][nt], ah[mt], b1h0, b1h1);
                    mma16816(acc[0][mt][nt], al[mt], b1h0, b1h1);
                    mma16816(acc[0][mt][nt], ah[mt], b1l0, b1l1);
                    mma16816(acc[1][mt][nt], ah[mt], b2h0, b2h1);
                    mma16816(acc[1][mt][nt], al[mt], b2h0, b2h1);
                    mma16816(acc[1][mt][nt], ah[mt], b2l0, b2l1);
                }
            }
        }
    }

    // epilogue
#pragma unroll
    for (int c = 0; c < 2; c++) {
        float* C = c ? C2 : C1;
#pragma unroll
        for (int mt = 0; mt < 2; mt++) {
            int row0 = m0 + wm + mt * 16 + g;
            int row1 = row0 + 8;
#pragma unroll
            for (int nt = 0; nt < 4; nt++) {
                int col = wn + nt * 8 + 2 * tg;
                if (row0 < nrows)
                    *(float2*)(C + (size_t)row0 * BN + col) =
                        make_float2(acc[c][mt][nt][0], acc[c][mt][nt][1]);
                if (row1 < nrows)
                    *(float2*)(C + (size_t)row1 * BN + col) =
                        make_float2(acc[c][mt][nt][2], acc[c][mt][nt][3]);
            }
        }
    }
}

// ---------------- single GEMM (pg layers): C[n,64] = A[n,64]@W[64,64] ----------------
template <int BN>
__global__ __launch_bounds__(256) void gemm_hmma_kernel(const float* __restrict__ A,
                                                        const float* __restrict__ W,
                                                        float* __restrict__ C,
                                                        int nrows, int K) {
    constexpr int BM = 128, BK = 64, LDK = 72;
    constexpr int NT = BN / 16;
    extern __shared__ __nv_bfloat16 sm2[];
    __nv_bfloat16* sAh = sm2;
    __nv_bfloat16* sAl = sAh + BM * LDK;
    __nv_bfloat16* sBh = sAl + BM * LDK;
    __nv_bfloat16* sBl = sBh + BN * LDK;

    int tid = threadIdx.x, wid = tid >> 5, lane = tid & 31;
    int g = lane >> 2, tg = lane & 3;
    int m0 = blockIdx.x * BM;
    int wm = (wid & 3) * 32;
    int wn = (wid >> 2) * (BN / 2);

    float acc[2][NT][4];
#pragma unroll
    for (int i = 0; i < 2; i++)
#pragma unroll
        for (int j = 0; j < NT; j++)
#pragma unroll
            for (int r = 0; r < 4; r++) acc[i][j][r] = 0.f;

    for (int k0 = 0; k0 < K; k0 += BK) {
        if (k0) __syncthreads();
        for (int idx = tid; idx < BM * BK / 4; idx += 256) {
            int m = idx >> 4, k = (idx & 15) * 4;
            int row = m0 + m;
            float4 v = (row < nrows) ? *(const float4*)(A + (size_t)row * K + k0 + k)
                                     : make_float4(0.f, 0.f, 0.f, 0.f);
            __nv_bfloat16 h0, h1, h2, h3, l0, l1, l2, l3;
            cvt_hilo(v.x, h0, l0);
            cvt_hilo(v.y, h1, l1);
            cvt_hilo(v.z, h2, l2);
            cvt_hilo(v.w, h3, l3);
            __nv_bfloat162* ph = (__nv_bfloat162*)(sAh + m * LDK + k);
            ph[0] = __halves2bfloat162(h0, h1);
            ph[1] = __halves2bfloat162(h2, h3);
            __nv_bfloat162* pl = (__nv_bfloat162*)(sAl + m * LDK + k);
            pl[0] = __halves2bfloat162(l0, l1);
            pl[1] = __halves2bfloat162(l2, l3);
        }
        for (int idx = tid; idx < BN * BK; idx += 256) {
            int k = idx / BN, n = idx % BN;
            float v = W[(size_t)(k0 + k) * BN + n];
            __nv_bfloat16 hi, lo;
            cvt_hilo(v, hi, lo);
            sBh[n * LDK + k] = hi;
            sBl[n * LDK + k] = lo;
        }
        __syncthreads();

#pragma unroll
        for (int kk = 0; kk < BK / 16; kk++) {
            int kb = kk * 16 + 2 * tg;
            uint32_t ah[2][4], al[2][4];
#pragma unroll
            for (int mt = 0; mt < 2; mt++) {
                int r = wm + mt * 16 + g;
                ah[mt][0] = *(const uint32_t*)(sAh + r * LDK + kb);
                ah[mt][1] = *(const uint32_t*)(sAh + (r + 8) * LDK + kb);
                ah[mt][2] = *(const uint32_t*)(sAh + r * LDK + kb + 8);
                ah[mt][3] = *(const uint32_t*)(sAh + (r + 8) * LDK + kb + 8);
                al[mt][0] = *(const uint32_t*)(sAl + r * LDK + kb);
                al[mt][1] = *(const uint32_t*)(sAl + (r + 8) * LDK + kb);
                al[mt][2] = *(const uint32_t*)(sAl + r * LDK + kb + 8);
                al[mt][3] = *(const uint32_t*)(sAl + (r + 8) * LDK + kb + 8);
            }
#pragma unroll
            for (int nt = 0; nt < NT; nt++) {
                int nb = (wn + nt * 8 + g) * LDK + kb;
                uint32_t bh0 = *(const uint32_t*)(sBh + nb);
                uint32_t bh1 = *(const uint32_t*)(sBh + nb + 8);
                uint32_t bl0 = *(const uint32_t*)(sBl + nb);
                uint32_t bl1 = *(const uint32_t*)(sBl + nb + 8);
#pragma unroll
                for (int mt = 0; mt < 2; mt++) {
                    mma16816(acc[mt][nt], ah[mt], bh0, bh1);
                    mma16816(acc[mt][nt], al[mt], bh0, bh1);
                    mma16816(acc[mt][nt], ah[mt], bl0, bl1);
                }
            }
        }
    }

#pragma unroll
    for (int mt = 0; mt < 2; mt++) {
        int row0 = m0 + wm + mt * 16 + g;
        int row1 = row0 + 8;
#pragma unroll
        for (int nt = 0; nt < NT; nt++) {
            int col = wn + nt * 8 + 2 * tg;
            if (row0 < nrows)
                *(float2*)(C + (size_t)row0 * BN + col) =
                    make_float2(acc[mt][nt][0], acc[mt][nt][1]);
            if (row1 < nrows)
                *(float2*)(C + (size_t)row1 * BN + col) =
                    make_float2(acc[mt][nt][2], acc[mt][nt][3]);
        }
    }
}

// ---------------- CSR build ----------------
__global__ void zero_kernel(int* p, int n) {
    int i = blockIdx.x * blockDim.x + threadIdx.x;
    if (i < n) p[i] = 0;
}

__global__ void count_kernel(const int* __restrict__ dst, int* __restrict__ deg, int e) {
    for (int i = blockIdx.x * blockDim.x + threadIdx.x; i < e; i += gridDim.x * blockDim.x)
        atomicAdd(&deg[dst[i]], 1);
}

__global__ __launch_bounds__(1024) void scan_kernel(const int* __restrict__ deg,
                                                    int* __restrict__ off,
                                                    int* __restrict__ fill, int n) {
    __shared__ int sums[1024];
    int t = threadIdx.x;
    int chunk = (n + 1023) / 1024;
    int begin = t * chunk;
    int end = begin + chunk;
    if (end > n) end = n;
    if (begin > n) begin = n;
    int s = 0;
    for (int i = begin; i < end; i++) s += deg[i];
    sums[t] = s;
    __syncthreads();
    for (int d = 1; d < 1024; d <<= 1) {
        int v = (t >= d) ? sums[t - d] : 0;
        __syncthreads();
        sums[t] += v;
        __syncthreads();
    }
    int run = (t == 0) ? 0 : sums[t - 1];
    for (int i = begin; i < end; i++) {
        off[i] = run;
        fill[i] = run;
        run += deg[i];
    }
    if (t == 1023) off[n] = sums[1023];
}

__global__ void scatter_kernel(const int* __restrict__ src, const int* __restrict__ dst,
                               int* __restrict__ fill, int* __restrict__ csrsrc, int e) {
    for (int i = blockIdx.x * blockDim.x + threadIdx.x; i < e; i += gridDim.x * blockDim.x) {
        int pos = atomicAdd(&fill[dst[i]], 1);
        csrsrc[pos] = src[i];
    }
}

// ---------------- attention logits per node: el/er [N,2] ----------------
__global__ void eler_kernel(const float* __restrict__ h, const float* __restrict__ al,
                            const float* __restrict__ ar, float* __restrict__ el,
                            float* __restrict__ er, int n, int D) {
    int i = blockIdx.x * blockDim.x + threadIdx.x;
    if (i >= n * 2) return;
    int node = i >> 1, hh = i & 1;
    const float* row = h + (size_t)node * (2 * D) + hh * D;
    const float* a = al + hh * D;
    const float* b = ar + hh * D;
    float s1 = 0.f, s2 = 0.f;
    for (int d = 0; d < D; d++) {
        float v = row[d];
        s1 = fmaf(v, a[d], s1);
        s2 = fmaf(v, b[d], s2);
    }
    el[i] = s1;
    er[i] = s2;
}

// ---------------- fused edge-softmax + aggregation + residual + activation ----------------
// warp per (node, head). Online softmax, shuffle-broadcast weights. ACT: 0=ELU, 1=tanh.
template <int HD, int D, int ACT>
__global__ __launch_bounds__(256) void aggsm_kernel(const float* __restrict__ hbuf,
                                                    const float* __restrict__ el,
                                                    const float* __restrict__ er,
                                                    const int* __restrict__ off,
                                                    const int* __restrict__ csr,
                                                    const float* __restrict__ resbuf,
                                                    float* __restrict__ out, int n) {
    int warp = (blockIdx.x * blockDim.x + threadIdx.x) >> 5;
    int lane = threadIdx.x & 31;
    int node = warp >> 1, head = warp & 1;
    if (node >= n) return;
    int start = off[node], end = off[node + 1];
    float erh = er[node * 2 + head];

    // online max+sum
    float m = -1e30f, ssum = 0.f;
    for (int i = start + lane; i < end; i += 32) {
        float e = el[csr[i] * 2 + head] + erh;
        e = e > 0.f ? e : 0.2f * e;
        float Mn = fmaxf(m, e);
        ssum = ssum * __expf(m - Mn) + __expf(e - Mn);
        m = Mn;
    }
#pragma unroll
    for (int o = 16; o; o >>= 1) {
        float mo = __shfl_xor_sync(0xffffffffu, m, o);
        float so = __shfl_xor_sync(0xffffffffu, ssum, o);
        float Mn = fmaxf(m, mo);
        ssum = ssum * __expf(m - Mn) + so * __expf(mo - Mn);
        m = Mn;
    }
    float inv = (ssum > 0.f) ? 1.f / ssum : 0.f;

    // weighted aggregation, weights broadcast from lanes
    float acc0 = 0.f, acc1 = 0.f;
    for (int t = start; t < end; t += 32) {
        int i = t + lane;
        float w = 0.f;
        int s = 0;
        if (i < end) {
            s = csr[i];
            float e = el[s * 2 + head] + erh;
            e = e > 0.f ? e : 0.2f * e;
            w = __expf(e - m) * inv;
        }
        int cnt = min(32, end - t);
        for (int j = 0; j < cnt; j++) {
            float wj = __shfl_sync(0xffffffffu, w, j);
            int sj = __shfl_sync(0xffffffffu, s, j);
            const float* row = hbuf + (size_t)sj * HD + head * D;
            acc0 = fmaf(row[lane], wj, acc0);
            if (D == 64) acc1 = fmaf(row[lane + 32], wj, acc1);
        }
    }

    size_t base = (size_t)node * HD + head * D;
    float v0 = acc0 + resbuf[base + lane];
    v0 = (ACT == 0) ? (v0 > 0.f ? v0 : expm1f(v0)) : tanhf(v0);
    out[base + lane] = v0;
    if (D == 64) {
        float v1 = acc1 + resbuf[base + lane + 32];
        v1 = (ACT == 0) ? (v1 > 0.f ? v1 : expm1f(v1)) : tanhf(v1);
        out[base + lane + 32] = v1;
    }
}

// final: mean over heads of [N,2,64] -> [N,64]
__global__ void mean_kernel(const float* __restrict__ in, float* __restrict__ out, int n) {
    int i = blockIdx.x * blockDim.x + threadIdx.x;
    if (i >= n * 64) return;
    int node = i >> 6, d = i & 63;
    out[i] = 0.5f * (in[(size_t)node * 128 + d] + in[(size_t)node * 128 + 64 + d]);
}

// ---------------- host ----------------
template <typename T>
static T* symaddr(const void* sym) {
    void* p = nullptr;
    cudaGetSymbolAddress(&p, sym);
    return (T*)p;
}

extern "C" void kernel_launch(void* const* d_in, const int* in_sizes, int n_in,
                              void* d_out, int out_size) {
    const float* fvs = (const float*)d_in[0];
    const float* pos = (const float*)d_in[1];
    const int* src = (const int*)d_in[2];
    const int* dst = (const int*)d_in[3];
    const float* gW[3] = {(const float*)d_in[4], (const float*)d_in[8], (const float*)d_in[12]};
    const float* gal[3] = {(const float*)d_in[5], (const float*)d_in[9], (const float*)d_in[13]};
    const float* gar[3] = {(const float*)d_in[6], (const float*)d_in[10], (const float*)d_in[14]};
    const float* grW[3] = {(const float*)d_in[7], (const float*)d_in[11], (const float*)d_in[15]};
    const float* pW[2] = {(const float*)d_in[16], (const float*)d_in[19]};
    const float* pal[2] = {(const float*)d_in[17], (const float*)d_in[20]};
    const float* par[2] = {(const float*)d_in[18], (const float*)d_in[21]};

    int n = in_sizes[0] / 128;
    int e = in_sizes[2];
    float* out = (float*)d_out;
    float* out_hs = out;                   // [N,64]
    float* out_hp = out + (size_t)n * 64;  // [N,64]

    float* hB = symaddr<float>(g_h);
    float* resB = symaddr<float>(g_res);
    float* elB = symaddr<float>(g_el);
    float* erB = symaddr<float>(g_er);
    float* s1B = symaddr<float>(g_s1);
    float* s2B = symaddr<float>(g_s2);
    float* p1B = symaddr<float>(g_p1);
    float* sfB = symaddr<float>(g_sfin);
    int* degB = symaddr<int>(g_deg);
    int* offB = symaddr<int>(g_off);
    int* fillB = symaddr<int>(g_fill);
    int* csrB = symaddr<int>(g_csrsrc);

    const int SMEM_DUAL = (2 * 128 * 72 + 4 * 128 * 70) * 2;  // 108544
    const int SMEM_G64 = (2 * 128 * 72 + 2 * 64 * 72) * 2;    // 55296
    cudaFuncSetAttribute(gemm_dual_kernel, cudaFuncAttributeMaxDynamicSharedMemorySize,
                         SMEM_DUAL);
    cudaFuncSetAttribute(gemm_hmma_kernel<64>, cudaFuncAttributeMaxDynamicSharedMemorySize,
                         SMEM_G64);

    const int TB = 256;
    // ---- CSR build (by dst) ----
    zero_kernel<<<(n + TB - 1) / TB, TB>>>(degB, n);
    count_kernel<<<(e + TB - 1) / TB, TB>>>(dst, degB, e);
    scan_kernel<<<1, 1024>>>(degB, offB, fillB, n);
    scatter_kernel<<<(e + TB - 1) / TB, TB>>>(src, dst, fillB, csrB, e);

    int agg_blocks = (n * 64 + TB - 1) / TB;
    int gemm_blocks = (n + 127) / 128;
    int eler_blocks = (n * 2 + TB - 1) / TB;

    // ---- layer 0: gat0 on concat(fvs, pos) ----
    gemm_dual_kernel<<<gemm_blocks, 512, SMEM_DUAL>>>(fvs, pos, gW[0], grW[0], hB, resB, n);
    eler_kernel<<<eler_blocks, TB>>>(hB, gal[0], gar[0], elB, erB, n, 64);
    aggsm_kernel<128, 64, 0><<<agg_blocks, TB>>>(hB, elB, erB, offB, csrB, resB, s1B, n);

    // ---- pg0 on pos (identity residual, tanh) ----
    gemm_hmma_kernel<64><<<gemm_blocks, 256, SMEM_G64>>>(pos, pW[0], hB, n, 64);
    eler_kernel<<<eler_blocks, TB>>>(hB, pal[0], par[0], elB, erB, n, 32);
    aggsm_kernel<64, 32, 1><<<agg_blocks, TB>>>(hB, elB, erB, offB, csrB, pos, p1B, n);

    // ---- layer 1: gat1 on concat(s1, p1) ----
    gemm_dual_kernel<<<gemm_blocks, 512, SMEM_DUAL>>>(s1B, p1B, gW[1], grW[1], hB, resB, n);
    eler_kernel<<<eler_blocks, TB>>>(hB, gal[1], gar[1], elB, erB, n, 64);
    aggsm_kernel<128, 64, 0><<<agg_blocks, TB>>>(hB, elB, erB, offB, csrB, resB, s2B, n);

    // ---- pg1 on p1 (identity residual, tanh) -> final h_p into d_out ----
    gemm_hmma_kernel<64><<<gemm_blocks, 256, SMEM_G64>>>(p1B, pW[1], hB, n, 64);
    eler_kernel<<<eler_blocks, TB>>>(hB, pal[1], par[1], elB, erB, n, 32);
    aggsm_kernel<64, 32, 1><<<agg_blocks, TB>>>(hB, elB, erB, offB, csrB, p1B, out_hp, n);

    // ---- layer 2: gat2 on concat(s2, h_p) -> elu -> mean heads ----
    gemm_dual_kernel<<<gemm_blocks, 512, SMEM_DUAL>>>(s2B, out_hp, gW[2], grW[2], hB, resB, n);
    eler_kernel<<<eler_blocks, TB>>>(hB, gal[2], gar[2], elB, erB, n, 64);
    aggsm_kernel<128, 64, 0><<<agg_blocks, TB>>>(hB, elB, erB, offB, csrB, resB, sfB, n);
    mean_kernel<<<(n * 64 + TB - 1) / TB, TB>>>(sfB, out_hs, n);
}

// round 7
// speedup vs baseline: 1.9292x; 1.2352x over previous
#include <cuda_runtime.h>
#include <cuda_bf16.h>
#include <math.h>
#include <cstdint>

// Problem-fixed maxima (setup_inputs: N=50000, E=800000)
#define NMAXC 50000
#define EMAXC 800000

// ---------------- scratch (static __device__ — no allocs allowed) ----------------
__device__ float g_h[NMAXC * 128];
__device__ float g_res[NMAXC * 128];
__device__ float g_el[NMAXC * 2];
__device__ float g_er[NMAXC * 2];
__device__ float g_s1[NMAXC * 128];
__device__ float g_s2[NMAXC * 128];
__device__ float g_p1[NMAXC * 64];
__device__ int g_deg[NMAXC];
__device__ int g_off[NMAXC + 1];
__device__ int g_fill[NMAXC];
__device__ int g_csrsrc[EMAXC];

// ---------------- HMMA helpers ----------------
__device__ __forceinline__ void mma16816(float* c, const uint32_t* a, uint32_t b0, uint32_t b1) {
    asm volatile(
        "mma.sync.aligned.m16n8k16.row.col.f32.bf16.bf16.f32 "
        "{%0,%1,%2,%3}, {%4,%5,%6,%7}, {%8,%9}, {%0,%1,%2,%3};"
        : "+f"(c[0]), "+f"(c[1]), "+f"(c[2]), "+f"(c[3])
        : "r"(a[0]), "r"(a[1]), "r"(a[2]), "r"(a[3]), "r"(b0), "r"(b1));
}

__device__ __forceinline__ void cvt_hilo(float v, __nv_bfloat16& hi, __nv_bfloat16& lo) {
    hi = __float2bfloat16(v);
    lo = __float2bfloat16(v - __bfloat162float(hi));
}

// ---------------- fused dual GEMM (gat layers): ----------------
// C1 = A@W1, C2 = A@W2; A = concat(A1[:,0:128], A2[:,0:64]) virtual, K=192, BN=128.
__global__ __launch_bounds__(512) void gemm_dual_kernel(const float* __restrict__ A1,
                                                        const float* __restrict__ A2,
                                                        const float* __restrict__ W1,
                                                        const float* __restrict__ W2,
                                                        float* __restrict__ C1,
                                                        float* __restrict__ C2, int nrows) {
    constexpr int BM = 128, BN = 128, LDA = 72, LDB = 70;
    extern __shared__ __nv_bfloat16 sm[];
    __nv_bfloat16* sAh = sm;
    __nv_bfloat16* sAl = sAh + BM * LDA;
    __nv_bfloat16* sB1h = sAl + BM * LDA;
    __nv_bfloat16* sB1l = sB1h + BN * LDB;
    __nv_bfloat16* sB2h = sB1l + BN * LDB;
    __nv_bfloat16* sB2l = sB2h + BN * LDB;

    int tid = threadIdx.x, wid = tid >> 5, lane = tid & 31;
    int g = lane >> 2, tg = lane & 3;
    int m0 = blockIdx.x * BM;
    int wm = (wid & 3) * 32;
    int wn = (wid >> 2) * 32;

    float acc[2][2][4][4];
#pragma unroll
    for (int c = 0; c < 2; c++)
#pragma unroll
        for (int mt = 0; mt < 2; mt++)
#pragma unroll
            for (int nt = 0; nt < 4; nt++)
#pragma unroll
                for (int r = 0; r < 4; r++) acc[c][mt][nt][r] = 0.f;

#pragma unroll
    for (int c = 0; c < 3; c++) {
        if (c) __syncthreads();
        int k0 = c * 64;
        const float* Asrc = (c < 2) ? A1 : A2;
        int astride = (c < 2) ? 128 : 64;
        int kbase = (c < 2) ? k0 : 0;
#pragma unroll
        for (int t = 0; t < 4; t++) {
            int slot = tid + t * 512;
            int m = slot >> 4, k = (slot & 15) * 4;
            int row = m0 + m;
            float4 v = (row < nrows)
                           ? *(const float4*)(Asrc + (size_t)row * astride + kbase + k)
                           : make_float4(0.f, 0.f, 0.f, 0.f);
            __nv_bfloat16 h0, h1, h2, h3, l0, l1, l2, l3;
            cvt_hilo(v.x, h0, l0);
            cvt_hilo(v.y, h1, l1);
            cvt_hilo(v.z, h2, l2);
            cvt_hilo(v.w, h3, l3);
            __nv_bfloat162* ph = (__nv_bfloat162*)(sAh + m * LDA + k);
            ph[0] = __halves2bfloat162(h0, h1);
            ph[1] = __halves2bfloat162(h2, h3);
            __nv_bfloat162* pl = (__nv_bfloat162*)(sAl + m * LDA + k);
            pl[0] = __halves2bfloat162(l0, l1);
            pl[1] = __halves2bfloat162(l2, l3);
        }
#pragma unroll
        for (int mat = 0; mat < 2; mat++) {
            const float* W = mat ? W2 : W1;
            __nv_bfloat16* sBh = mat ? sB2h : sB1h;
            __nv_bfloat16* sBl = mat ? sB2l : sB1l;
#pragma unroll
            for (int t = 0; t < 4; t++) {
                int slot = tid + t * 512;
                int k = slot >> 5, n = (slot & 31) * 4;
                float4 v = *(const float4*)(W + (size_t)(k0 + k) * BN + n);
                __nv_bfloat16 hi, lo;
                cvt_hilo(v.x, hi, lo);
                sBh[(n + 0) * LDB + k] = hi;
                sBl[(n + 0) * LDB + k] = lo;
                cvt_hilo(v.y, hi, lo);
                sBh[(n + 1) * LDB + k] = hi;
                sBl[(n + 1) * LDB + k] = lo;
                cvt_hilo(v.z, hi, lo);
                sBh[(n + 2) * LDB + k] = hi;
                sBl[(n + 2) * LDB + k] = lo;
                cvt_hilo(v.w, hi, lo);
                sBh[(n + 3) * LDB + k] = hi;
                sBl[(n + 3) * LDB + k] = lo;
            }
        }
        __syncthreads();

#pragma unroll
        for (int kk = 0; kk < 4; kk++) {
            int kb = kk * 16 + 2 * tg;
            uint32_t ah[2][4], al[2][4];
#pragma unroll
            for (int mt = 0; mt < 2; mt++) {
                int r = wm + mt * 16 + g;
                ah[mt][0] = *(const uint32_t*)(sAh + r * LDA + kb);
                ah[mt][1] = *(const uint32_t*)(sAh + (r + 8) * LDA + kb);
                ah[mt][2] = *(const uint32_t*)(sAh + r * LDA + kb + 8);
                ah[mt][3] = *(const uint32_t*)(sAh + (r + 8) * LDA + kb + 8);
                al[mt][0] = *(const uint32_t*)(sAl + r * LDA + kb);
                al[mt][1] = *(const uint32_t*)(sAl + (r + 8) * LDA + kb);
                al[mt][2] = *(const uint32_t*)(sAl + r * LDA + kb + 8);
                al[mt][3] = *(const uint32_t*)(sAl + (r + 8) * LDA + kb + 8);
            }
#pragma unroll
            for (int nt = 0; nt < 4; nt++) {
                int nb = (wn + nt * 8 + g) * LDB + kb;
                uint32_t b1h0 = *(const uint32_t*)(sB1h + nb);
                uint32_t b1h1 = *(const uint32_t*)(sB1h + nb + 8);
                uint32_t b1l0 = *(const uint32_t*)(sB1l + nb);
                uint32_t b1l1 = *(const uint32_t*)(sB1l + nb + 8);
                uint32_t b2h0 = *(const uint32_t*)(sB2h + nb);
                uint32_t b2h1 = *(const uint32_t*)(sB2h + nb + 8);
                uint32_t b2l0 = *(const uint32_t*)(sB2l + nb);
                uint32_t b2l1 = *(const uint32_t*)(sB2l + nb + 8);
#pragma unroll
                for (int mt = 0; mt < 2; mt++) {
                    mma16816(acc[0][mt][nt], ah[mt], b1h0, b1h1);
                    mma16816(acc[0][mt][nt], al[mt], b1h0, b1h1);
                    mma16816(acc[0][mt][nt], ah[mt], b1l0, b1l1);
                    mma16816(acc[1][mt][nt], ah[mt], b2h0, b2h1);
                    mma16816(acc[1][mt][nt], al[mt], b2h0, b2h1);
                    mma16816(acc[1][mt][nt], ah[mt], b2l0, b2l1);
                }
            }
        }
    }

#pragma unroll
    for (int c = 0; c < 2; c++) {
        float* C = c ? C2 : C1;
#pragma unroll
        for (int mt = 0; mt < 2; mt++) {
            int row0 = m0 + wm + mt * 16 + g;
            int row1 = row0 + 8;
#pragma unroll
            for (int nt = 0; nt < 4; nt++) {
                int col = wn + nt * 8 + 2 * tg;
                if (row0 < nrows)
                    *(float2*)(C + (size_t)row0 * BN + col) =
                        make_float2(acc[c][mt][nt][0], acc[c][mt][nt][1]);
                if (row1 < nrows)
                    *(float2*)(C + (size_t)row1 * BN + col) =
                        make_float2(acc[c][mt][nt][2], acc[c][mt][nt][3]);
            }
        }
    }
}

// ---------------- single GEMM (pg layers): C[n,64] = A[n,64]@W[64,64] ----------------
template <int BN>
__global__ __launch_bounds__(256) void gemm_hmma_kernel(const float* __restrict__ A,
                                                        const float* __restrict__ W,
                                                        float* __restrict__ C,
                                                        int nrows, int K) {
    constexpr int BM = 128, BK = 64, LDK = 72;
    constexpr int NT = BN / 16;
    extern __shared__ __nv_bfloat16 sm2[];
    __nv_bfloat16* sAh = sm2;
    __nv_bfloat16* sAl = sAh + BM * LDK;
    __nv_bfloat16* sBh = sAl + BM * LDK;
    __nv_bfloat16* sBl = sBh + BN * LDK;

    int tid = threadIdx.x, wid = tid >> 5, lane = tid & 31;
    int g = lane >> 2, tg = lane & 3;
    int m0 = blockIdx.x * BM;
    int wm = (wid & 3) * 32;
    int wn = (wid >> 2) * (BN / 2);

    float acc[2][NT][4];
#pragma unroll
    for (int i = 0; i < 2; i++)
#pragma unroll
        for (int j = 0; j < NT; j++)
#pragma unroll
            for (int r = 0; r < 4; r++) acc[i][j][r] = 0.f;

    for (int k0 = 0; k0 < K; k0 += BK) {
        if (k0) __syncthreads();
        for (int idx = tid; idx < BM * BK / 4; idx += 256) {
            int m = idx >> 4, k = (idx & 15) * 4;
            int row = m0 + m;
            float4 v = (row < nrows) ? *(const float4*)(A + (size_t)row * K + k0 + k)
                                     : make_float4(0.f, 0.f, 0.f, 0.f);
            __nv_bfloat16 h0, h1, h2, h3, l0, l1, l2, l3;
            cvt_hilo(v.x, h0, l0);
            cvt_hilo(v.y, h1, l1);
            cvt_hilo(v.z, h2, l2);
            cvt_hilo(v.w, h3, l3);
            __nv_bfloat162* ph = (__nv_bfloat162*)(sAh + m * LDK + k);
            ph[0] = __halves2bfloat162(h0, h1);
            ph[1] = __halves2bfloat162(h2, h3);
            __nv_bfloat162* pl = (__nv_bfloat162*)(sAl + m * LDK + k);
            pl[0] = __halves2bfloat162(l0, l1);
            pl[1] = __halves2bfloat162(l2, l3);
        }
        for (int idx = tid; idx < BN * BK; idx += 256) {
            int k = idx / BN, n = idx % BN;
            float v = W[(size_t)(k0 + k) * BN + n];
            __nv_bfloat16 hi, lo;
            cvt_hilo(v, hi, lo);
            sBh[n * LDK + k] = hi;
            sBl[n * LDK + k] = lo;
        }
        __syncthreads();

#pragma unroll
        for (int kk = 0; kk < BK / 16; kk++) {
            int kb = kk * 16 + 2 * tg;
            uint32_t ah[2][4], al[2][4];
#pragma unroll
            for (int mt = 0; mt < 2; mt++) {
                int r = wm + mt * 16 + g;
                ah[mt][0] = *(const uint32_t*)(sAh + r * LDK + kb);
                ah[mt][1] = *(const uint32_t*)(sAh + (r + 8) * LDK + kb);
                ah[mt][2] = *(const uint32_t*)(sAh + r * LDK + kb + 8);
                ah[mt][3] = *(const uint32_t*)(sAh + (r + 8) * LDK + kb + 8);
                al[mt][0] = *(const uint32_t*)(sAl + r * LDK + kb);
                al[mt][1] = *(const uint32_t*)(sAl + (r + 8) * LDK + kb);
                al[mt][2] = *(const uint32_t*)(sAl + r * LDK + kb + 8);
                al[mt][3] = *(const uint32_t*)(sAl + (r + 8) * LDK + kb + 8);
            }
#pragma unroll
            for (int nt = 0; nt < NT; nt++) {
                int nb = (wn + nt * 8 + g) * LDK + kb;
                uint32_t bh0 = *(const uint32_t*)(sBh + nb);
                uint32_t bh1 = *(const uint32_t*)(sBh + nb + 8);
                uint32_t bl0 = *(const uint32_t*)(sBl + nb);
                uint32_t bl1 = *(const uint32_t*)(sBl + nb + 8);
#pragma unroll
                for (int mt = 0; mt < 2; mt++) {
                    mma16816(acc[mt][nt], ah[mt], bh0, bh1);
                    mma16816(acc[mt][nt], al[mt], bh0, bh1);
                    mma16816(acc[mt][nt], ah[mt], bl0, bl1);
                }
            }
        }
    }

#pragma unroll
    for (int mt = 0; mt < 2; mt++) {
        int row0 = m0 + wm + mt * 16 + g;
        int row1 = row0 + 8;
#pragma unroll
        for (int nt = 0; nt < NT; nt++) {
            int col = wn + nt * 8 + 2 * tg;
            if (row0 < nrows)
                *(float2*)(C + (size_t)row0 * BN + col) =
                    make_float2(acc[mt][nt][0], acc[mt][nt][1]);
            if (row1 < nrows)
                *(float2*)(C + (size_t)row1 * BN + col) =
                    make_float2(acc[mt][nt][2], acc[mt][nt][3]);
        }
    }
}

// ---------------- CSR build ----------------
__global__ void zero_kernel(int* p, int n) {
    int i = blockIdx.x * blockDim.x + threadIdx.x;
    if (i < n) p[i] = 0;
}

__global__ void count_kernel(const int* __restrict__ dst, int* __restrict__ deg, int e) {
    for (int i = blockIdx.x * blockDim.x + threadIdx.x; i < e; i += gridDim.x * blockDim.x)
        atomicAdd(&deg[dst[i]], 1);
}

__global__ __launch_bounds__(1024) void scan_kernel(const int* __restrict__ deg,
                                                    int* __restrict__ off,
                                                    int* __restrict__ fill, int n) {
    __shared__ int sums[1024];
    int t = threadIdx.x;
    int chunk = (n + 1023) / 1024;
    int begin = t * chunk;
    int end = begin + chunk;
    if (end > n) end = n;
    if (begin > n) begin = n;
    int s = 0;
    for (int i = begin; i < end; i++) s += deg[i];
    sums[t] = s;
    __syncthreads();
    for (int d = 1; d < 1024; d <<= 1) {
        int v = (t >= d) ? sums[t - d] : 0;
        __syncthreads();
        sums[t] += v;
        __syncthreads();
    }
    int run = (t == 0) ? 0 : sums[t - 1];
    for (int i = begin; i < end; i++) {
        off[i] = run;
        fill[i] = run;
        run += deg[i];
    }
    if (t == 1023) off[n] = sums[1023];
}

__global__ void scatter_kernel(const int* __restrict__ src, const int* __restrict__ dst,
                               int* __restrict__ fill, int* __restrict__ csrsrc, int e) {
    for (int i = blockIdx.x * blockDim.x + threadIdx.x; i < e; i += gridDim.x * blockDim.x) {
        int pos = atomicAdd(&fill[dst[i]], 1);
        csrsrc[pos] = src[i];
    }
}

// ---------------- attention logits per node: el/er [N,2], vectorized ----------------
template <int D>
__global__ void eler_kernel(const float* __restrict__ h, const float* __restrict__ al,
                            const float* __restrict__ ar, float* __restrict__ el,
                            float* __restrict__ er, int n) {
    int i = blockIdx.x * blockDim.x + threadIdx.x;
    if (i >= n * 2) return;
    int node = i >> 1, hh = i & 1;
    const float4* row = (const float4*)(h + (size_t)node * (2 * D) + hh * D);
    const float4* a = (const float4*)(al + hh * D);
    const float4* b = (const float4*)(ar + hh * D);
    float s1 = 0.f, s2 = 0.f;
#pragma unroll
    for (int d = 0; d < D / 4; d++) {
        float4 v = row[d], av = a[d], bv = b[d];
        s1 = fmaf(v.x, av.x, fmaf(v.y, av.y, fmaf(v.z, av.z, fmaf(v.w, av.w, s1))));
        s2 = fmaf(v.x, bv.x, fmaf(v.y, bv.y, fmaf(v.z, bv.z, fmaf(v.w, bv.w, s2))));
    }
    el[i] = s1;
    er[i] = s2;
}

// ---------------- fused edge-softmax + aggregation + residual + act (+mean) ----------------
// ONE warp per node, both heads. Lane covers HD/32 contiguous floats of the row
// (lanes >= 16 are head 1). ACT: 0=ELU, 1=tanh. MEAN: average heads into [N,64].
template <int HD, int ACT, int MEAN>
__global__ __launch_bounds__(256) void aggsm_kernel(const float* __restrict__ hbuf,
                                                    const float* __restrict__ el,
                                                    const float* __restrict__ er,
                                                    const int* __restrict__ off,
                                                    const int* __restrict__ csr,
                                                    const float* __restrict__ resbuf,
                                                    float* __restrict__ out, int n) {
    constexpr int VEC = HD / 32;  // 4 (HD=128) or 2 (HD=64)
    int node = (blockIdx.x * blockDim.x + threadIdx.x) >> 5;
    int lane = threadIdx.x & 31;
    if (node >= n) return;
    int start = off[node], end = off[node + 1];
    float2 erh = ((const float2*)er)[node];

    // phase 1: online softmax stats for both heads
    float m0 = -1e30f, s0 = 0.f, m1 = -1e30f, s1 = 0.f;
    for (int i = start + lane; i < end; i += 32) {
        float2 ev = ((const float2*)el)[csr[i]];
        float e0 = ev.x + erh.x;
        e0 = e0 > 0.f ? e0 : 0.2f * e0;
        float e1 = ev.y + erh.y;
        e1 = e1 > 0.f ? e1 : 0.2f * e1;
        float M0 = fmaxf(m0, e0);
        s0 = s0 * __expf(m0 - M0) + __expf(e0 - M0);
        m0 = M0;
        float M1 = fmaxf(m1, e1);
        s1 = s1 * __expf(m1 - M1) + __expf(e1 - M1);
        m1 = M1;
    }
#pragma unroll
    for (int o = 16; o; o >>= 1) {
        float mo = __shfl_xor_sync(0xffffffffu, m0, o);
        float so = __shfl_xor_sync(0xffffffffu, s0, o);
        float M = fmaxf(m0, mo);
        s0 = s0 * __expf(m0 - M) + so * __expf(mo - M);
        m0 = M;
        mo = __shfl_xor_sync(0xffffffffu, m1, o);
        so = __shfl_xor_sync(0xffffffffu, s1, o);
        M = fmaxf(m1, mo);
        s1 = s1 * __expf(m1 - M) + so * __expf(mo - M);
        m1 = M;
    }
    float inv0 = (s0 > 0.f) ? 1.f / s0 : 0.f;
    float inv1 = (s1 > 0.f) ? 1.f / s1 : 0.f;

    // phase 2: weighted gather; weights broadcast from lanes
    float acc[VEC];
#pragma unroll
    for (int d = 0; d < VEC; d++) acc[d] = 0.f;
    bool hi = lane >= 16;

    for (int t = start; t < end; t += 32) {
        int i = t + lane;
        int s = 0;
        float w0 = 0.f, w1 = 0.f;
        if (i < end) {
            s = csr[i];
            float2 ev = ((const float2*)el)[s];
            float e0 = ev.x + erh.x;
            e0 = e0 > 0.f ? e0 : 0.2f * e0;
            float e1 = ev.y + erh.y;
            e1 = e1 > 0.f ? e1 : 0.2f * e1;
            w0 = __expf(e0 - m0) * inv0;
            w1 = __expf(e1 - m1) * inv1;
        }
        int cnt = min(32, end - t);
        if (cnt == 32) {
#pragma unroll 8
            for (int j = 0; j < 32; j++) {
                int sj = __shfl_sync(0xffffffffu, s, j);
                float wj0 = __shfl_sync(0xffffffffu, w0, j);
                float wj1 = __shfl_sync(0xffffffffu, w1, j);
                float w = hi ? wj1 : wj0;
                const float* row = hbuf + (size_t)sj * HD + lane * VEC;
                if (VEC == 4) {
                    float4 v = *(const float4*)row;
                    acc[0] = fmaf(v.x, w, acc[0]);
                    acc[1] = fmaf(v.y, w, acc[1]);
                    acc[2] = fmaf(v.z, w, acc[2]);
                    acc[3] = fmaf(v.w, w, acc[3]);
                } else {
                    float2 v = *(const float2*)row;
                    acc[0] = fmaf(v.x, w, acc[0]);
                    acc[1] = fmaf(v.y, w, acc[1]);
                }
            }
        } else {
            for (int j = 0; j < cnt; j++) {
                int sj = __shfl_sync(0xffffffffu, s, j);
                float wj0 = __shfl_sync(0xffffffffu, w0, j);
                float wj1 = __shfl_sync(0xffffffffu, w1, j);
                float w = hi ? wj1 : wj0;
                const float* row = hbuf + (size_t)sj * HD + lane * VEC;
                if (VEC == 4) {
                    float4 v = *(const float4*)row;
                    acc[0] = fmaf(v.x, w, acc[0]);
                    acc[1] = fmaf(v.y, w, acc[1]);
                    acc[2] = fmaf(v.z, w, acc[2]);
                    acc[3] = fmaf(v.w, w, acc[3]);
                } else {
                    float2 v = *(const float2*)row;
                    acc[0] = fmaf(v.x, w, acc[0]);
                    acc[1] = fmaf(v.y, w, acc[1]);
                }
            }
        }
    }

    // epilogue: residual + activation (+ head mean)
    size_t base = (size_t)node * HD + lane * VEC;
    float v[VEC];
    if (VEC == 4) {
        float4 r = *(const float4*)(resbuf + base);
        v[0] = acc[0] + r.x;
        v[1] = acc[1] + r.y;
        v[2] = acc[2] + r.z;
        v[3] = acc[3] + r.w;
    } else {
        float2 r = *(const float2*)(resbuf + base);
        v[0] = acc[0] + r.x;
        v[1] = acc[1] + r.y;
    }
#pragma unroll
    for (int d = 0; d < VEC; d++)
        v[d] = (ACT == 0) ? (v[d] > 0.f ? v[d] : expm1f(v[d])) : tanhf(v[d]);

    if (MEAN) {
        // HD==128: average lane (head0) with lane+16 (head1), lanes<16 write [N,64]
        float o[VEC];
#pragma unroll
        for (int d = 0; d < VEC; d++) {
            float vo = __shfl_xor_sync(0xffffffffu, v[d], 16);
            o[d] = 0.5f * (v[d] + vo);
        }
        if (lane < 16)
            *(float4*)(out + (size_t)node * 64 + lane * 4) = make_float4(o[0], o[1], o[2], o[3]);
    } else {
        if (VEC == 4)
            *(float4*)(out + base) = make_float4(v[0], v[1], v[2], v[3]);
        else
            *(float2*)(out + base) = make_float2(v[0], v[1]);
    }
}

// ---------------- host ----------------
template <typename T>
static T* symaddr(const void* sym) {
    void* p = nullptr;
    cudaGetSymbolAddress(&p, sym);
    return (T*)p;
}

extern "C" void kernel_launch(void* const* d_in, const int* in_sizes, int n_in,
                              void* d_out, int out_size) {
    const float* fvs = (const float*)d_in[0];
    const float* pos = (const float*)d_in[1];
    const int* src = (const int*)d_in[2];
    const int* dst = (const int*)d_in[3];
    const float* gW[3] = {(const float*)d_in[4], (const float*)d_in[8], (const float*)d_in[12]};
    const float* gal[3] = {(const float*)d_in[5], (const float*)d_in[9], (const float*)d_in[13]};
    const float* gar[3] = {(const float*)d_in[6], (const float*)d_in[10], (const float*)d_in[14]};
    const float* grW[3] = {(const float*)d_in[7], (const float*)d_in[11], (const float*)d_in[15]};
    const float* pW[2] = {(const float*)d_in[16], (const float*)d_in[19]};
    const float* pal[2] = {(const float*)d_in[17], (const float*)d_in[20]};
    const float* par[2] = {(const float*)d_in[18], (const float*)d_in[21]};

    int n = in_sizes[0] / 128;
    int e = in_sizes[2];
    float* out = (float*)d_out;
    float* out_hs = out;                   // [N,64]
    float* out_hp = out + (size_t)n * 64;  // [N,64]

    float* hB = symaddr<float>(g_h);
    float* resB = symaddr<float>(g_res);
    float* elB = symaddr<float>(g_el);
    float* erB = symaddr<float>(g_er);
    float* s1B = symaddr<float>(g_s1);
    float* s2B = symaddr<float>(g_s2);
    float* p1B = symaddr<float>(g_p1);
    int* degB = symaddr<int>(g_deg);
    int* offB = symaddr<int>(g_off);
    int* fillB = symaddr<int>(g_fill);
    int* csrB = symaddr<int>(g_csrsrc);

    const int SMEM_DUAL = (2 * 128 * 72 + 4 * 128 * 70) * 2;  // 108544
    const int SMEM_G64 = (2 * 128 * 72 + 2 * 64 * 72) * 2;    // 55296
    cudaFuncSetAttribute(gemm_dual_kernel, cudaFuncAttributeMaxDynamicSharedMemorySize,
                         SMEM_DUAL);
    cudaFuncSetAttribute(gemm_hmma_kernel<64>, cudaFuncAttributeMaxDynamicSharedMemorySize,
                         SMEM_G64);

    const int TB = 256;
    // ---- CSR build (by dst) ----
    zero_kernel<<<(n + TB - 1) / TB, TB>>>(degB, n);
    count_kernel<<<(e + TB - 1) / TB, TB>>>(dst, degB, e);
    scan_kernel<<<1, 1024>>>(degB, offB, fillB, n);
    scatter_kernel<<<(e + TB - 1) / TB, TB>>>(src, dst, fillB, csrB, e);

    int agg_blocks = (n * 32 + TB - 1) / TB;  // 1 warp per node
    int gemm_blocks = (n + 127) / 128;
    int eler_blocks = (n * 2 + TB - 1) / TB;

    // ---- layer 0: gat0 on concat(fvs, pos) ----
    gemm_dual_kernel<<<gemm_blocks, 512, SMEM_DUAL>>>(fvs, pos, gW[0], grW[0], hB, resB, n);
    eler_kernel<64><<<eler_blocks, TB>>>(hB, gal[0], gar[0], elB, erB, n);
    aggsm_kernel<128, 0, 0><<<agg_blocks, TB>>>(hB, elB, erB, offB, csrB, resB, s1B, n);

    // ---- pg0 on pos (identity residual, tanh) ----
    gemm_hmma_kernel<64><<<gemm_blocks, 256, SMEM_G64>>>(pos, pW[0], hB, n, 64);
    eler_kernel<32><<<eler_blocks, TB>>>(hB, pal[0], par[0], elB, erB, n);
    aggsm_kernel<64, 1, 0><<<agg_blocks, TB>>>(hB, elB, erB, offB, csrB, pos, p1B, n);

    // ---- layer 1: gat1 on concat(s1, p1) ----
    gemm_dual_kernel<<<gemm_blocks, 512, SMEM_DUAL>>>(s1B, p1B, gW[1], grW[1], hB, resB, n);
    eler_kernel<64><<<eler_blocks, TB>>>(hB, gal[1], gar[1], elB, erB, n);
    aggsm_kernel<128, 0, 0><<<agg_blocks, TB>>>(hB, elB, erB, offB, csrB, resB, s2B, n);

    // ---- pg1 on p1 (identity residual, tanh) -> final h_p into d_out ----
    gemm_hmma_kernel<64><<<gemm_blocks, 256, SMEM_G64>>>(p1B, pW[1], hB, n, 64);
    eler_kernel<32><<<eler_blocks, TB>>>(hB, pal[1], par[1], elB, erB, n);
    aggsm_kernel<64, 1, 0><<<agg_blocks, TB>>>(hB, elB, erB, offB, csrB, p1B, out_hp, n);

    // ---- layer 2: gat2 on concat(s2, h_p) -> elu -> mean heads (fused) ----
    gemm_dual_kernel<<<gemm_blocks, 512, SMEM_DUAL>>>(s2B, out_hp, gW[2], grW[2], hB, resB, n);
    eler_kernel<64><<<eler_blocks, TB>>>(hB, gal[2], gar[2], elB, erB, n);
    aggsm_kernel<128, 0, 1><<<agg_blocks, TB>>>(hB, elB, erB, offB, csrB, resB, out_hs, n);
}

// round 8
// speedup vs baseline: 2.1695x; 1.1246x over previous
#include <cuda_runtime.h>
#include <cuda_bf16.h>
#include <math.h>
#include <cstdint>

// Problem-fixed maxima (setup_inputs: N=50000, E=800000)
#define NMAXC 50000
#define EMAXC 800000

// ---------------- scratch (static __device__ — no allocs allowed) ----------------
__device__ float g_h[NMAXC * 128];
__device__ float g_res[NMAXC * 128];
__device__ float g_el[NMAXC * 2];
__device__ float g_er[NMAXC * 2];
__device__ float g_s1[NMAXC * 128];
__device__ float g_s2[NMAXC * 128];
__device__ float g_p1[NMAXC * 64];
__device__ int g_deg[NMAXC];
__device__ int g_off[NMAXC + 1];
__device__ int g_fill[NMAXC];
__device__ int g_csrsrc[EMAXC];

// ---------------- HMMA helpers ----------------
__device__ __forceinline__ void mma16816(float* c, const uint32_t* a, uint32_t b0, uint32_t b1) {
    asm volatile(
        "mma.sync.aligned.m16n8k16.row.col.f32.bf16.bf16.f32 "
        "{%0,%1,%2,%3}, {%4,%5,%6,%7}, {%8,%9}, {%0,%1,%2,%3};"
        : "+f"(c[0]), "+f"(c[1]), "+f"(c[2]), "+f"(c[3])
        : "r"(a[0]), "r"(a[1]), "r"(a[2]), "r"(a[3]), "r"(b0), "r"(b1));
}

__device__ __forceinline__ void cvt_hilo(float v, __nv_bfloat16& hi, __nv_bfloat16& lo) {
    hi = __float2bfloat16(v);
    lo = __float2bfloat16(v - __bfloat162float(hi));
}

// ---------------- fused dual GEMM + attention logits (gat layers) ----------------
// C1 = A@W1 (h), C2 = A@W2 (res); A = concat(A1[:,0:128], A2[:,0:64]), K=192, BN=128.
// Also emits el[node,2], er[node,2] = per-head dots of h with attL/attR (D=64).
__global__ __launch_bounds__(512) void gemm_dual_kernel(const float* __restrict__ A1,
                                                        const float* __restrict__ A2,
                                                        const float* __restrict__ W1,
                                                        const float* __restrict__ W2,
                                                        const float* __restrict__ attL,
                                                        const float* __restrict__ attR,
                                                        float* __restrict__ C1,
                                                        float* __restrict__ C2,
                                                        float* __restrict__ elg,
                                                        float* __restrict__ erg, int nrows) {
    constexpr int BM = 128, BN = 128, LDA = 72, LDB = 70;
    extern __shared__ __nv_bfloat16 sm[];
    __nv_bfloat16* sAh = sm;
    __nv_bfloat16* sAl = sAh + BM * LDA;
    __nv_bfloat16* sB1h = sAl + BM * LDA;
    __nv_bfloat16* sB1l = sB1h + BN * LDB;
    __nv_bfloat16* sB2h = sB1l + BN * LDB;
    __nv_bfloat16* sB2l = sB2h + BN * LDB;
    __shared__ float sEl[128][2];
    __shared__ float sEr[128][2];

    int tid = threadIdx.x, wid = tid >> 5, lane = tid & 31;
    int g = lane >> 2, tg = lane & 3;
    int m0 = blockIdx.x * BM;
    int wm = (wid & 3) * 32;
    int wn = (wid >> 2) * 32;

    if (tid < 128) {
        sEl[tid][0] = 0.f;
        sEl[tid][1] = 0.f;
        sEr[tid][0] = 0.f;
        sEr[tid][1] = 0.f;
    }

    float acc[2][2][4][4];
#pragma unroll
    for (int c = 0; c < 2; c++)
#pragma unroll
        for (int mt = 0; mt < 2; mt++)
#pragma unroll
            for (int nt = 0; nt < 4; nt++)
#pragma unroll
                for (int r = 0; r < 4; r++) acc[c][mt][nt][r] = 0.f;

#pragma unroll
    for (int c = 0; c < 3; c++) {
        if (c) __syncthreads();
        int k0 = c * 64;
        const float* Asrc = (c < 2) ? A1 : A2;
        int astride = (c < 2) ? 128 : 64;
        int kbase = (c < 2) ? k0 : 0;
#pragma unroll
        for (int t = 0; t < 4; t++) {
            int slot = tid + t * 512;
            int m = slot >> 4, k = (slot & 15) * 4;
            int row = m0 + m;
            float4 v = (row < nrows)
                           ? *(const float4*)(Asrc + (size_t)row * astride + kbase + k)
                           : make_float4(0.f, 0.f, 0.f, 0.f);
            __nv_bfloat16 h0, h1, h2, h3, l0, l1, l2, l3;
            cvt_hilo(v.x, h0, l0);
            cvt_hilo(v.y, h1, l1);
            cvt_hilo(v.z, h2, l2);
            cvt_hilo(v.w, h3, l3);
            __nv_bfloat162* ph = (__nv_bfloat162*)(sAh + m * LDA + k);
            ph[0] = __halves2bfloat162(h0, h1);
            ph[1] = __halves2bfloat162(h2, h3);
            __nv_bfloat162* pl = (__nv_bfloat162*)(sAl + m * LDA + k);
            pl[0] = __halves2bfloat162(l0, l1);
            pl[1] = __halves2bfloat162(l2, l3);
        }
#pragma unroll
        for (int mat = 0; mat < 2; mat++) {
            const float* W = mat ? W2 : W1;
            __nv_bfloat16* sBh = mat ? sB2h : sB1h;
            __nv_bfloat16* sBl = mat ? sB2l : sB1l;
#pragma unroll
            for (int t = 0; t < 4; t++) {
                int slot = tid + t * 512;
                int k = slot >> 5, n = (slot & 31) * 4;
                float4 v = *(const float4*)(W + (size_t)(k0 + k) * BN + n);
                __nv_bfloat16 hi, lo;
                cvt_hilo(v.x, hi, lo);
                sBh[(n + 0) * LDB + k] = hi;
                sBl[(n + 0) * LDB + k] = lo;
                cvt_hilo(v.y, hi, lo);
                sBh[(n + 1) * LDB + k] = hi;
                sBl[(n + 1) * LDB + k] = lo;
                cvt_hilo(v.z, hi, lo);
                sBh[(n + 2) * LDB + k] = hi;
                sBl[(n + 2) * LDB + k] = lo;
                cvt_hilo(v.w, hi, lo);
                sBh[(n + 3) * LDB + k] = hi;
                sBl[(n + 3) * LDB + k] = lo;
            }
        }
        __syncthreads();

#pragma unroll
        for (int kk = 0; kk < 4; kk++) {
            int kb = kk * 16 + 2 * tg;
            uint32_t ah[2][4], al[2][4];
#pragma unroll
            for (int mt = 0; mt < 2; mt++) {
                int r = wm + mt * 16 + g;
                ah[mt][0] = *(const uint32_t*)(sAh + r * LDA + kb);
                ah[mt][1] = *(const uint32_t*)(sAh + (r + 8) * LDA + kb);
                ah[mt][2] = *(const uint32_t*)(sAh + r * LDA + kb + 8);
                ah[mt][3] = *(const uint32_t*)(sAh + (r + 8) * LDA + kb + 8);
                al[mt][0] = *(const uint32_t*)(sAl + r * LDA + kb);
                al[mt][1] = *(const uint32_t*)(sAl + (r + 8) * LDA + kb);
                al[mt][2] = *(const uint32_t*)(sAl + r * LDA + kb + 8);
                al[mt][3] = *(const uint32_t*)(sAl + (r + 8) * LDA + kb + 8);
            }
#pragma unroll
            for (int nt = 0; nt < 4; nt++) {
                int nb = (wn + nt * 8 + g) * LDB + kb;
                uint32_t b1h0 = *(const uint32_t*)(sB1h + nb);
                uint32_t b1h1 = *(const uint32_t*)(sB1h + nb + 8);
                uint32_t b1l0 = *(const uint32_t*)(sB1l + nb);
                uint32_t b1l1 = *(const uint32_t*)(sB1l + nb + 8);
                uint32_t b2h0 = *(const uint32_t*)(sB2h + nb);
                uint32_t b2h1 = *(const uint32_t*)(sB2h + nb + 8);
                uint32_t b2l0 = *(const uint32_t*)(sB2l + nb);
                uint32_t b2l1 = *(const uint32_t*)(sB2l + nb + 8);
#pragma unroll
                for (int mt = 0; mt < 2; mt++) {
                    mma16816(acc[0][mt][nt], ah[mt], b1h0, b1h1);
                    mma16816(acc[0][mt][nt], al[mt], b1h0, b1h1);
                    mma16816(acc[0][mt][nt], ah[mt], b1l0, b1l1);
                    mma16816(acc[1][mt][nt], ah[mt], b2h0, b2h1);
                    mma16816(acc[1][mt][nt], al[mt], b2h0, b2h1);
                    mma16816(acc[1][mt][nt], ah[mt], b2l0, b2l1);
                }
            }
        }
    }

    // epilogue: write C1/C2
#pragma unroll
    for (int c = 0; c < 2; c++) {
        float* C = c ? C2 : C1;
#pragma unroll
        for (int mt = 0; mt < 2; mt++) {
            int row0 = m0 + wm + mt * 16 + g;
            int row1 = row0 + 8;
#pragma unroll
            for (int nt = 0; nt < 4; nt++) {
                int col = wn + nt * 8 + 2 * tg;
                if (row0 < nrows)
                    *(float2*)(C + (size_t)row0 * BN + col) =
                        make_float2(acc[c][mt][nt][0], acc[c][mt][nt][1]);
                if (row1 < nrows)
                    *(float2*)(C + (size_t)row1 * BN + col) =
                        make_float2(acc[c][mt][nt][2], acc[c][mt][nt][3]);
            }
        }
    }

    // fused attention logits from h (= acc[0]) : head = col/64, D=64
    {
        int head = (wn >= 64) ? 1 : 0;
        int cbase = wn & 63;
        float elp[4] = {0.f, 0.f, 0.f, 0.f}, erp[4] = {0.f, 0.f, 0.f, 0.f};
#pragma unroll
        for (int nt = 0; nt < 4; nt++) {
            int cih = cbase + nt * 8 + 2 * tg;
            float a0 = attL[head * 64 + cih], a1 = attL[head * 64 + cih + 1];
            float b0 = attR[head * 64 + cih], b1 = attR[head * 64 + cih + 1];
#pragma unroll
            for (int mt = 0; mt < 2; mt++) {
                elp[mt * 2 + 0] += acc[0][mt][nt][0] * a0 + acc[0][mt][nt][1] * a1;
                erp[mt * 2 + 0] += acc[0][mt][nt][0] * b0 + acc[0][mt][nt][1] * b1;
                elp[mt * 2 + 1] += acc[0][mt][nt][2] * a0 + acc[0][mt][nt][3] * a1;
                erp[mt * 2 + 1] += acc[0][mt][nt][2] * b0 + acc[0][mt][nt][3] * b1;
            }
        }
#pragma unroll
        for (int sl = 0; sl < 4; sl++) {
            float ev = elp[sl], rv = erp[sl];
            ev += __shfl_xor_sync(0xffffffffu, ev, 1);
            ev += __shfl_xor_sync(0xffffffffu, ev, 2);
            rv += __shfl_xor_sync(0xffffffffu, rv, 1);
            rv += __shfl_xor_sync(0xffffffffu, rv, 2);
            if (tg == 0) {
                int rl = wm + (sl >> 1) * 16 + g + (sl & 1) * 8;
                atomicAdd(&sEl[rl][head], ev);
                atomicAdd(&sEr[rl][head], rv);
            }
        }
        __syncthreads();
        if (tid < 128) {
            int row = m0 + tid;
            if (row < nrows) {
                ((float2*)elg)[row] = make_float2(sEl[tid][0], sEl[tid][1]);
                ((float2*)erg)[row] = make_float2(sEr[tid][0], sEr[tid][1]);
            }
        }
    }
}

// ---------------- single GEMM + logits (pg layers): C[n,64]=A[n,64]@W, D=32 ----------------
__global__ __launch_bounds__(256) void gemm_pg_kernel(const float* __restrict__ A,
                                                      const float* __restrict__ W,
                                                      const float* __restrict__ attL,
                                                      const float* __restrict__ attR,
                                                      float* __restrict__ C,
                                                      float* __restrict__ elg,
                                                      float* __restrict__ erg, int nrows) {
    constexpr int BM = 128, BN = 64, BK = 64, LDK = 72;
    constexpr int NT = 4;
    extern __shared__ __nv_bfloat16 sm2[];
    __nv_bfloat16* sAh = sm2;
    __nv_bfloat16* sAl = sAh + BM * LDK;
    __nv_bfloat16* sBh = sAl + BM * LDK;
    __nv_bfloat16* sBl = sBh + BN * LDK;
    __shared__ float sEl[128][2];
    __shared__ float sEr[128][2];

    int tid = threadIdx.x, wid = tid >> 5, lane = tid & 31;
    int g = lane >> 2, tg = lane & 3;
    int m0 = blockIdx.x * BM;
    int wm = (wid & 3) * 32;
    int wn = (wid >> 2) * 32;

    if (tid < 128) {
        sEl[tid][0] = 0.f;
        sEl[tid][1] = 0.f;
        sEr[tid][0] = 0.f;
        sEr[tid][1] = 0.f;
    }

    float acc[2][NT][4];
#pragma unroll
    for (int i = 0; i < 2; i++)
#pragma unroll
        for (int j = 0; j < NT; j++)
#pragma unroll
            for (int r = 0; r < 4; r++) acc[i][j][r] = 0.f;

    {
        for (int idx = tid; idx < BM * BK / 4; idx += 256) {
            int m = idx >> 4, k = (idx & 15) * 4;
            int row = m0 + m;
            float4 v = (row < nrows) ? *(const float4*)(A + (size_t)row * BK + k)
                                     : make_float4(0.f, 0.f, 0.f, 0.f);
            __nv_bfloat16 h0, h1, h2, h3, l0, l1, l2, l3;
            cvt_hilo(v.x, h0, l0);
            cvt_hilo(v.y, h1, l1);
            cvt_hilo(v.z, h2, l2);
            cvt_hilo(v.w, h3, l3);
            __nv_bfloat162* ph = (__nv_bfloat162*)(sAh + m * LDK + k);
            ph[0] = __halves2bfloat162(h0, h1);
            ph[1] = __halves2bfloat162(h2, h3);
            __nv_bfloat162* pl = (__nv_bfloat162*)(sAl + m * LDK + k);
            pl[0] = __halves2bfloat162(l0, l1);
            pl[1] = __halves2bfloat162(l2, l3);
        }
        for (int idx = tid; idx < BN * BK; idx += 256) {
            int k = idx / BN, n = idx % BN;
            float v = W[(size_t)k * BN + n];
            __nv_bfloat16 hi, lo;
            cvt_hilo(v, hi, lo);
            sBh[n * LDK + k] = hi;
            sBl[n * LDK + k] = lo;
        }
        __syncthreads();

#pragma unroll
        for (int kk = 0; kk < BK / 16; kk++) {
            int kb = kk * 16 + 2 * tg;
            uint32_t ah[2][4], al[2][4];
#pragma unroll
            for (int mt = 0; mt < 2; mt++) {
                int r = wm + mt * 16 + g;
                ah[mt][0] = *(const uint32_t*)(sAh + r * LDK + kb);
                ah[mt][1] = *(const uint32_t*)(sAh + (r + 8) * LDK + kb);
                ah[mt][2] = *(const uint32_t*)(sAh + r * LDK + kb + 8);
                ah[mt][3] = *(const uint32_t*)(sAh + (r + 8) * LDK + kb + 8);
                al[mt][0] = *(const uint32_t*)(sAl + r * LDK + kb);
                al[mt][1] = *(const uint32_t*)(sAl + (r + 8) * LDK + kb);
                al[mt][2] = *(const uint32_t*)(sAl + r * LDK + kb + 8);
                al[mt][3] = *(const uint32_t*)(sAl + (r + 8) * LDK + kb + 8);
            }
#pragma unroll
            for (int nt = 0; nt < NT; nt++) {
                int nb = ((wn & 31) + (wn >= 32 ? 32 : 0) + nt * 8 + g) * LDK + kb;
                uint32_t bh0 = *(const uint32_t*)(sBh + nb);
                uint32_t bh1 = *(const uint32_t*)(sBh + nb + 8);
                uint32_t bl0 = *(const uint32_t*)(sBl + nb);
                uint32_t bl1 = *(const uint32_t*)(sBl + nb + 8);
#pragma unroll
                for (int mt = 0; mt < 2; mt++) {
                    mma16816(acc[mt][nt], ah[mt], bh0, bh1);
                    mma16816(acc[mt][nt], al[mt], bh0, bh1);
                    mma16816(acc[mt][nt], ah[mt], bl0, bl1);
                }
            }
        }
    }

#pragma unroll
    for (int mt = 0; mt < 2; mt++) {
        int row0 = m0 + wm + mt * 16 + g;
        int row1 = row0 + 8;
#pragma unroll
        for (int nt = 0; nt < NT; nt++) {
            int col = wn + nt * 8 + 2 * tg;
            if (row0 < nrows)
                *(float2*)(C + (size_t)row0 * BN + col) =
                    make_float2(acc[mt][nt][0], acc[mt][nt][1]);
            if (row1 < nrows)
                *(float2*)(C + (size_t)row1 * BN + col) =
                    make_float2(acc[mt][nt][2], acc[mt][nt][3]);
        }
    }

    // fused attention logits: head = col/32, D=32
    {
        int head = (wn >= 32) ? 1 : 0;
        int cbase = wn & 31;
        float elp[4] = {0.f, 0.f, 0.f, 0.f}, erp[4] = {0.f, 0.f, 0.f, 0.f};
#pragma unroll
        for (int nt = 0; nt < NT; nt++) {
            int cih = cbase + nt * 8 + 2 * tg;
            float a0 = attL[head * 32 + cih], a1 = attL[head * 32 + cih + 1];
            float b0 = attR[head * 32 + cih], b1 = attR[head * 32 + cih + 1];
#pragma unroll
            for (int mt = 0; mt < 2; mt++) {
                elp[mt * 2 + 0] += acc[mt][nt][0] * a0 + acc[mt][nt][1] * a1;
                erp[mt * 2 + 0] += acc[mt][nt][0] * b0 + acc[mt][nt][1] * b1;
                elp[mt * 2 + 1] += acc[mt][nt][2] * a0 + acc[mt][nt][3] * a1;
                erp[mt * 2 + 1] += acc[mt][nt][2] * b0 + acc[mt][nt][3] * b1;
            }
        }
#pragma unroll
        for (int sl = 0; sl < 4; sl++) {
            float ev = elp[sl], rv = erp[sl];
            ev += __shfl_xor_sync(0xffffffffu, ev, 1);
            ev += __shfl_xor_sync(0xffffffffu, ev, 2);
            rv += __shfl_xor_sync(0xffffffffu, rv, 1);
            rv += __shfl_xor_sync(0xffffffffu, rv, 2);
            if (tg == 0) {
                int rl = wm + (sl >> 1) * 16 + g + (sl & 1) * 8;
                atomicAdd(&sEl[rl][head], ev);
                atomicAdd(&sEr[rl][head], rv);
            }
        }
        __syncthreads();
        if (tid < 128) {
            int row = m0 + tid;
            if (row < nrows) {
                ((float2*)elg)[row] = make_float2(sEl[tid][0], sEl[tid][1]);
                ((float2*)erg)[row] = make_float2(sEr[tid][0], sEr[tid][1]);
            }
        }
    }
}

// ---------------- CSR build ----------------
__global__ void count_kernel(const int* __restrict__ dst, int* __restrict__ deg, int e) {
    for (int i = blockIdx.x * blockDim.x + threadIdx.x; i < e; i += gridDim.x * blockDim.x)
        atomicAdd(&deg[dst[i]], 1);
}

__global__ __launch_bounds__(1024) void scan_kernel(const int* __restrict__ deg,
                                                    int* __restrict__ off,
                                                    int* __restrict__ fill, int n) {
    __shared__ int sums[1024];
    int t = threadIdx.x;
    int chunk = (n + 1023) / 1024;
    int begin = t * chunk;
    int end = begin + chunk;
    if (end > n) end = n;
    if (begin > n) begin = n;
    int s = 0;
    for (int i = begin; i < end; i++) s += deg[i];
    sums[t] = s;
    __syncthreads();
    for (int d = 1; d < 1024; d <<= 1) {
        int v = (t >= d) ? sums[t - d] : 0;
        __syncthreads();
        sums[t] += v;
        __syncthreads();
    }
    int run = (t == 0) ? 0 : sums[t - 1];
    for (int i = begin; i < end; i++) {
        off[i] = run;
        fill[i] = run;
        run += deg[i];
    }
    if (t == 1023) off[n] = sums[1023];
}

__global__ void scatter_kernel(const int* __restrict__ src, const int* __restrict__ dst,
                               int* __restrict__ fill, int* __restrict__ csrsrc, int e) {
    for (int i = blockIdx.x * blockDim.x + threadIdx.x; i < e; i += gridDim.x * blockDim.x) {
        int pos = atomicAdd(&fill[dst[i]], 1);
        csrsrc[pos] = src[i];
    }
}

// ---------------- fused edge-softmax + aggregation + residual + act (+mean) ----------------
template <int VEC>
__device__ __forceinline__ void gather_step(float* acc, const float* row, float w) {
    if (VEC == 4) {
        float4 v = *(const float4*)row;
        acc[0] = fmaf(v.x, w, acc[0]);
        acc[1] = fmaf(v.y, w, acc[1]);
        acc[2] = fmaf(v.z, w, acc[2]);
        acc[3] = fmaf(v.w, w, acc[3]);
    } else {
        float2 v = *(const float2*)row;
        acc[0] = fmaf(v.x, w, acc[0]);
        acc[1] = fmaf(v.y, w, acc[1]);
    }
}

// ONE warp per node, both heads. ACT: 0=ELU, 1=tanh. MEAN: average heads into [N,64].
template <int HD, int ACT, int MEAN>
__global__ __launch_bounds__(256) void aggsm_kernel(const float* __restrict__ hbuf,
                                                    const float* __restrict__ el,
                                                    const float* __restrict__ er,
                                                    const int* __restrict__ off,
                                                    const int* __restrict__ csr,
                                                    const float* __restrict__ resbuf,
                                                    float* __restrict__ out, int n) {
    constexpr int VEC = HD / 32;
    int node = (blockIdx.x * blockDim.x + threadIdx.x) >> 5;
    int lane = threadIdx.x & 31;
    if (node >= n) return;
    int start = off[node], end = off[node + 1];
    int deg = end - start;
    float2 erh = ((const float2*)er)[node];
    bool hi = lane >= 16;

    float acc[VEC];
#pragma unroll
    for (int d = 0; d < VEC; d++) acc[d] = 0.f;

    if (deg <= 32) {
        // --- fast path: everything stays in registers, single edge pass ---
        int i = start + lane;
        bool valid = i < end;
        int sv = 0;
        float e0 = -1e30f, e1 = -1e30f;
        if (valid) {
            sv = csr[i];
            float2 ev = ((const float2*)el)[sv];
            e0 = ev.x + erh.x;
            e0 = e0 > 0.f ? e0 : 0.2f * e0;
            e1 = ev.y + erh.y;
            e1 = e1 > 0.f ? e1 : 0.2f * e1;
        }
        float m0 = e0, s0 = valid ? 1.f : 0.f;
        float m1 = e1, s1 = valid ? 1.f : 0.f;
#pragma unroll
        for (int o = 16; o; o >>= 1) {
            float mo = __shfl_xor_sync(0xffffffffu, m0, o);
            float so = __shfl_xor_sync(0xffffffffu, s0, o);
            float M = fmaxf(m0, mo);
            s0 = s0 * __expf(m0 - M) + so * __expf(mo - M);
            m0 = M;
            mo = __shfl_xor_sync(0xffffffffu, m1, o);
            so = __shfl_xor_sync(0xffffffffu, s1, o);
            M = fmaxf(m1, mo);
            s1 = s1 * __expf(m1 - M) + so * __expf(mo - M);
            m1 = M;
        }
        float inv0 = (s0 > 0.f) ? 1.f / s0 : 0.f;
        float inv1 = (s1 > 0.f) ? 1.f / s1 : 0.f;
        float w0 = __expf(e0 - m0) * inv0;
        float w1 = __expf(e1 - m1) * inv1;

#pragma unroll 8
        for (int j = 0; j < deg; j++) {
            int sj = __shfl_sync(0xffffffffu, sv, j);
            float wj0 = __shfl_sync(0xffffffffu, w0, j);
            float wj1 = __shfl_sync(0xffffffffu, w1, j);
            gather_step<VEC>(acc, hbuf + (size_t)sj * HD + lane * VEC, hi ? wj1 : wj0);
        }
    } else {
        // --- general path ---
        float m0 = -1e30f, s0 = 0.f, m1 = -1e30f, s1 = 0.f;
        for (int i = start + lane; i < end; i += 32) {
            float2 ev = ((const float2*)el)[csr[i]];
            float e0 = ev.x + erh.x;
            e0 = e0 > 0.f ? e0 : 0.2f * e0;
            float e1 = ev.y + erh.y;
            e1 = e1 > 0.f ? e1 : 0.2f * e1;
            float M0 = fmaxf(m0, e0);
            s0 = s0 * __expf(m0 - M0) + __expf(e0 - M0);
            m0 = M0;
            float M1 = fmaxf(m1, e1);
            s1 = s1 * __expf(m1 - M1) + __expf(e1 - M1);
            m1 = M1;
        }
#pragma unroll
        for (int o = 16; o; o >>= 1) {
            float mo = __shfl_xor_sync(0xffffffffu, m0, o);
            float so = __shfl_xor_sync(0xffffffffu, s0, o);
            float M = fmaxf(m0, mo);
            s0 = s0 * __expf(m0 - M) + so * __expf(mo - M);
            m0 = M;
            mo = __shfl_xor_sync(0xffffffffu, m1, o);
            so = __shfl_xor_sync(0xffffffffu, s1, o);
            M = fmaxf(m1, mo);
            s1 = s1 * __expf(m1 - M) + so * __expf(mo - M);
            m1 = M;
        }
        float inv0 = (s0 > 0.f) ? 1.f / s0 : 0.f;
        float inv1 = (s1 > 0.f) ? 1.f / s1 : 0.f;

        for (int t = start; t < end; t += 32) {
            int i = t + lane;
            int s = 0;
            float w0 = 0.f, w1 = 0.f;
            if (i < end) {
                s = csr[i];
                float2 ev = ((const float2*)el)[s];
                float e0 = ev.x + erh.x;
                e0 = e0 > 0.f ? e0 : 0.2f * e0;
                float e1 = ev.y + erh.y;
                e1 = e1 > 0.f ? e1 : 0.2f * e1;
                w0 = __expf(e0 - m0) * inv0;
                w1 = __expf(e1 - m1) * inv1;
            }
            int cnt = min(32, end - t);
#pragma unroll 8
            for (int j = 0; j < cnt; j++) {
                int sj = __shfl_sync(0xffffffffu, s, j);
                float wj0 = __shfl_sync(0xffffffffu, w0, j);
                float wj1 = __shfl_sync(0xffffffffu, w1, j);
                gather_step<VEC>(acc, hbuf + (size_t)sj * HD + lane * VEC, hi ? wj1 : wj0);
            }
        }
    }

    // epilogue: residual + activation (+ head mean)
    size_t base = (size_t)node * HD + lane * VEC;
    float v[VEC];
    if (VEC == 4) {
        float4 r = *(const float4*)(resbuf + base);
        v[0] = acc[0] + r.x;
        v[1] = acc[1] + r.y;
        v[2] = acc[2] + r.z;
        v[3] = acc[3] + r.w;
    } else {
        float2 r = *(const float2*)(resbuf + base);
        v[0] = acc[0] + r.x;
        v[1] = acc[1] + r.y;
    }
#pragma unroll
    for (int d = 0; d < VEC; d++)
        v[d] = (ACT == 0) ? (v[d] > 0.f ? v[d] : expm1f(v[d])) : tanhf(v[d]);

    if (MEAN) {
        float o[VEC];
#pragma unroll
        for (int d = 0; d < VEC; d++) {
            float vo = __shfl_xor_sync(0xffffffffu, v[d], 16);
            o[d] = 0.5f * (v[d] + vo);
        }
        if (lane < 16)
            *(float4*)(out + (size_t)node * 64 + lane * 4) = make_float4(o[0], o[1], o[2], o[3]);
    } else {
        if (VEC == 4)
            *(float4*)(out + base) = make_float4(v[0], v[1], v[2], v[3]);
        else
            *(float2*)(out + base) = make_float2(v[0], v[1]);
    }
}

// ---------------- host ----------------
template <typename T>
static T* symaddr(const void* sym) {
    void* p = nullptr;
    cudaGetSymbolAddress(&p, sym);
    return (T*)p;
}

extern "C" void kernel_launch(void* const* d_in, const int* in_sizes, int n_in,
                              void* d_out, int out_size) {
    const float* fvs = (const float*)d_in[0];
    const float* pos = (const float*)d_in[1];
    const int* src = (const int*)d_in[2];
    const int* dst = (const int*)d_in[3];
    const float* gW[3] = {(const float*)d_in[4], (const float*)d_in[8], (const float*)d_in[12]};
    const float* gal[3] = {(const float*)d_in[5], (const float*)d_in[9], (const float*)d_in[13]};
    const float* gar[3] = {(const float*)d_in[6], (const float*)d_in[10], (const float*)d_in[14]};
    const float* grW[3] = {(const float*)d_in[7], (const float*)d_in[11], (const float*)d_in[15]};
    const float* pW[2] = {(const float*)d_in[16], (const float*)d_in[19]};
    const float* pal[2] = {(const float*)d_in[17], (const float*)d_in[20]};
    const float* par[2] = {(const float*)d_in[18], (const float*)d_in[21]};

    int n = in_sizes[0] / 128;
    int e = in_sizes[2];
    float* out = (float*)d_out;
    float* out_hs = out;                   // [N,64]
    float* out_hp = out + (size_t)n * 64;  // [N,64]

    float* hB = symaddr<float>(g_h);
    float* resB = symaddr<float>(g_res);
    float* elB = symaddr<float>(g_el);
    float* erB = symaddr<float>(g_er);
    float* s1B = symaddr<float>(g_s1);
    float* s2B = symaddr<float>(g_s2);
    float* p1B = symaddr<float>(g_p1);
    int* degB = symaddr<int>(g_deg);
    int* offB = symaddr<int>(g_off);
    int* fillB = symaddr<int>(g_fill);
    int* csrB = symaddr<int>(g_csrsrc);

    const int SMEM_DUAL = (2 * 128 * 72 + 4 * 128 * 70) * 2;  // 108544
    const int SMEM_PG = (2 * 128 * 72 + 2 * 64 * 72) * 2;     // 55296
    cudaFuncSetAttribute(gemm_dual_kernel, cudaFuncAttributeMaxDynamicSharedMemorySize,
                         SMEM_DUAL);
    cudaFuncSetAttribute(gemm_pg_kernel, cudaFuncAttributeMaxDynamicSharedMemorySize, SMEM_PG);

    const int TB = 256;
    // ---- CSR build (by dst) ----
    cudaMemsetAsync(degB, 0, (size_t)n * sizeof(int));
    count_kernel<<<(e + TB - 1) / TB, TB>>>(dst, degB, e);
    scan_kernel<<<1, 1024>>>(degB, offB, fillB, n);
    scatter_kernel<<<(e + TB - 1) / TB, TB>>>(src, dst, fillB, csrB, e);

    int agg_blocks = (n * 32 + TB - 1) / TB;  // 1 warp per node
    int gemm_blocks = (n + 127) / 128;

    // ---- layer 0: gat0 on concat(fvs, pos) ----
    gemm_dual_kernel<<<gemm_blocks, 512, SMEM_DUAL>>>(fvs, pos, gW[0], grW[0], gal[0], gar[0],
                                                      hB, resB, elB, erB, n);
    aggsm_kernel<128, 0, 0><<<agg_blocks, TB>>>(hB, elB, erB, offB, csrB, resB, s1B, n);

    // ---- pg0 on pos (identity residual, tanh) ----
    gemm_pg_kernel<<<gemm_blocks, 256, SMEM_PG>>>(pos, pW[0], pal[0], par[0], hB, elB, erB, n);
    aggsm_kernel<64, 1, 0><<<agg_blocks, TB>>>(hB, elB, erB, offB, csrB, pos, p1B, n);

    // ---- layer 1: gat1 on concat(s1, p1) ----
    gemm_dual_kernel<<<gemm_blocks, 512, SMEM_DUAL>>>(s1B, p1B, gW[1], grW[1], gal[1], gar[1],
                                                      hB, resB, elB, erB, n);
    aggsm_kernel<128, 0, 0><<<agg_blocks, TB>>>(hB, elB, erB, offB, csrB, resB, s2B, n);

    // ---- pg1 on p1 (identity residual, tanh) -> final h_p into d_out ----
    gemm_pg_kernel<<<gemm_blocks, 256, SMEM_PG>>>(p1B, pW[1], pal[1], par[1], hB, elB, erB, n);
    aggsm_kernel<64, 1, 0><<<agg_blocks, TB>>>(hB, elB, erB, offB, csrB, p1B, out_hp, n);

    // ---- layer 2: gat2 on concat(s2, h_p) -> elu -> mean heads (fused) ----
    gemm_dual_kernel<<<gemm_blocks, 512, SMEM_DUAL>>>(s2B, out_hp, gW[2], grW[2], gal[2], gar[2],
                                                      hB, resB, elB, erB, n);
    aggsm_kernel<128, 0, 1><<<agg_blocks, TB>>>(hB, elB, erB, offB, csrB, resB, out_hs, n);
}

// round 9
// speedup vs baseline: 2.4053x; 1.1087x over previous
#include <cuda_runtime.h>
#include <cuda_bf16.h>
#include <math.h>
#include <cstdint>

// Problem-fixed maxima (setup_inputs: N=50000, E=800000)
#define NMAXC 50000
#define EMAXC 800000
#define NPAD 50048  // 391 * 128

// ---------------- scratch (static __device__ — no allocs allowed) ----------------
__device__ __align__(16) float g_h[NMAXC * 128];
__device__ __align__(16) float g_res[NMAXC * 128];
__device__ __align__(16) float g_el[NMAXC * 2];
__device__ __align__(16) float g_er[NMAXC * 2];
__device__ __align__(16) float g_p1[NMAXC * 64];
__device__ int g_deg[NMAXC];
__device__ int g_off[NMAXC + 1];
__device__ int g_fill[NMAXC];
__device__ int g_csrsrc[EMAXC];
// bf16 hi/lo activation buffers, 192 cols each (concat layout), padded rows
__device__ __align__(16) __nv_bfloat16 g_b0h[NPAD * 192];
__device__ __align__(16) __nv_bfloat16 g_b0l[NPAD * 192];
__device__ __align__(16) __nv_bfloat16 g_b1h[NPAD * 192];
__device__ __align__(16) __nv_bfloat16 g_b1l[NPAD * 192];
// preconverted weights: 6 dual mats (3 chunks x 128n x 64k = 24576) + 2 pg (64n x 64k = 4096)
__device__ __align__(16) __nv_bfloat16 g_wh[6 * 24576 + 2 * 4096];
__device__ __align__(16) __nv_bfloat16 g_wl[6 * 24576 + 2 * 4096];

// ---------------- helpers ----------------
__device__ __forceinline__ void mma16816(float* c, const uint32_t* a, uint32_t b0, uint32_t b1) {
    asm volatile(
        "mma.sync.aligned.m16n8k16.row.col.f32.bf16.bf16.f32 "
        "{%0,%1,%2,%3}, {%4,%5,%6,%7}, {%8,%9}, {%0,%1,%2,%3};"
        : "+f"(c[0]), "+f"(c[1]), "+f"(c[2]), "+f"(c[3])
        : "r"(a[0]), "r"(a[1]), "r"(a[2]), "r"(a[3]), "r"(b0), "r"(b1));
}
__device__ __forceinline__ void ldsm4(uint32_t* r, uint32_t a) {
    asm volatile("ldmatrix.sync.aligned.m8n8.x4.shared.b16 {%0,%1,%2,%3}, [%4];"
                 : "=r"(r[0]), "=r"(r[1]), "=r"(r[2]), "=r"(r[3]) : "r"(a));
}
__device__ __forceinline__ uint32_t smem_u32(const void* p) {
    uint32_t a;
    asm("{ .reg .u64 t; cvta.to.shared.u64 t, %1; cvt.u32.u64 %0, t; }" : "=r"(a) : "l"(p));
    return a;
}
__device__ __forceinline__ void cvt_hilo(float v, __nv_bfloat16& hi, __nv_bfloat16& lo) {
    hi = __float2bfloat16(v);
    lo = __float2bfloat16(v - __bfloat162float(hi));
}
__device__ __forceinline__ uint32_t pack2(__nv_bfloat16 a, __nv_bfloat16 b) {
    __nv_bfloat162 t = __halves2bfloat162(a, b);
    return *(uint32_t*)&t;
}

// ---------------- setup: convert weights to bf16 hi/lo in smem-ready swizzled layout ----
// dual mats: layout per mat: chunk c (64 k), row n (128), unit u (8 k each):
//   elt offset = mat*24576 + c*8192 + n*64 + ((u ^ (n&7)) * 8)
__global__ void wsetup_dual(const float* W0, const float* W1, const float* W2,
                            const float* W3, const float* W4, const float* W5) {
    int idx = blockIdx.x * blockDim.x + threadIdx.x;
    if (idx >= 6 * 3 * 1024) return;
    int mat = idx / 3072;
    int r = idx % 3072;
    int c = r >> 10;
    int w = r & 1023;
    int n = w & 127, u = w >> 7;
    const float* Ws[6] = {W0, W1, W2, W3, W4, W5};
    const float* W = Ws[mat];
    uint32_t hp[4], lp[4];
#pragma unroll
    for (int j2 = 0; j2 < 4; j2++) {
        __nv_bfloat16 h0, l0, h1, l1;
        cvt_hilo(W[(c * 64 + u * 8 + 2 * j2) * 128 + n], h0, l0);
        cvt_hilo(W[(c * 64 + u * 8 + 2 * j2 + 1) * 128 + n], h1, l1);
        hp[j2] = pack2(h0, h1);
        lp[j2] = pack2(l0, l1);
    }
    int off = mat * 24576 + c * 8192 + n * 64 + ((u ^ (n & 7)) * 8);
    *(uint4*)(g_wh + off) = make_uint4(hp[0], hp[1], hp[2], hp[3]);
    *(uint4*)(g_wl + off) = make_uint4(lp[0], lp[1], lp[2], lp[3]);
}

__global__ void wsetup_pg(const float* W0, const float* W1) {
    int idx = blockIdx.x * blockDim.x + threadIdx.x;
    if (idx >= 2 * 512) return;
    int mat = idx >> 9;
    int w = idx & 511;
    int n = w & 63, u = w >> 6;
    const float* W = mat ? W1 : W0;
    uint32_t hp[4], lp[4];
#pragma unroll
    for (int j2 = 0; j2 < 4; j2++) {
        __nv_bfloat16 h0, l0, h1, l1;
        cvt_hilo(W[(u * 8 + 2 * j2) * 64 + n], h0, l0);
        cvt_hilo(W[(u * 8 + 2 * j2 + 1) * 64 + n], h1, l1);
        hp[j2] = pack2(h0, h1);
        lp[j2] = pack2(l0, l1);
    }
    int off = 6 * 24576 + mat * 4096 + n * 64 + ((u ^ (n & 7)) * 8);
    *(uint4*)(g_wh + off) = make_uint4(hp[0], hp[1], hp[2], hp[3]);
    *(uint4*)(g_wl + off) = make_uint4(lp[0], lp[1], lp[2], lp[3]);
}

// setup: fvs -> b0 cols 0..127, pos -> b0 cols 128..191 (bf16 hi/lo, row-major 192)
__global__ void fsetup(const float* __restrict__ fvs, const float* __restrict__ pos, int n) {
    int total = n * 48;  // float4 slots: 32 (fvs) + 16 (pos) per node
    for (int idx = blockIdx.x * blockDim.x + threadIdx.x; idx < total;
         idx += gridDim.x * blockDim.x) {
        int node, col;
        const float* src;
        if (idx < n * 32) {
            node = idx >> 5;
            col = (idx & 31) * 4;
            src = fvs + (size_t)node * 128 + col;
        } else {
            int t = idx - n * 32;
            node = t >> 4;
            col = (t & 15) * 4;
            src = pos + (size_t)node * 64 + col;
            col += 128;
        }
        float4 v = *(const float4*)src;
        __nv_bfloat16 h0, h1, h2, h3, l0, l1, l2, l3;
        cvt_hilo(v.x, h0, l0);
        cvt_hilo(v.y, h1, l1);
        cvt_hilo(v.z, h2, l2);
        cvt_hilo(v.w, h3, l3);
        size_t bo = (size_t)node * 192 + col;
        *(uint2*)(g_b0h + bo) = make_uint2(pack2(h0, h1), pack2(h2, h3));
        *(uint2*)(g_b0l + bo) = make_uint2(pack2(l0, l1), pack2(l2, l3));
    }
}

// ---------------- fused dual GEMM + attention logits (gat layers) ----------------
// C1 = A@W1 (h), C2 = A@W2 (res); A bf16 hi/lo 192-col buffer, K=192, BN=128.
__global__ __launch_bounds__(512) void gemm_dual_kernel(
    const __nv_bfloat16* __restrict__ Ah, const __nv_bfloat16* __restrict__ Al,
    const __nv_bfloat16* __restrict__ wbh, const __nv_bfloat16* __restrict__ wbl,
    const float* __restrict__ attL, const float* __restrict__ attR,
    float* __restrict__ C1, float* __restrict__ C2,
    float* __restrict__ elg, float* __restrict__ erg, int nrows) {
    extern __shared__ char smem[];
    const int SA_H = 0, SA_L = 16384, SB = 32768;  // B planes: m1h, m1l, m2h, m2l (16KB each)
    uint32_t sbase = smem_u32(smem);
    __shared__ float sEl[128][2];
    __shared__ float sEr[128][2];

    int tid = threadIdx.x, wid = tid >> 5, lane = tid & 31;
    int g = lane >> 2, tg = lane & 3;
    int m0 = blockIdx.x * 128;
    int wm = (wid & 3) * 32;
    int wn = (wid >> 2) * 32;
    int laneq = lane >> 4;
    int lane8 = (lane >> 3) & 1;

    if (tid < 128) {
        sEl[tid][0] = 0.f;
        sEl[tid][1] = 0.f;
        sEr[tid][0] = 0.f;
        sEr[tid][1] = 0.f;
    }

    // ldmatrix lane addresses (per-lane row bases)
    uint32_t aAddr[2];
    int aSw[2];
#pragma unroll
    for (int mt = 0; mt < 2; mt++) {
        int r = wm + mt * 16 + (lane & 15);
        aAddr[mt] = sbase + SA_H + r * 128;
        aSw[mt] = r & 7;
    }
    uint32_t bAddr[2];
    int bSw[2];
#pragma unroll
    for (int q = 0; q < 2; q++) {
        int nr = wn + (q * 2 + laneq) * 8 + (lane & 7);
        bAddr[q] = sbase + SB + nr * 128;
        bSw[q] = nr & 7;
    }

    float acc[2][2][4][4];
#pragma unroll
    for (int c = 0; c < 2; c++)
#pragma unroll
        for (int mt = 0; mt < 2; mt++)
#pragma unroll
            for (int nt = 0; nt < 4; nt++)
#pragma unroll
                for (int r = 0; r < 4; r++) acc[c][mt][nt][r] = 0.f;

#pragma unroll
    for (int c = 0; c < 3; c++) {
        if (c) __syncthreads();
        // A fill: 2048 16B units (2 planes x 128 rows x 8)
#pragma unroll
        for (int t = 0; t < 4; t++) {
            int s = tid + t * 512;
            int pl = s >> 10, w = s & 1023;
            int m = w >> 3, u = w & 7;
            const __nv_bfloat16* src =
                (pl ? Al : Ah) + (size_t)(m0 + m) * 192 + c * 64 + u * 8;
            uint4 v = *(const uint4*)src;
            *(uint4*)(smem + (pl ? SA_L : SA_H) + m * 128 + ((u ^ (m & 7)) << 4)) = v;
        }
        // B fill: 4096 16B units (4 planes x 128 rows x 8), straight copy
#pragma unroll
        for (int t = 0; t < 8; t++) {
            int s = tid + t * 512;
            int pl = s >> 10, w = s & 1023;
            const __nv_bfloat16* src = (pl & 1) ? wbl : wbh;
            src += (pl >> 1) * 24576 + c * 8192 + w * 8;
            uint4 v = *(const uint4*)src;
            *(uint4*)(smem + SB + pl * 16384 + w * 16) = v;
        }
        __syncthreads();

#pragma unroll
        for (int kk = 0; kk < 4; kk++) {
            uint32_t ah[2][4], alr[2][4];
#pragma unroll
            for (int mt = 0; mt < 2; mt++) {
                uint32_t ad = aAddr[mt] + (((2 * kk + laneq) ^ aSw[mt]) << 4);
                ldsm4(ah[mt], ad);
                ldsm4(alr[mt], ad + 16384);
            }
#pragma unroll
            for (int q = 0; q < 2; q++) {
                uint32_t bd = bAddr[q] + (((2 * kk + lane8) ^ bSw[q]) << 4);
                uint32_t f1h[4], f1l[4], f2h[4], f2l[4];
                ldsm4(f1h, bd);
                ldsm4(f1l, bd + 16384);
                ldsm4(f2h, bd + 32768);
                ldsm4(f2l, bd + 49152);
#pragma unroll
                for (int t2 = 0; t2 < 2; t2++) {
                    int nt = q * 2 + t2;
#pragma unroll
                    for (int mt = 0; mt < 2; mt++) {
                        mma16816(acc[0][mt][nt], ah[mt], f1h[2 * t2], f1h[2 * t2 + 1]);
                        mma16816(acc[0][mt][nt], alr[mt], f1h[2 * t2], f1h[2 * t2 + 1]);
                        mma16816(acc[0][mt][nt], ah[mt], f1l[2 * t2], f1l[2 * t2 + 1]);
                        mma16816(acc[1][mt][nt], ah[mt], f2h[2 * t2], f2h[2 * t2 + 1]);
                        mma16816(acc[1][mt][nt], alr[mt], f2h[2 * t2], f2h[2 * t2 + 1]);
                        mma16816(acc[1][mt][nt], ah[mt], f2l[2 * t2], f2l[2 * t2 + 1]);
                    }
                }
            }
        }
    }

    // epilogue: C1/C2 stores
#pragma unroll
    for (int c = 0; c < 2; c++) {
        float* C = c ? C2 : C1;
#pragma unroll
        for (int mt = 0; mt < 2; mt++) {
            int row0 = m0 + wm + mt * 16 + g;
            int row1 = row0 + 8;
#pragma unroll
            for (int nt = 0; nt < 4; nt++) {
                int col = wn + nt * 8 + 2 * tg;
                if (row0 < nrows)
                    *(float2*)(C + (size_t)row0 * 128 + col) =
                        make_float2(acc[c][mt][nt][0], acc[c][mt][nt][1]);
                if (row1 < nrows)
                    *(float2*)(C + (size_t)row1 * 128 + col) =
                        make_float2(acc[c][mt][nt][2], acc[c][mt][nt][3]);
            }
        }
    }

    // fused attention logits from h (= acc[0]); head = col/64, D=64
    {
        int head = (wn >= 64) ? 1 : 0;
        int cbase = wn & 63;
        float elp[4] = {0.f, 0.f, 0.f, 0.f}, erp[4] = {0.f, 0.f, 0.f, 0.f};
#pragma unroll
        for (int nt = 0; nt < 4; nt++) {
            int cih = cbase + nt * 8 + 2 * tg;
            float a0 = attL[head * 64 + cih], a1 = attL[head * 64 + cih + 1];
            float b0 = attR[head * 64 + cih], b1 = attR[head * 64 + cih + 1];
#pragma unroll
            for (int mt = 0; mt < 2; mt++) {
                elp[mt * 2 + 0] += acc[0][mt][nt][0] * a0 + acc[0][mt][nt][1] * a1;
                erp[mt * 2 + 0] += acc[0][mt][nt][0] * b0 + acc[0][mt][nt][1] * b1;
                elp[mt * 2 + 1] += acc[0][mt][nt][2] * a0 + acc[0][mt][nt][3] * a1;
                erp[mt * 2 + 1] += acc[0][mt][nt][2] * b0 + acc[0][mt][nt][3] * b1;
            }
        }
#pragma unroll
        for (int sl = 0; sl < 4; sl++) {
            float ev = elp[sl], rv = erp[sl];
            ev += __shfl_xor_sync(0xffffffffu, ev, 1);
            ev += __shfl_xor_sync(0xffffffffu, ev, 2);
            rv += __shfl_xor_sync(0xffffffffu, rv, 1);
            rv += __shfl_xor_sync(0xffffffffu, rv, 2);
            if (tg == 0) {
                int rl = wm + (sl >> 1) * 16 + g + (sl & 1) * 8;
                atomicAdd(&sEl[rl][head], ev);
                atomicAdd(&sEr[rl][head], rv);
            }
        }
        __syncthreads();
        if (tid < 128) {
            int row = m0 + tid;
            if (row < nrows) {
                ((float2*)elg)[row] = make_float2(sEl[tid][0], sEl[tid][1]);
                ((float2*)erg)[row] = make_float2(sEr[tid][0], sEr[tid][1]);
            }
        }
    }
}

// ---------------- pg GEMM + logits: C[n,64] = A[n,64]@W[64,64], D=32 ----------------
__global__ __launch_bounds__(256) void gemm_pg_kernel(
    const __nv_bfloat16* __restrict__ Ah, const __nv_bfloat16* __restrict__ Al,
    const __nv_bfloat16* __restrict__ wbh, const __nv_bfloat16* __restrict__ wbl,
    const float* __restrict__ attL, const float* __restrict__ attR,
    float* __restrict__ C, float* __restrict__ elg, float* __restrict__ erg,
    int k0base, int nrows) {
    extern __shared__ char smem2[];
    const int SA_H = 0, SA_L = 16384, SB_H = 32768, SB_L = 40960;
    uint32_t sbase = smem_u32(smem2);
    __shared__ float sEl[128][2];
    __shared__ float sEr[128][2];

    int tid = threadIdx.x, wid = tid >> 5, lane = tid & 31;
    int g = lane >> 2, tg = lane & 3;
    int m0 = blockIdx.x * 128;
    int wm = (wid & 3) * 32;
    int wn = (wid >> 2) * 32;
    int laneq = lane >> 4;
    int lane8 = (lane >> 3) & 1;

    if (tid < 128) {
        sEl[tid][0] = 0.f;
        sEl[tid][1] = 0.f;
        sEr[tid][0] = 0.f;
        sEr[tid][1] = 0.f;
    }

    uint32_t aAddr[2];
    int aSw[2];
#pragma unroll
    for (int mt = 0; mt < 2; mt++) {
        int r = wm + mt * 16 + (lane & 15);
        aAddr[mt] = sbase + SA_H + r * 128;
        aSw[mt] = r & 7;
    }
    uint32_t bAddr[2];
    int bSw[2];
#pragma unroll
    for (int q = 0; q < 2; q++) {
        int nr = wn + (q * 2 + laneq) * 8 + (lane & 7);
        bAddr[q] = sbase + SB_H + nr * 128;
        bSw[q] = nr & 7;
    }

    float acc[2][4][4];
#pragma unroll
    for (int mt = 0; mt < 2; mt++)
#pragma unroll
        for (int nt = 0; nt < 4; nt++)
#pragma unroll
            for (int r = 0; r < 4; r++) acc[mt][nt][r] = 0.f;

    // A fill: 2048 units
#pragma unroll
    for (int t = 0; t < 8; t++) {
        int s = tid + t * 256;
        int pl = s >> 10, w = s & 1023;
        int m = w >> 3, u = w & 7;
        const __nv_bfloat16* src = (pl ? Al : Ah) + (size_t)(m0 + m) * 192 + k0base + u * 8;
        uint4 v = *(const uint4*)src;
        *(uint4*)(smem2 + (pl ? SA_L : SA_H) + m * 128 + ((u ^ (m & 7)) << 4)) = v;
    }
    // B fill: 1024 units (2 planes x 64 rows x 8)
#pragma unroll
    for (int t = 0; t < 4; t++) {
        int s = tid + t * 256;
        int pl = s >> 9, w = s & 511;
        const __nv_bfloat16* src = (pl ? wbl : wbh) + w * 8;
        uint4 v = *(const uint4*)src;
        *(uint4*)(smem2 + (pl ? SB_L : SB_H) + w * 16) = v;
    }
    __syncthreads();

#pragma unroll
    for (int kk = 0; kk < 4; kk++) {
        uint32_t ah[2][4], alr[2][4];
#pragma unroll
        for (int mt = 0; mt < 2; mt++) {
            uint32_t ad = aAddr[mt] + (((2 * kk + laneq) ^ aSw[mt]) << 4);
            ldsm4(ah[mt], ad);
            ldsm4(alr[mt], ad + 16384);
        }
#pragma unroll
        for (int q = 0; q < 2; q++) {
            uint32_t bd = bAddr[q] + (((2 * kk + lane8) ^ bSw[q]) << 4);
            uint32_t fh[4], fl[4];
            ldsm4(fh, bd);
            ldsm4(fl, bd + 8192);
#pragma unroll
            for (int t2 = 0; t2 < 2; t2++) {
                int nt = q * 2 + t2;
#pragma unroll
                for (int mt = 0; mt < 2; mt++) {
                    mma16816(acc[mt][nt], ah[mt], fh[2 * t2], fh[2 * t2 + 1]);
                    mma16816(acc[mt][nt], alr[mt], fh[2 * t2], fh[2 * t2 + 1]);
                    mma16816(acc[mt][nt], ah[mt], fl[2 * t2], fl[2 * t2 + 1]);
                }
            }
        }
    }

#pragma unroll
    for (int mt = 0; mt < 2; mt++) {
        int row0 = m0 + wm + mt * 16 + g;
        int row1 = row0 + 8;
#pragma unroll
        for (int nt = 0; nt < 4; nt++) {
            int col = wn + nt * 8 + 2 * tg;
            if (row0 < nrows)
                *(float2*)(C + (size_t)row0 * 64 + col) =
                    make_float2(acc[mt][nt][0], acc[mt][nt][1]);
            if (row1 < nrows)
                *(float2*)(C + (size_t)row1 * 64 + col) =
                    make_float2(acc[mt][nt][2], acc[mt][nt][3]);
        }
    }

    // fused attention logits: head = col/32, D=32
    {
        int head = (wn >= 32) ? 1 : 0;
        int cbase = wn & 31;
        float elp[4] = {0.f, 0.f, 0.f, 0.f}, erp[4] = {0.f, 0.f, 0.f, 0.f};
#pragma unroll
        for (int nt = 0; nt < 4; nt++) {
            int cih = cbase + nt * 8 + 2 * tg;
            float a0 = attL[head * 32 + cih], a1 = attL[head * 32 + cih + 1];
            float b0 = attR[head * 32 + cih], b1 = attR[head * 32 + cih + 1];
#pragma unroll
            for (int mt = 0; mt < 2; mt++) {
                elp[mt * 2 + 0] += acc[mt][nt][0] * a0 + acc[mt][nt][1] * a1;
                erp[mt * 2 + 0] += acc[mt][nt][0] * b0 + acc[mt][nt][1] * b1;
                elp[mt * 2 + 1] += acc[mt][nt][2] * a0 + acc[mt][nt][3] * a1;
                erp[mt * 2 + 1] += acc[mt][nt][2] * b0 + acc[mt][nt][3] * b1;
            }
        }
#pragma unroll
        for (int sl = 0; sl < 4; sl++) {
            float ev = elp[sl], rv = erp[sl];
            ev += __shfl_xor_sync(0xffffffffu, ev, 1);
            ev += __shfl_xor_sync(0xffffffffu, ev, 2);
            rv += __shfl_xor_sync(0xffffffffu, rv, 1);
            rv += __shfl_xor_sync(0xffffffffu, rv, 2);
            if (tg == 0) {
                int rl = wm + (sl >> 1) * 16 + g + (sl & 1) * 8;
                atomicAdd(&sEl[rl][head], ev);
                atomicAdd(&sEr[rl][head], rv);
            }
        }
        __syncthreads();
        if (tid < 128) {
            int row = m0 + tid;
            if (row < nrows) {
                ((float2*)elg)[row] = make_float2(sEl[tid][0], sEl[tid][1]);
                ((float2*)erg)[row] = make_float2(sEr[tid][0], sEr[tid][1]);
            }
        }
    }
}

// ---------------- CSR build ----------------
__global__ void count_kernel(const int* __restrict__ dst, int* __restrict__ deg, int e) {
    for (int i = blockIdx.x * blockDim.x + threadIdx.x; i < e; i += gridDim.x * blockDim.x)
        atomicAdd(&deg[dst[i]], 1);
}

__global__ __launch_bounds__(1024) void scan_kernel(const int* __restrict__ deg,
                                                    int* __restrict__ off,
                                                    int* __restrict__ fill, int n) {
    __shared__ int sums[1024];
    int t = threadIdx.x;
    int chunk = (n + 1023) / 1024;
    int begin = t * chunk;
    int end = begin + chunk;
    if (end > n) end = n;
    if (begin > n) begin = n;
    int s = 0;
    for (int i = begin; i < end; i++) s += deg[i];
    sums[t] = s;
    __syncthreads();
    for (int d = 1; d < 1024; d <<= 1) {
        int v = (t >= d) ? sums[t - d] : 0;
        __syncthreads();
        sums[t] += v;
        __syncthreads();
    }
    int run = (t == 0) ? 0 : sums[t - 1];
    for (int i = begin; i < end; i++) {
        off[i] = run;
        fill[i] = run;
        run += deg[i];
    }
    if (t == 1023) off[n] = sums[1023];
}

__global__ void scatter_kernel(const int* __restrict__ src, const int* __restrict__ dst,
                               int* __restrict__ fill, int* __restrict__ csrsrc, int e) {
    for (int i = blockIdx.x * blockDim.x + threadIdx.x; i < e; i += gridDim.x * blockDim.x) {
        int pos = atomicAdd(&fill[dst[i]], 1);
        csrsrc[pos] = src[i];
    }
}

// ---------------- fused edge-softmax + aggregation + residual + act ----------------
template <int VEC>
__device__ __forceinline__ void gather_step(float* acc, const float* row, float w) {
    if (VEC == 4) {
        float4 v = *(const float4*)row;
        acc[0] = fmaf(v.x, w, acc[0]);
        acc[1] = fmaf(v.y, w, acc[1]);
        acc[2] = fmaf(v.z, w, acc[2]);
        acc[3] = fmaf(v.w, w, acc[3]);
    } else {
        float2 v = *(const float2*)row;
        acc[0] = fmaf(v.x, w, acc[0]);
        acc[1] = fmaf(v.y, w, acc[1]);
    }
}

// ONE warp per node. ACT: 0=ELU, 1=tanh. MEAN: head-mean to [N,64].
// WB: also write bf16 hi/lo into 192-col concat buffer at colofs. OF: write fp32 out.
template <int HD, int ACT, int MEAN, int WB, int OF>
__global__ __launch_bounds__(256) void aggsm_kernel(
    const float* __restrict__ hbuf, const float* __restrict__ el,
    const float* __restrict__ er, const int* __restrict__ off,
    const int* __restrict__ csr, const float* __restrict__ resbuf,
    float* __restrict__ out, __nv_bfloat16* __restrict__ bfh,
    __nv_bfloat16* __restrict__ bfl, int colofs, int n) {
    constexpr int VEC = HD / 32;
    int node = (blockIdx.x * blockDim.x + threadIdx.x) >> 5;
    int lane = threadIdx.x & 31;
    if (node >= n) return;
    int start = off[node], end = off[node + 1];
    int deg = end - start;
    float2 erh = ((const float2*)er)[node];
    bool hi = lane >= 16;

    float acc[VEC];
#pragma unroll
    for (int d = 0; d < VEC; d++) acc[d] = 0.f;

    if (deg <= 32) {
        int i = start + lane;
        bool valid = i < end;
        int sv = 0;
        float e0 = -1e30f, e1 = -1e30f;
        if (valid) {
            sv = csr[i];
            float2 ev = ((const float2*)el)[sv];
            e0 = ev.x + erh.x;
            e0 = e0 > 0.f ? e0 : 0.2f * e0;
            e1 = ev.y + erh.y;
            e1 = e1 > 0.f ? e1 : 0.2f * e1;
        }
        float m0 = e0, s0 = valid ? 1.f : 0.f;
        float m1 = e1, s1 = valid ? 1.f : 0.f;
#pragma unroll
        for (int o = 16; o; o >>= 1) {
            float mo = __shfl_xor_sync(0xffffffffu, m0, o);
            float so = __shfl_xor_sync(0xffffffffu, s0, o);
            float M = fmaxf(m0, mo);
            s0 = s0 * __expf(m0 - M) + so * __expf(mo - M);
            m0 = M;
            mo = __shfl_xor_sync(0xffffffffu, m1, o);
            so = __shfl_xor_sync(0xffffffffu, s1, o);
            M = fmaxf(m1, mo);
            s1 = s1 * __expf(m1 - M) + so * __expf(mo - M);
            m1 = M;
        }
        float inv0 = (s0 > 0.f) ? 1.f / s0 : 0.f;
        float inv1 = (s1 > 0.f) ? 1.f / s1 : 0.f;
        float w0 = __expf(e0 - m0) * inv0;
        float w1 = __expf(e1 - m1) * inv1;

#pragma unroll 8
        for (int j = 0; j < deg; j++) {
            int sj = __shfl_sync(0xffffffffu, sv, j);
            float wj0 = __shfl_sync(0xffffffffu, w0, j);
            float wj1 = __shfl_sync(0xffffffffu, w1, j);
            gather_step<VEC>(acc, hbuf + (size_t)sj * HD + lane * VEC, hi ? wj1 : wj0);
        }
    } else {
        float m0 = -1e30f, s0 = 0.f, m1 = -1e30f, s1 = 0.f;
        for (int i = start + lane; i < end; i += 32) {
            float2 ev = ((const float2*)el)[csr[i]];
            float e0 = ev.x + erh.x;
            e0 = e0 > 0.f ? e0 : 0.2f * e0;
            float e1 = ev.y + erh.y;
            e1 = e1 > 0.f ? e1 : 0.2f * e1;
            float M0 = fmaxf(m0, e0);
            s0 = s0 * __expf(m0 - M0) + __expf(e0 - M0);
            m0 = M0;
            float M1 = fmaxf(m1, e1);
            s1 = s1 * __expf(m1 - M1) + __expf(e1 - M1);
            m1 = M1;
        }
#pragma unroll
        for (int o = 16; o; o >>= 1) {
            float mo = __shfl_xor_sync(0xffffffffu, m0, o);
            float so = __shfl_xor_sync(0xffffffffu, s0, o);
            float M = fmaxf(m0, mo);
            s0 = s0 * __expf(m0 - M) + so * __expf(mo - M);
            m0 = M;
            mo = __shfl_xor_sync(0xffffffffu, m1, o);
            so = __shfl_xor_sync(0xffffffffu, s1, o);
            M = fmaxf(m1, mo);
            s1 = s1 * __expf(m1 - M) + so * __expf(mo - M);
            m1 = M;
        }
        float inv0 = (s0 > 0.f) ? 1.f / s0 : 0.f;
        float inv1 = (s1 > 0.f) ? 1.f / s1 : 0.f;

        for (int t = start; t < end; t += 32) {
            int i = t + lane;
            int s = 0;
            float w0 = 0.f, w1 = 0.f;
            if (i < end) {
                s = csr[i];
                float2 ev = ((const float2*)el)[s];
                float e0 = ev.x + erh.x;
                e0 = e0 > 0.f ? e0 : 0.2f * e0;
                float e1 = ev.y + erh.y;
                e1 = e1 > 0.f ? e1 : 0.2f * e1;
                w0 = __expf(e0 - m0) * inv0;
                w1 = __expf(e1 - m1) * inv1;
            }
            int cnt = min(32, end - t);
#pragma unroll 8
            for (int j = 0; j < cnt; j++) {
                int sj = __shfl_sync(0xffffffffu, s, j);
                float wj0 = __shfl_sync(0xffffffffu, w0, j);
                float wj1 = __shfl_sync(0xffffffffu, w1, j);
                gather_step<VEC>(acc, hbuf + (size_t)sj * HD + lane * VEC, hi ? wj1 : wj0);
            }
        }
    }

    // epilogue
    size_t base = (size_t)node * HD + lane * VEC;
    float v[4];
    if (VEC == 4) {
        float4 r = *(const float4*)(resbuf + base);
        v[0] = acc[0] + r.x;
        v[1] = acc[1] + r.y;
        v[2] = acc[2] + r.z;
        v[3] = acc[3] + r.w;
    } else {
        float2 r = *(const float2*)(resbuf + base);
        v[0] = acc[0] + r.x;
        v[1] = acc[1] + r.y;
    }
#pragma unroll
    for (int d = 0; d < VEC; d++)
        v[d] = (ACT == 0) ? (v[d] > 0.f ? v[d] : expm1f(v[d])) : tanhf(v[d]);

    if (MEAN) {
        float o[4];
#pragma unroll
        for (int d = 0; d < VEC; d++) {
            float vo = __shfl_xor_sync(0xffffffffu, v[d], 16);
            o[d] = 0.5f * (v[d] + vo);
        }
        if (lane < 16)
            *(float4*)(out + (size_t)node * 64 + lane * 4) = make_float4(o[0], o[1], o[2], o[3]);
    } else if (OF) {
        if (VEC == 4)
            *(float4*)(out + base) = make_float4(v[0], v[1], v[2], v[3]);
        else
            *(float2*)(out + base) = make_float2(v[0], v[1]);
    }
    if (WB) {
        __nv_bfloat16 hb[4], lb[4];
#pragma unroll
        for (int d = 0; d < VEC; d++) cvt_hilo(v[d], hb[d], lb[d]);
        size_t bo = (size_t)node * 192 + colofs + lane * VEC;
        if (VEC == 4) {
            *(uint2*)(bfh + bo) = make_uint2(pack2(hb[0], hb[1]), pack2(hb[2], hb[3]));
            *(uint2*)(bfl + bo) = make_uint2(pack2(lb[0], lb[1]), pack2(lb[2], lb[3]));
        } else {
            *(uint32_t*)(bfh + bo) = pack2(hb[0], hb[1]);
            *(uint32_t*)(bfl + bo) = pack2(lb[0], lb[1]);
        }
    }
}

// ---------------- host ----------------
template <typename T>
static T* symaddr(const void* sym) {
    void* p = nullptr;
    cudaGetSymbolAddress(&p, sym);
    return (T*)p;
}

extern "C" void kernel_launch(void* const* d_in, const int* in_sizes, int n_in,
                              void* d_out, int out_size) {
    const float* fvs = (const float*)d_in[0];
    const float* pos = (const float*)d_in[1];
    const int* src = (const int*)d_in[2];
    const int* dst = (const int*)d_in[3];
    const float* gW[3] = {(const float*)d_in[4], (const float*)d_in[8], (const float*)d_in[12]};
    const float* gal[3] = {(const float*)d_in[5], (const float*)d_in[9], (const float*)d_in[13]};
    const float* gar[3] = {(const float*)d_in[6], (const float*)d_in[10], (const float*)d_in[14]};
    const float* grW[3] = {(const float*)d_in[7], (const float*)d_in[11], (const float*)d_in[15]};
    const float* pW[2] = {(const float*)d_in[16], (const float*)d_in[19]};
    const float* pal[2] = {(const float*)d_in[17], (const float*)d_in[20]};
    const float* par[2] = {(const float*)d_in[18], (const float*)d_in[21]};

    int n = in_sizes[0] / 128;
    int e = in_sizes[2];
    float* out = (float*)d_out;
    float* out_hs = out;                   // [N,64]
    float* out_hp = out + (size_t)n * 64;  // [N,64]

    float* hB = symaddr<float>(g_h);
    float* resB = symaddr<float>(g_res);
    float* elB = symaddr<float>(g_el);
    float* erB = symaddr<float>(g_er);
    float* p1B = symaddr<float>(g_p1);
    int* degB = symaddr<int>(g_deg);
    int* offB = symaddr<int>(g_off);
    int* fillB = symaddr<int>(g_fill);
    int* csrB = symaddr<int>(g_csrsrc);
    __nv_bfloat16* b0h = symaddr<__nv_bfloat16>(g_b0h);
    __nv_bfloat16* b0l = symaddr<__nv_bfloat16>(g_b0l);
    __nv_bfloat16* b1h = symaddr<__nv_bfloat16>(g_b1h);
    __nv_bfloat16* b1l = symaddr<__nv_bfloat16>(g_b1l);
    __nv_bfloat16* wh = symaddr<__nv_bfloat16>(g_wh);
    __nv_bfloat16* wl = symaddr<__nv_bfloat16>(g_wl);

    const int SMEM_DUAL = 98304;
    const int SMEM_PG = 49152;
    cudaFuncSetAttribute(gemm_dual_kernel, cudaFuncAttributeMaxDynamicSharedMemorySize,
                         SMEM_DUAL);
    cudaFuncSetAttribute(gemm_pg_kernel, cudaFuncAttributeMaxDynamicSharedMemorySize, SMEM_PG);

    const int TB = 256;
    // ---- setup: weight + feature conversion ----
    wsetup_dual<<<(18432 + TB - 1) / TB, TB>>>(gW[0], grW[0], gW[1], grW[1], gW[2], grW[2]);
    wsetup_pg<<<(1024 + TB - 1) / TB, TB>>>(pW[0], pW[1]);
    fsetup<<<2048, TB>>>(fvs, pos, n);

    // ---- CSR build (by dst) ----
    cudaMemsetAsync(degB, 0, (size_t)n * sizeof(int));
    count_kernel<<<(e + TB - 1) / TB, TB>>>(dst, degB, e);
    scan_kernel<<<1, 1024>>>(degB, offB, fillB, n);
    scatter_kernel<<<(e + TB - 1) / TB, TB>>>(src, dst, fillB, csrB, e);

    int agg_blocks = (n * 32 + TB - 1) / TB;
    int gemm_blocks = (n + 127) / 128;

    // ---- layer 0: gat0 ----
    gemm_dual_kernel<<<gemm_blocks, 512, SMEM_DUAL>>>(b0h, b0l, wh, wl, gal[0], gar[0], hB,
                                                      resB, elB, erB, n);
    aggsm_kernel<128, 0, 0, 1, 0><<<agg_blocks, TB>>>(hB, elB, erB, offB, csrB, resB, hB, b1h,
                                                      b1l, 0, n);

    // ---- pg0 (identity residual, tanh) ----
    gemm_pg_kernel<<<gemm_blocks, 256, SMEM_PG>>>(b0h, b0l, wh + 6 * 24576, wl + 6 * 24576,
                                                  pal[0], par[0], hB, elB, erB, 128, n);
    aggsm_kernel<64, 1, 0, 1, 1><<<agg_blocks, TB>>>(hB, elB, erB, offB, csrB, pos, p1B, b1h,
                                                     b1l, 128, n);

    // ---- layer 1: gat1 ----
    gemm_dual_kernel<<<gemm_blocks, 512, SMEM_DUAL>>>(b1h, b1l, wh + 2 * 24576, wl + 2 * 24576,
                                                      gal[1], gar[1], hB, resB, elB, erB, n);
    aggsm_kernel<128, 0, 0, 1, 0><<<agg_blocks, TB>>>(hB, elB, erB, offB, csrB, resB, hB, b0h,
                                                      b0l, 0, n);

    // ---- pg1 -> final h_p (fp32 to d_out, bf16 to buf0 cols 128+) ----
    gemm_pg_kernel<<<gemm_blocks, 256, SMEM_PG>>>(b1h, b1l, wh + 6 * 24576 + 4096,
                                                  wl + 6 * 24576 + 4096, pal[1], par[1], hB,
                                                  elB, erB, 128, n);
    aggsm_kernel<64, 1, 0, 1, 1><<<agg_blocks, TB>>>(hB, elB, erB, offB, csrB, p1B, out_hp,
                                                     b0h, b0l, 128, n);

    // ---- layer 2: gat2 -> elu -> head mean ----
    gemm_dual_kernel<<<gemm_blocks, 512, SMEM_DUAL>>>(b0h, b0l, wh + 4 * 24576, wl + 4 * 24576,
                                                      gal[2], gar[2], hB, resB, elB, erB, n);
    aggsm_kernel<128, 0, 1, 0, 1><<<agg_blocks, TB>>>(hB, elB, erB, offB, csrB, resB, out_hs,
                                                      nullptr, nullptr, 0, n);
}

// round 10
// speedup vs baseline: 2.5068x; 1.0422x over previous
#include <cuda_runtime.h>
#include <cuda_bf16.h>
#include <math.h>
#include <cstdint>

// Problem-fixed maxima (setup_inputs: N=50000, E=800000)
#define NMAXC 50000
#define EMAXC 800000
#define NPAD 50048  // 391 * 128

// ---------------- scratch (static __device__ — no allocs allowed) ----------------
__device__ __align__(16) float g_h[NMAXC * 128];
__device__ __align__(16) float g_res[NMAXC * 128];
__device__ __align__(16) float g_el[NMAXC * 2];
__device__ __align__(16) float g_er[NMAXC * 2];
__device__ __align__(16) float g_p1[NMAXC * 64];
__device__ int g_deg[NMAXC];
__device__ int g_off[NMAXC + 1];
__device__ int g_fill[NMAXC];
__device__ int g_csrsrc[EMAXC];
// bf16 hi/lo activation buffers, 192 cols each (concat layout), padded rows
__device__ __align__(16) __nv_bfloat16 g_b0h[NPAD * 192];
__device__ __align__(16) __nv_bfloat16 g_b0l[NPAD * 192];
__device__ __align__(16) __nv_bfloat16 g_b1h[NPAD * 192];
__device__ __align__(16) __nv_bfloat16 g_b1l[NPAD * 192];
// preconverted weights: 6 dual mats (3 chunks x 128n x 64k = 24576) + 2 pg (64n x 64k = 4096)
__device__ __align__(16) __nv_bfloat16 g_wh[6 * 24576 + 2 * 4096];
__device__ __align__(16) __nv_bfloat16 g_wl[6 * 24576 + 2 * 4096];

// ---------------- helpers ----------------
__device__ __forceinline__ void mma16816(float* c, const uint32_t* a, uint32_t b0, uint32_t b1) {
    asm volatile(
        "mma.sync.aligned.m16n8k16.row.col.f32.bf16.bf16.f32 "
        "{%0,%1,%2,%3}, {%4,%5,%6,%7}, {%8,%9}, {%0,%1,%2,%3};"
        : "+f"(c[0]), "+f"(c[1]), "+f"(c[2]), "+f"(c[3])
        : "r"(a[0]), "r"(a[1]), "r"(a[2]), "r"(a[3]), "r"(b0), "r"(b1));
}
__device__ __forceinline__ void ldsm4(uint32_t* r, uint32_t a) {
    asm volatile("ldmatrix.sync.aligned.m8n8.x4.shared.b16 {%0,%1,%2,%3}, [%4];"
                 : "=r"(r[0]), "=r"(r[1]), "=r"(r[2]), "=r"(r[3]) : "r"(a));
}
__device__ __forceinline__ uint32_t smem_u32(const void* p) {
    uint32_t a;
    asm("{ .reg .u64 t; cvta.to.shared.u64 t, %1; cvt.u32.u64 %0, t; }" : "=r"(a) : "l"(p));
    return a;
}
__device__ __forceinline__ void cp16(uint32_t saddr, const void* g) {
    asm volatile("cp.async.cg.shared.global [%0], [%1], 16;" :: "r"(saddr), "l"(g));
}
__device__ __forceinline__ void cp_commit() { asm volatile("cp.async.commit_group;" ::: "memory"); }
template <int N>
__device__ __forceinline__ void cp_wait() {
    asm volatile("cp.async.wait_group %0;" :: "n"(N) : "memory");
}
__device__ __forceinline__ void cvt_hilo(float v, __nv_bfloat16& hi, __nv_bfloat16& lo) {
    hi = __float2bfloat16(v);
    lo = __float2bfloat16(v - __bfloat162float(hi));
}
__device__ __forceinline__ uint32_t pack2(__nv_bfloat16 a, __nv_bfloat16 b) {
    __nv_bfloat162 t = __halves2bfloat162(a, b);
    return *(uint32_t*)&t;
}

// ---------------- setup: convert weights to bf16 hi/lo in smem-ready swizzled layout ----
__global__ void wsetup_dual(const float* W0, const float* W1, const float* W2,
                            const float* W3, const float* W4, const float* W5) {
    int idx = blockIdx.x * blockDim.x + threadIdx.x;
    if (idx >= 6 * 3 * 1024) return;
    int mat = idx / 3072;
    int r = idx % 3072;
    int c = r >> 10;
    int w = r & 1023;
    int n = w & 127, u = w >> 7;
    const float* Ws[6] = {W0, W1, W2, W3, W4, W5};
    const float* W = Ws[mat];
    uint32_t hp[4], lp[4];
#pragma unroll
    for (int j2 = 0; j2 < 4; j2++) {
        __nv_bfloat16 h0, l0, h1, l1;
        cvt_hilo(W[(c * 64 + u * 8 + 2 * j2) * 128 + n], h0, l0);
        cvt_hilo(W[(c * 64 + u * 8 + 2 * j2 + 1) * 128 + n], h1, l1);
        hp[j2] = pack2(h0, h1);
        lp[j2] = pack2(l0, l1);
    }
    int off = mat * 24576 + c * 8192 + n * 64 + ((u ^ (n & 7)) * 8);
    *(uint4*)(g_wh + off) = make_uint4(hp[0], hp[1], hp[2], hp[3]);
    *(uint4*)(g_wl + off) = make_uint4(lp[0], lp[1], lp[2], lp[3]);
}

__global__ void wsetup_pg(const float* W0, const float* W1) {
    int idx = blockIdx.x * blockDim.x + threadIdx.x;
    if (idx >= 2 * 512) return;
    int mat = idx >> 9;
    int w = idx & 511;
    int n = w & 63, u = w >> 6;
    const float* W = mat ? W1 : W0;
    uint32_t hp[4], lp[4];
#pragma unroll
    for (int j2 = 0; j2 < 4; j2++) {
        __nv_bfloat16 h0, l0, h1, l1;
        cvt_hilo(W[(u * 8 + 2 * j2) * 64 + n], h0, l0);
        cvt_hilo(W[(u * 8 + 2 * j2 + 1) * 64 + n], h1, l1);
        hp[j2] = pack2(h0, h1);
        lp[j2] = pack2(l0, l1);
    }
    int off = 6 * 24576 + mat * 4096 + n * 64 + ((u ^ (n & 7)) * 8);
    *(uint4*)(g_wh + off) = make_uint4(hp[0], hp[1], hp[2], hp[3]);
    *(uint4*)(g_wl + off) = make_uint4(lp[0], lp[1], lp[2], lp[3]);
}

// setup: fvs -> b0 cols 0..127, pos -> b0 cols 128..191 (bf16 hi/lo, row-major 192)
__global__ void fsetup(const float* __restrict__ fvs, const float* __restrict__ pos, int n) {
    int total = n * 48;
    for (int idx = blockIdx.x * blockDim.x + threadIdx.x; idx < total;
         idx += gridDim.x * blockDim.x) {
        int node, col;
        const float* src;
        if (idx < n * 32) {
            node = idx >> 5;
            col = (idx & 31) * 4;
            src = fvs + (size_t)node * 128 + col;
        } else {
            int t = idx - n * 32;
            node = t >> 4;
            col = (t & 15) * 4;
            src = pos + (size_t)node * 64 + col;
            col += 128;
        }
        float4 v = *(const float4*)src;
        __nv_bfloat16 h0, h1, h2, h3, l0, l1, l2, l3;
        cvt_hilo(v.x, h0, l0);
        cvt_hilo(v.y, h1, l1);
        cvt_hilo(v.z, h2, l2);
        cvt_hilo(v.w, h3, l3);
        size_t bo = (size_t)node * 192 + col;
        *(uint2*)(g_b0h + bo) = make_uint2(pack2(h0, h1), pack2(h2, h3));
        *(uint2*)(g_b0l + bo) = make_uint2(pack2(l0, l1), pack2(l2, l3));
    }
}

// ---------------- fused dual GEMM + attention logits (gat layers) ----------------
// cp.async double-buffered: buffer = 96KB {A_H 16K, A_L 16K, B 64K}, two buffers.
__global__ __launch_bounds__(512) void gemm_dual_kernel(
    const __nv_bfloat16* __restrict__ Ah, const __nv_bfloat16* __restrict__ Al,
    const __nv_bfloat16* __restrict__ wbh, const __nv_bfloat16* __restrict__ wbl,
    const float* __restrict__ attL, const float* __restrict__ attR,
    float* __restrict__ C1, float* __restrict__ C2,
    float* __restrict__ elg, float* __restrict__ erg, int nrows) {
    extern __shared__ char smem[];
    const int SA_L = 16384, SB = 32768, BUFSZ = 98304;
    uint32_t sbase = smem_u32(smem);
    __shared__ float sEl[128][2];
    __shared__ float sEr[128][2];

    int tid = threadIdx.x, wid = tid >> 5, lane = tid & 31;
    int g = lane >> 2, tg = lane & 3;
    int m0 = blockIdx.x * 128;
    int wm = (wid & 3) * 32;
    int wn = (wid >> 2) * 32;
    int laneq = lane >> 4;
    int lane8 = (lane >> 3) & 1;

    if (tid < 128) {
        sEl[tid][0] = 0.f;
        sEl[tid][1] = 0.f;
        sEr[tid][0] = 0.f;
        sEr[tid][1] = 0.f;
    }

    // ldmatrix lane addresses (buffer-relative)
    uint32_t aAddr[2];
    int aSw[2];
#pragma unroll
    for (int mt = 0; mt < 2; mt++) {
        int r = wm + mt * 16 + (lane & 15);
        aAddr[mt] = sbase + r * 128;
        aSw[mt] = r & 7;
    }
    uint32_t bAddr[2];
    int bSw[2];
#pragma unroll
    for (int q = 0; q < 2; q++) {
        int nr = wn + (q * 2 + laneq) * 8 + (lane & 7);
        bAddr[q] = sbase + SB + nr * 128;
        bSw[q] = nr & 7;
    }

    // async fill of chunk c into buffer buf
    auto fill = [&](int c, int buf) {
        uint32_t sb = sbase + buf * BUFSZ;
#pragma unroll
        for (int t = 0; t < 4; t++) {
            int s = tid + t * 512;
            int pl = s >> 10, w = s & 1023;
            int m = w >> 3, u = w & 7;
            const __nv_bfloat16* src =
                (pl ? Al : Ah) + (size_t)(m0 + m) * 192 + c * 64 + u * 8;
            cp16(sb + pl * SA_L + m * 128 + ((u ^ (m & 7)) << 4), src);
        }
#pragma unroll
        for (int t = 0; t < 8; t++) {
            int s = tid + t * 512;
            int pl = s >> 10, w = s & 1023;
            const __nv_bfloat16* src = (pl & 1) ? wbl : wbh;
            src += (pl >> 1) * 24576 + c * 8192 + w * 8;
            cp16(sb + SB + pl * 16384 + w * 16, src);
        }
        cp_commit();
    };

    float acc[2][2][4][4];
#pragma unroll
    for (int c = 0; c < 2; c++)
#pragma unroll
        for (int mt = 0; mt < 2; mt++)
#pragma unroll
            for (int nt = 0; nt < 4; nt++)
#pragma unroll
                for (int r = 0; r < 4; r++) acc[c][mt][nt][r] = 0.f;

    fill(0, 0);
#pragma unroll
    for (int c = 0; c < 3; c++) {
        int buf = c & 1;
        uint32_t bofs = buf * BUFSZ;
        if (c) __syncthreads();  // all warps done reading the buffer we're about to overwrite
        if (c < 2) fill(c + 1, (c + 1) & 1);
        if (c < 2)
            cp_wait<1>();
        else
            cp_wait<0>();
        __syncthreads();

#pragma unroll
        for (int kk = 0; kk < 4; kk++) {
            uint32_t ah[2][4], alr[2][4];
#pragma unroll
            for (int mt = 0; mt < 2; mt++) {
                uint32_t ad = aAddr[mt] + bofs + (((2 * kk + laneq) ^ aSw[mt]) << 4);
                ldsm4(ah[mt], ad);
                ldsm4(alr[mt], ad + 16384);
            }
#pragma unroll
            for (int q = 0; q < 2; q++) {
                uint32_t bd = bAddr[q] + bofs + (((2 * kk + lane8) ^ bSw[q]) << 4);
                uint32_t f1h[4], f1l[4], f2h[4], f2l[4];
                ldsm4(f1h, bd);
                ldsm4(f1l, bd + 16384);
                ldsm4(f2h, bd + 32768);
                ldsm4(f2l, bd + 49152);
#pragma unroll
                for (int t2 = 0; t2 < 2; t2++) {
                    int nt = q * 2 + t2;
#pragma unroll
                    for (int mt = 0; mt < 2; mt++) {
                        mma16816(acc[0][mt][nt], ah[mt], f1h[2 * t2], f1h[2 * t2 + 1]);
                        mma16816(acc[0][mt][nt], alr[mt], f1h[2 * t2], f1h[2 * t2 + 1]);
                        mma16816(acc[0][mt][nt], ah[mt], f1l[2 * t2], f1l[2 * t2 + 1]);
                        mma16816(acc[1][mt][nt], ah[mt], f2h[2 * t2], f2h[2 * t2 + 1]);
                        mma16816(acc[1][mt][nt], alr[mt], f2h[2 * t2], f2h[2 * t2 + 1]);
                        mma16816(acc[1][mt][nt], ah[mt], f2l[2 * t2], f2l[2 * t2 + 1]);
                    }
                }
            }
        }
    }

    // epilogue: C1/C2 stores
#pragma unroll
    for (int c = 0; c < 2; c++) {
        float* C = c ? C2 : C1;
#pragma unroll
        for (int mt = 0; mt < 2; mt++) {
            int row0 = m0 + wm + mt * 16 + g;
            int row1 = row0 + 8;
#pragma unroll
            for (int nt = 0; nt < 4; nt++) {
                int col = wn + nt * 8 + 2 * tg;
                if (row0 < nrows)
                    *(float2*)(C + (size_t)row0 * 128 + col) =
                        make_float2(acc[c][mt][nt][0], acc[c][mt][nt][1]);
                if (row1 < nrows)
                    *(float2*)(C + (size_t)row1 * 128 + col) =
                        make_float2(acc[c][mt][nt][2], acc[c][mt][nt][3]);
            }
        }
    }

    // fused attention logits from h (= acc[0]); head = col/64, D=64
    {
        int head = (wn >= 64) ? 1 : 0;
        int cbase = wn & 63;
        float elp[4] = {0.f, 0.f, 0.f, 0.f}, erp[4] = {0.f, 0.f, 0.f, 0.f};
#pragma unroll
        for (int nt = 0; nt < 4; nt++) {
            int cih = cbase + nt * 8 + 2 * tg;
            float a0 = attL[head * 64 + cih], a1 = attL[head * 64 + cih + 1];
            float b0 = attR[head * 64 + cih], b1 = attR[head * 64 + cih + 1];
#pragma unroll
            for (int mt = 0; mt < 2; mt++) {
                elp[mt * 2 + 0] += acc[0][mt][nt][0] * a0 + acc[0][mt][nt][1] * a1;
                erp[mt * 2 + 0] += acc[0][mt][nt][0] * b0 + acc[0][mt][nt][1] * b1;
                elp[mt * 2 + 1] += acc[0][mt][nt][2] * a0 + acc[0][mt][nt][3] * a1;
                erp[mt * 2 + 1] += acc[0][mt][nt][2] * b0 + acc[0][mt][nt][3] * b1;
            }
        }
#pragma unroll
        for (int sl = 0; sl < 4; sl++) {
            float ev = elp[sl], rv = erp[sl];
            ev += __shfl_xor_sync(0xffffffffu, ev, 1);
            ev += __shfl_xor_sync(0xffffffffu, ev, 2);
            rv += __shfl_xor_sync(0xffffffffu, rv, 1);
            rv += __shfl_xor_sync(0xffffffffu, rv, 2);
            if (tg == 0) {
                int rl = wm + (sl >> 1) * 16 + g + (sl & 1) * 8;
                atomicAdd(&sEl[rl][head], ev);
                atomicAdd(&sEr[rl][head], rv);
            }
        }
        __syncthreads();
        if (tid < 128) {
            int row = m0 + tid;
            if (row < nrows) {
                ((float2*)elg)[row] = make_float2(sEl[tid][0], sEl[tid][1]);
                ((float2*)erg)[row] = make_float2(sEr[tid][0], sEr[tid][1]);
            }
        }
    }
}

// ---------------- pg GEMM + logits: C[n,64] = A[n,64]@W[64,64], D=32 ----------------
__global__ __launch_bounds__(256) void gemm_pg_kernel(
    const __nv_bfloat16* __restrict__ Ah, const __nv_bfloat16* __restrict__ Al,
    const __nv_bfloat16* __restrict__ wbh, const __nv_bfloat16* __restrict__ wbl,
    const float* __restrict__ attL, const float* __restrict__ attR,
    float* __restrict__ C, float* __restrict__ elg, float* __restrict__ erg,
    int k0base, int nrows) {
    extern __shared__ char smem2[];
    const int SA_H = 0, SA_L = 16384, SB_H = 32768, SB_L = 40960;
    uint32_t sbase = smem_u32(smem2);
    __shared__ float sEl[128][2];
    __shared__ float sEr[128][2];

    int tid = threadIdx.x, wid = tid >> 5, lane = tid & 31;
    int g = lane >> 2, tg = lane & 3;
    int m0 = blockIdx.x * 128;
    int wm = (wid & 3) * 32;
    int wn = (wid >> 2) * 32;
    int laneq = lane >> 4;
    int lane8 = (lane >> 3) & 1;

    if (tid < 128) {
        sEl[tid][0] = 0.f;
        sEl[tid][1] = 0.f;
        sEr[tid][0] = 0.f;
        sEr[tid][1] = 0.f;
    }

    uint32_t aAddr[2];
    int aSw[2];
#pragma unroll
    for (int mt = 0; mt < 2; mt++) {
        int r = wm + mt * 16 + (lane & 15);
        aAddr[mt] = sbase + SA_H + r * 128;
        aSw[mt] = r & 7;
    }
    uint32_t bAddr[2];
    int bSw[2];
#pragma unroll
    for (int q = 0; q < 2; q++) {
        int nr = wn + (q * 2 + laneq) * 8 + (lane & 7);
        bAddr[q] = sbase + SB_H + nr * 128;
        bSw[q] = nr & 7;
    }

    float acc[2][4][4];
#pragma unroll
    for (int mt = 0; mt < 2; mt++)
#pragma unroll
        for (int nt = 0; nt < 4; nt++)
#pragma unroll
            for (int r = 0; r < 4; r++) acc[mt][nt][r] = 0.f;

    // async fills
#pragma unroll
    for (int t = 0; t < 8; t++) {
        int s = tid + t * 256;
        int pl = s >> 10, w = s & 1023;
        int m = w >> 3, u = w & 7;
        const __nv_bfloat16* src = (pl ? Al : Ah) + (size_t)(m0 + m) * 192 + k0base + u * 8;
        cp16(sbase + (pl ? SA_L : SA_H) + m * 128 + ((u ^ (m & 7)) << 4), src);
    }
#pragma unroll
    for (int t = 0; t < 4; t++) {
        int s = tid + t * 256;
        int pl = s >> 9, w = s & 511;
        const __nv_bfloat16* src = (pl ? wbl : wbh) + w * 8;
        cp16(sbase + (pl ? SB_L : SB_H) + w * 16, src);
    }
    cp_commit();
    cp_wait<0>();
    __syncthreads();

#pragma unroll
    for (int kk = 0; kk < 4; kk++) {
        uint32_t ah[2][4], alr[2][4];
#pragma unroll
        for (int mt = 0; mt < 2; mt++) {
            uint32_t ad = aAddr[mt] + (((2 * kk + laneq) ^ aSw[mt]) << 4);
            ldsm4(ah[mt], ad);
            ldsm4(alr[mt], ad + 16384);
        }
#pragma unroll
        for (int q = 0; q < 2; q++) {
            uint32_t bd = bAddr[q] + (((2 * kk + lane8) ^ bSw[q]) << 4);
            uint32_t fh[4], fl[4];
            ldsm4(fh, bd);
            ldsm4(fl, bd + 8192);
#pragma unroll
            for (int t2 = 0; t2 < 2; t2++) {
                int nt = q * 2 + t2;
#pragma unroll
                for (int mt = 0; mt < 2; mt++) {
                    mma16816(acc[mt][nt], ah[mt], fh[2 * t2], fh[2 * t2 + 1]);
                    mma16816(acc[mt][nt], alr[mt], fh[2 * t2], fh[2 * t2 + 1]);
                    mma16816(acc[mt][nt], ah[mt], fl[2 * t2], fl[2 * t2 + 1]);
                }
            }
        }
    }

#pragma unroll
    for (int mt = 0; mt < 2; mt++) {
        int row0 = m0 + wm + mt * 16 + g;
        int row1 = row0 + 8;
#pragma unroll
        for (int nt = 0; nt < 4; nt++) {
            int col = wn + nt * 8 + 2 * tg;
            if (row0 < nrows)
                *(float2*)(C + (size_t)row0 * 64 + col) =
                    make_float2(acc[mt][nt][0], acc[mt][nt][1]);
            if (row1 < nrows)
                *(float2*)(C + (size_t)row1 * 64 + col) =
                    make_float2(acc[mt][nt][2], acc[mt][nt][3]);
        }
    }

    // fused attention logits: head = col/32, D=32
    {
        int head = (wn >= 32) ? 1 : 0;
        int cbase = wn & 31;
        float elp[4] = {0.f, 0.f, 0.f, 0.f}, erp[4] = {0.f, 0.f, 0.f, 0.f};
#pragma unroll
        for (int nt = 0; nt < 4; nt++) {
            int cih = cbase + nt * 8 + 2 * tg;
            float a0 = attL[head * 32 + cih], a1 = attL[head * 32 + cih + 1];
            float b0 = attR[head * 32 + cih], b1 = attR[head * 32 + cih + 1];
#pragma unroll
            for (int mt = 0; mt < 2; mt++) {
                elp[mt * 2 + 0] += acc[mt][nt][0] * a0 + acc[mt][nt][1] * a1;
                erp[mt * 2 + 0] += acc[mt][nt][0] * b0 + acc[mt][nt][1] * b1;
                elp[mt * 2 + 1] += acc[mt][nt][2] * a0 + acc[mt][nt][3] * a1;
                erp[mt * 2 + 1] += acc[mt][nt][2] * b0 + acc[mt][nt][3] * b1;
            }
        }
#pragma unroll
        for (int sl = 0; sl < 4; sl++) {
            float ev = elp[sl], rv = erp[sl];
            ev += __shfl_xor_sync(0xffffffffu, ev, 1);
            ev += __shfl_xor_sync(0xffffffffu, ev, 2);
            rv += __shfl_xor_sync(0xffffffffu, rv, 1);
            rv += __shfl_xor_sync(0xffffffffu, rv, 2);
            if (tg == 0) {
                int rl = wm + (sl >> 1) * 16 + g + (sl & 1) * 8;
                atomicAdd(&sEl[rl][head], ev);
                atomicAdd(&sEr[rl][head], rv);
            }
        }
        __syncthreads();
        if (tid < 128) {
            int row = m0 + tid;
            if (row < nrows) {
                ((float2*)elg)[row] = make_float2(sEl[tid][0], sEl[tid][1]);
                ((float2*)erg)[row] = make_float2(sEr[tid][0], sEr[tid][1]);
            }
        }
    }
}

// ---------------- CSR build ----------------
__global__ void count_kernel(const int* __restrict__ dst, int* __restrict__ deg, int e) {
    for (int i = blockIdx.x * blockDim.x + threadIdx.x; i < e; i += gridDim.x * blockDim.x)
        atomicAdd(&deg[dst[i]], 1);
}

__global__ __launch_bounds__(1024) void scan_kernel(const int* __restrict__ deg,
                                                    int* __restrict__ off,
                                                    int* __restrict__ fill, int n) {
    __shared__ int sums[1024];
    int t = threadIdx.x;
    int chunk = (n + 1023) / 1024;
    int begin = t * chunk;
    int end = begin + chunk;
    if (end > n) end = n;
    if (begin > n) begin = n;
    int s = 0;
    for (int i = begin; i < end; i++) s += deg[i];
    sums[t] = s;
    __syncthreads();
    for (int d = 1; d < 1024; d <<= 1) {
        int v = (t >= d) ? sums[t - d] : 0;
        __syncthreads();
        sums[t] += v;
        __syncthreads();
    }
    int run = (t == 0) ? 0 : sums[t - 1];
    for (int i = begin; i < end; i++) {
        off[i] = run;
        fill[i] = run;
        run += deg[i];
    }
    if (t == 1023) off[n] = sums[1023];
}

__global__ void scatter_kernel(const int* __restrict__ src, const int* __restrict__ dst,
                               int* __restrict__ fill, int* __restrict__ csrsrc, int e) {
    for (int i = blockIdx.x * blockDim.x + threadIdx.x; i < e; i += gridDim.x * blockDim.x) {
        int pos = atomicAdd(&fill[dst[i]], 1);
        csrsrc[pos] = src[i];
    }
}

// ---------------- fused edge-softmax + aggregation + residual + act ----------------
template <int VEC>
__device__ __forceinline__ void gather_step(float* acc, const float* row, float w) {
    if (VEC == 4) {
        float4 v = *(const float4*)row;
        acc[0] = fmaf(v.x, w, acc[0]);
        acc[1] = fmaf(v.y, w, acc[1]);
        acc[2] = fmaf(v.z, w, acc[2]);
        acc[3] = fmaf(v.w, w, acc[3]);
    } else {
        float2 v = *(const float2*)row;
        acc[0] = fmaf(v.x, w, acc[0]);
        acc[1] = fmaf(v.y, w, acc[1]);
    }
}

// ONE warp per node. ACT: 0=ELU, 1=tanh. MEAN: head-mean to [N,64].
// WB: also write bf16 hi/lo into 192-col concat buffer at colofs. OF: write fp32 out.
template <int HD, int ACT, int MEAN, int WB, int OF>
__global__ __launch_bounds__(256) void aggsm_kernel(
    const float* __restrict__ hbuf, const float* __restrict__ el,
    const float* __restrict__ er, const int* __restrict__ off,
    const int* __restrict__ csr, const float* __restrict__ resbuf,
    float* __restrict__ out, __nv_bfloat16* __restrict__ bfh,
    __nv_bfloat16* __restrict__ bfl, int colofs, int n) {
    constexpr int VEC = HD / 32;
    int node = (blockIdx.x * blockDim.x + threadIdx.x) >> 5;
    int lane = threadIdx.x & 31;
    if (node >= n) return;
    int start = off[node], end = off[node + 1];
    int deg = end - start;
    float2 erh = ((const float2*)er)[node];
    bool hi = lane >= 16;

    float acc[VEC];
#pragma unroll
    for (int d = 0; d < VEC; d++) acc[d] = 0.f;

    if (deg <= 32) {
        int i = start + lane;
        bool valid = i < end;
        int sv = 0;
        float e0 = -1e30f, e1 = -1e30f;
        if (valid) {
            sv = csr[i];
            float2 ev = ((const float2*)el)[sv];
            e0 = ev.x + erh.x;
            e0 = e0 > 0.f ? e0 : 0.2f * e0;
            e1 = ev.y + erh.y;
            e1 = e1 > 0.f ? e1 : 0.2f * e1;
        }
        float m0 = e0, s0 = valid ? 1.f : 0.f;
        float m1 = e1, s1 = valid ? 1.f : 0.f;
#pragma unroll
        for (int o = 16; o; o >>= 1) {
            float mo = __shfl_xor_sync(0xffffffffu, m0, o);
            float so = __shfl_xor_sync(0xffffffffu, s0, o);
            float M = fmaxf(m0, mo);
            s0 = s0 * __expf(m0 - M) + so * __expf(mo - M);
            m0 = M;
            mo = __shfl_xor_sync(0xffffffffu, m1, o);
            so = __shfl_xor_sync(0xffffffffu, s1, o);
            M = fmaxf(m1, mo);
            s1 = s1 * __expf(m1 - M) + so * __expf(mo - M);
            m1 = M;
        }
        float inv0 = (s0 > 0.f) ? 1.f / s0 : 0.f;
        float inv1 = (s1 > 0.f) ? 1.f / s1 : 0.f;
        float w0 = __expf(e0 - m0) * inv0;
        float w1 = __expf(e1 - m1) * inv1;

#pragma unroll 8
        for (int j = 0; j < deg; j++) {
            int sj = __shfl_sync(0xffffffffu, sv, j);
            float wj0 = __shfl_sync(0xffffffffu, w0, j);
            float wj1 = __shfl_sync(0xffffffffu, w1, j);
            gather_step<VEC>(acc, hbuf + (size_t)sj * HD + lane * VEC, hi ? wj1 : wj0);
        }
    } else {
        float m0 = -1e30f, s0 = 0.f, m1 = -1e30f, s1 = 0.f;
        for (int i = start + lane; i < end; i += 32) {
            float2 ev = ((const float2*)el)[csr[i]];
            float e0 = ev.x + erh.x;
            e0 = e0 > 0.f ? e0 : 0.2f * e0;
            float e1 = ev.y + erh.y;
            e1 = e1 > 0.f ? e1 : 0.2f * e1;
            float M0 = fmaxf(m0, e0);
            s0 = s0 * __expf(m0 - M0) + __expf(e0 - M0);
            m0 = M0;
            float M1 = fmaxf(m1, e1);
            s1 = s1 * __expf(m1 - M1) + __expf(e1 - M1);
            m1 = M1;
        }
#pragma unroll
        for (int o = 16; o; o >>= 1) {
            float mo = __shfl_xor_sync(0xffffffffu, m0, o);
            float so = __shfl_xor_sync(0xffffffffu, s0, o);
            float M = fmaxf(m0, mo);
            s0 = s0 * __expf(m0 - M) + so * __expf(mo - M);
            m0 = M;
            mo = __shfl_xor_sync(0xffffffffu, m1, o);
            so = __shfl_xor_sync(0xffffffffu, s1, o);
            M = fmaxf(m1, mo);
            s1 = s1 * __expf(m1 - M) + so * __expf(mo - M);
            m1 = M;
        }
        float inv0 = (s0 > 0.f) ? 1.f / s0 : 0.f;
        float inv1 = (s1 > 0.f) ? 1.f / s1 : 0.f;

        for (int t = start; t < end; t += 32) {
            int i = t + lane;
            int s = 0;
            float w0 = 0.f, w1 = 0.f;
            if (i < end) {
                s = csr[i];
                float2 ev = ((const float2*)el)[s];
                float e0 = ev.x + erh.x;
                e0 = e0 > 0.f ? e0 : 0.2f * e0;
                float e1 = ev.y + erh.y;
                e1 = e1 > 0.f ? e1 : 0.2f * e1;
                w0 = __expf(e0 - m0) * inv0;
                w1 = __expf(e1 - m1) * inv1;
            }
            int cnt = min(32, end - t);
#pragma unroll 8
            for (int j = 0; j < cnt; j++) {
                int sj = __shfl_sync(0xffffffffu, s, j);
                float wj0 = __shfl_sync(0xffffffffu, w0, j);
                float wj1 = __shfl_sync(0xffffffffu, w1, j);
                gather_step<VEC>(acc, hbuf + (size_t)sj * HD + lane * VEC, hi ? wj1 : wj0);
            }
        }
    }

    // epilogue
    size_t base = (size_t)node * HD + lane * VEC;
    float v[4];
    if (VEC == 4) {
        float4 r = *(const float4*)(resbuf + base);
        v[0] = acc[0] + r.x;
        v[1] = acc[1] + r.y;
        v[2] = acc[2] + r.z;
        v[3] = acc[3] + r.w;
    } else {
        float2 r = *(const float2*)(resbuf + base);
        v[0] = acc[0] + r.x;
        v[1] = acc[1] + r.y;
    }
#pragma unroll
    for (int d = 0; d < VEC; d++)
        v[d] = (ACT == 0) ? (v[d] > 0.f ? v[d] : expm1f(v[d])) : tanhf(v[d]);

    if (MEAN) {
        float o[4];
#pragma unroll
        for (int d = 0; d < VEC; d++) {
            float vo = __shfl_xor_sync(0xffffffffu, v[d], 16);
            o[d] = 0.5f * (v[d] + vo);
        }
        if (lane < 16)
            *(float4*)(out + (size_t)node * 64 + lane * 4) = make_float4(o[0], o[1], o[2], o[3]);
    } else if (OF) {
        if (VEC == 4)
            *(float4*)(out + base) = make_float4(v[0], v[1], v[2], v[3]);
        else
            *(float2*)(out + base) = make_float2(v[0], v[1]);
    }
    if (WB) {
        __nv_bfloat16 hb[4], lb[4];
#pragma unroll
        for (int d = 0; d < VEC; d++) cvt_hilo(v[d], hb[d], lb[d]);
        size_t bo = (size_t)node * 192 + colofs + lane * VEC;
        if (VEC == 4) {
            *(uint2*)(bfh + bo) = make_uint2(pack2(hb[0], hb[1]), pack2(hb[2], hb[3]));
            *(uint2*)(bfl + bo) = make_uint2(pack2(lb[0], lb[1]), pack2(lb[2], lb[3]));
        } else {
            *(uint32_t*)(bfh + bo) = pack2(hb[0], hb[1]);
            *(uint32_t*)(bfl + bo) = pack2(lb[0], lb[1]);
        }
    }
}

// ---------------- host ----------------
template <typename T>
static T* symaddr(const void* sym) {
    void* p = nullptr;
    cudaGetSymbolAddress(&p, sym);
    return (T*)p;
}

extern "C" void kernel_launch(void* const* d_in, const int* in_sizes, int n_in,
                              void* d_out, int out_size) {
    const float* fvs = (const float*)d_in[0];
    const float* pos = (const float*)d_in[1];
    const int* src = (const int*)d_in[2];
    const int* dst = (const int*)d_in[3];
    const float* gW[3] = {(const float*)d_in[4], (const float*)d_in[8], (const float*)d_in[12]};
    const float* gal[3] = {(const float*)d_in[5], (const float*)d_in[9], (const float*)d_in[13]};
    const float* gar[3] = {(const float*)d_in[6], (const float*)d_in[10], (const float*)d_in[14]};
    const float* grW[3] = {(const float*)d_in[7], (const float*)d_in[11], (const float*)d_in[15]};
    const float* pW[2] = {(const float*)d_in[16], (const float*)d_in[19]};
    const float* pal[2] = {(const float*)d_in[17], (const float*)d_in[20]};
    const float* par[2] = {(const float*)d_in[18], (const float*)d_in[21]};

    int n = in_sizes[0] / 128;
    int e = in_sizes[2];
    float* out = (float*)d_out;
    float* out_hs = out;                   // [N,64]
    float* out_hp = out + (size_t)n * 64;  // [N,64]

    float* hB = symaddr<float>(g_h);
    float* resB = symaddr<float>(g_res);
    float* elB = symaddr<float>(g_el);
    float* erB = symaddr<float>(g_er);
    float* p1B = symaddr<float>(g_p1);
    int* degB = symaddr<int>(g_deg);
    int* offB = symaddr<int>(g_off);
    int* fillB = symaddr<int>(g_fill);
    int* csrB = symaddr<int>(g_csrsrc);
    __nv_bfloat16* b0h = symaddr<__nv_bfloat16>(g_b0h);
    __nv_bfloat16* b0l = symaddr<__nv_bfloat16>(g_b0l);
    __nv_bfloat16* b1h = symaddr<__nv_bfloat16>(g_b1h);
    __nv_bfloat16* b1l = symaddr<__nv_bfloat16>(g_b1l);
    __nv_bfloat16* wh = symaddr<__nv_bfloat16>(g_wh);
    __nv_bfloat16* wl = symaddr<__nv_bfloat16>(g_wl);

    const int SMEM_DUAL = 196608;  // 2 x 96KB double buffer
    const int SMEM_PG = 49152;
    cudaFuncSetAttribute(gemm_dual_kernel, cudaFuncAttributeMaxDynamicSharedMemorySize,
                         SMEM_DUAL);
    cudaFuncSetAttribute(gemm_pg_kernel, cudaFuncAttributeMaxDynamicSharedMemorySize, SMEM_PG);

    const int TB = 256;
    // ---- setup: weight + feature conversion ----
    wsetup_dual<<<(18432 + TB - 1) / TB, TB>>>(gW[0], grW[0], gW[1], grW[1], gW[2], grW[2]);
    wsetup_pg<<<(1024 + TB - 1) / TB, TB>>>(pW[0], pW[1]);
    fsetup<<<2048, TB>>>(fvs, pos, n);

    // ---- CSR build (by dst) ----
    cudaMemsetAsync(degB, 0, (size_t)n * sizeof(int));
    count_kernel<<<(e + TB - 1) / TB, TB>>>(dst, degB, e);
    scan_kernel<<<1, 1024>>>(degB, offB, fillB, n);
    scatter_kernel<<<(e + TB - 1) / TB, TB>>>(src, dst, fillB, csrB, e);

    int agg_blocks = (n * 32 + TB - 1) / TB;
    int gemm_blocks = (n + 127) / 128;

    // ---- layer 0: gat0 ----
    gemm_dual_kernel<<<gemm_blocks, 512, SMEM_DUAL>>>(b0h, b0l, wh, wl, gal[0], gar[0], hB,
                                                      resB, elB, erB, n);
    aggsm_kernel<128, 0, 0, 1, 0><<<agg_blocks, TB>>>(hB, elB, erB, offB, csrB, resB, hB, b1h,
                                                      b1l, 0, n);

    // ---- pg0 (identity residual, tanh) ----
    gemm_pg_kernel<<<gemm_blocks, 256, SMEM_PG>>>(b0h, b0l, wh + 6 * 24576, wl + 6 * 24576,
                                                  pal[0], par[0], hB, elB, erB, 128, n);
    aggsm_kernel<64, 1, 0, 1, 1><<<agg_blocks, TB>>>(hB, elB, erB, offB, csrB, pos, p1B, b1h,
                                                     b1l, 128, n);

    // ---- layer 1: gat1 ----
    gemm_dual_kernel<<<gemm_blocks, 512, SMEM_DUAL>>>(b1h, b1l, wh + 2 * 24576, wl + 2 * 24576,
                                                      gal[1], gar[1], hB, resB, elB, erB, n);
    aggsm_kernel<128, 0, 0, 1, 0><<<agg_blocks, TB>>>(hB, elB, erB, offB, csrB, resB, hB, b0h,
                                                      b0l, 0, n);

    // ---- pg1 -> final h_p (fp32 to d_out, bf16 to buf0 cols 128+) ----
    gemm_pg_kernel<<<gemm_blocks, 256, SMEM_PG>>>(b1h, b1l, wh + 6 * 24576 + 4096,
                                                  wl + 6 * 24576 + 4096, pal[1], par[1], hB,
                                                  elB, erB, 128, n);
    aggsm_kernel<64, 1, 0, 1, 1><<<agg_blocks, TB>>>(hB, elB, erB, offB, csrB, p1B, out_hp,
                                                     b0h, b0l, 128, n);

    // ---- layer 2: gat2 -> elu -> head mean ----
    gemm_dual_kernel<<<gemm_blocks, 512, SMEM_DUAL>>>(b0h, b0l, wh + 4 * 24576, wl + 4 * 24576,
                                                      gal[2], gar[2], hB, resB, elB, erB, n);
    aggsm_kernel<128, 0, 1, 0, 1><<<agg_blocks, TB>>>(hB, elB, erB, offB, csrB, resB, out_hs,
                                                      nullptr, nullptr, 0, n);
}

// round 11
// speedup vs baseline: 2.5511x; 1.0177x over previous
#include <cuda_runtime.h>
#include <cuda_bf16.h>
#include <math.h>
#include <cstdint>

// Problem-fixed maxima (setup_inputs: N=50000, E=800000)
#define NMAXC 50000
#define EMAXC 800000
#define NPAD 50176  // 196 * 256 (covers pg 256-row blocking and gat 128-row blocking)

// ---------------- scratch (static __device__ — no allocs allowed) ----------------
__device__ __align__(16) float g_h[NMAXC * 128];
__device__ __align__(16) float g_res[NMAXC * 128];
__device__ __align__(16) float g_el[NMAXC * 2];
__device__ __align__(16) float g_er[NMAXC * 2];
__device__ __align__(16) float g_hp[NMAXC * 64];
__device__ __align__(16) float g_elp[NMAXC * 2];
__device__ __align__(16) float g_erp[NMAXC * 2];
__device__ __align__(16) float g_p1[NMAXC * 64];
__device__ int g_deg[NMAXC];
__device__ int g_off[NMAXC + 1];
__device__ int g_fill[NMAXC];
__device__ int g_csrsrc[EMAXC];
// bf16 hi/lo activation buffers, 192 cols each (concat layout), padded rows
__device__ __align__(16) __nv_bfloat16 g_b0h[NPAD * 192];
__device__ __align__(16) __nv_bfloat16 g_b0l[NPAD * 192];
__device__ __align__(16) __nv_bfloat16 g_b1h[NPAD * 192];
__device__ __align__(16) __nv_bfloat16 g_b1l[NPAD * 192];
// preconverted weights: 6 dual mats (3 chunks x 128n x 64k = 24576) + 2 pg (64n x 64k = 4096)
__device__ __align__(16) __nv_bfloat16 g_wh[6 * 24576 + 2 * 4096];
__device__ __align__(16) __nv_bfloat16 g_wl[6 * 24576 + 2 * 4096];

// ---------------- helpers ----------------
__device__ __forceinline__ void mma16816(float* c, const uint32_t* a, uint32_t b0, uint32_t b1) {
    asm volatile(
        "mma.sync.aligned.m16n8k16.row.col.f32.bf16.bf16.f32 "
        "{%0,%1,%2,%3}, {%4,%5,%6,%7}, {%8,%9}, {%0,%1,%2,%3};"
        : "+f"(c[0]), "+f"(c[1]), "+f"(c[2]), "+f"(c[3])
        : "r"(a[0]), "r"(a[1]), "r"(a[2]), "r"(a[3]), "r"(b0), "r"(b1));
}
__device__ __forceinline__ void ldsm4(uint32_t* r, uint32_t a) {
    asm volatile("ldmatrix.sync.aligned.m8n8.x4.shared.b16 {%0,%1,%2,%3}, [%4];"
                 : "=r"(r[0]), "=r"(r[1]), "=r"(r[2]), "=r"(r[3]) : "r"(a));
}
__device__ __forceinline__ uint32_t smem_u32(const void* p) {
    uint32_t a;
    asm("{ .reg .u64 t; cvta.to.shared.u64 t, %1; cvt.u32.u64 %0, t; }" : "=r"(a) : "l"(p));
    return a;
}
__device__ __forceinline__ void cp16(uint32_t saddr, const void* g) {
    asm volatile("cp.async.cg.shared.global [%0], [%1], 16;" :: "r"(saddr), "l"(g));
}
__device__ __forceinline__ void cp_commit() { asm volatile("cp.async.commit_group;" ::: "memory"); }
template <int N>
__device__ __forceinline__ void cp_wait() {
    asm volatile("cp.async.wait_group %0;" :: "n"(N) : "memory");
}
__device__ __forceinline__ void cvt_hilo(float v, __nv_bfloat16& hi, __nv_bfloat16& lo) {
    hi = __float2bfloat16(v);
    lo = __float2bfloat16(v - __bfloat162float(hi));
}
__device__ __forceinline__ uint32_t pack2(__nv_bfloat16 a, __nv_bfloat16 b) {
    __nv_bfloat162 t = __halves2bfloat162(a, b);
    return *(uint32_t*)&t;
}

// ---------------- setup kernels ----------------
__global__ void wsetup_dual(const float* W0, const float* W1, const float* W2,
                            const float* W3, const float* W4, const float* W5) {
    int idx = blockIdx.x * blockDim.x + threadIdx.x;
    if (idx >= 6 * 3 * 1024) return;
    int mat = idx / 3072;
    int r = idx % 3072;
    int c = r >> 10;
    int w = r & 1023;
    int n = w & 127, u = w >> 7;
    const float* Ws[6] = {W0, W1, W2, W3, W4, W5};
    const float* W = Ws[mat];
    uint32_t hp[4], lp[4];
#pragma unroll
    for (int j2 = 0; j2 < 4; j2++) {
        __nv_bfloat16 h0, l0, h1, l1;
        cvt_hilo(W[(c * 64 + u * 8 + 2 * j2) * 128 + n], h0, l0);
        cvt_hilo(W[(c * 64 + u * 8 + 2 * j2 + 1) * 128 + n], h1, l1);
        hp[j2] = pack2(h0, h1);
        lp[j2] = pack2(l0, l1);
    }
    int off = mat * 24576 + c * 8192 + n * 64 + ((u ^ (n & 7)) * 8);
    *(uint4*)(g_wh + off) = make_uint4(hp[0], hp[1], hp[2], hp[3]);
    *(uint4*)(g_wl + off) = make_uint4(lp[0], lp[1], lp[2], lp[3]);
}

__global__ void wsetup_pg(const float* W0, const float* W1) {
    int idx = blockIdx.x * blockDim.x + threadIdx.x;
    if (idx >= 2 * 512) return;
    int mat = idx >> 9;
    int w = idx & 511;
    int n = w & 63, u = w >> 6;
    const float* W = mat ? W1 : W0;
    uint32_t hp[4], lp[4];
#pragma unroll
    for (int j2 = 0; j2 < 4; j2++) {
        __nv_bfloat16 h0, l0, h1, l1;
        cvt_hilo(W[(u * 8 + 2 * j2) * 64 + n], h0, l0);
        cvt_hilo(W[(u * 8 + 2 * j2 + 1) * 64 + n], h1, l1);
        hp[j2] = pack2(h0, h1);
        lp[j2] = pack2(l0, l1);
    }
    int off = 6 * 24576 + mat * 4096 + n * 64 + ((u ^ (n & 7)) * 8);
    *(uint4*)(g_wh + off) = make_uint4(hp[0], hp[1], hp[2], hp[3]);
    *(uint4*)(g_wl + off) = make_uint4(lp[0], lp[1], lp[2], lp[3]);
}

// fsetup: feature conversion + edge degree count (fused; deg must be pre-zeroed)
__global__ void fsetup(const float* __restrict__ fvs, const float* __restrict__ pos,
                       const int* __restrict__ dst, int* __restrict__ deg, int n, int e) {
    int stride = gridDim.x * blockDim.x;
    int total = n * 48;
    for (int idx = blockIdx.x * blockDim.x + threadIdx.x; idx < total; idx += stride) {
        int node, col;
        const float* src;
        if (idx < n * 32) {
            node = idx >> 5;
            col = (idx & 31) * 4;
            src = fvs + (size_t)node * 128 + col;
        } else {
            int t = idx - n * 32;
            node = t >> 4;
            col = (t & 15) * 4;
            src = pos + (size_t)node * 64 + col;
            col += 128;
        }
        float4 v = *(const float4*)src;
        __nv_bfloat16 h0, h1, h2, h3, l0, l1, l2, l3;
        cvt_hilo(v.x, h0, l0);
        cvt_hilo(v.y, h1, l1);
        cvt_hilo(v.z, h2, l2);
        cvt_hilo(v.w, h3, l3);
        size_t bo = (size_t)node * 192 + col;
        *(uint2*)(g_b0h + bo) = make_uint2(pack2(h0, h1), pack2(h2, h3));
        *(uint2*)(g_b0l + bo) = make_uint2(pack2(l0, l1), pack2(l2, l3));
    }
    for (int i = blockIdx.x * blockDim.x + threadIdx.x; i < e; i += stride)
        atomicAdd(&deg[dst[i]], 1);
}

// ---------------- combined GEMM: dual-gat blocks + pg blocks in one grid ----------------
__global__ __launch_bounds__(512) void gemm_combo_kernel(
    const __nv_bfloat16* __restrict__ Ah, const __nv_bfloat16* __restrict__ Al,
    const __nv_bfloat16* __restrict__ wdh, const __nv_bfloat16* __restrict__ wdl,
    const float* __restrict__ attLg, const float* __restrict__ attRg,
    float* __restrict__ C1, float* __restrict__ C2,
    float* __restrict__ elg, float* __restrict__ erg,
    const __nv_bfloat16* __restrict__ wph, const __nv_bfloat16* __restrict__ wpl,
    const float* __restrict__ attLp, const float* __restrict__ attRp,
    float* __restrict__ Cp, float* __restrict__ elp, float* __restrict__ erp,
    int nbdual, int nrows) {
    extern __shared__ char smem[];
    uint32_t sbase = smem_u32(smem);
    __shared__ float sEl[256][2];
    __shared__ float sEr[256][2];

    int tid = threadIdx.x, lane = tid & 31;
    int g = lane >> 2, tg = lane & 3;
    int laneq = lane >> 4;
    int lane8 = (lane >> 3) & 1;

    if (tid < 256) {
        sEl[tid][0] = 0.f;
        sEl[tid][1] = 0.f;
        sEr[tid][0] = 0.f;
        sEr[tid][1] = 0.f;
    }

    if (blockIdx.x < nbdual) {
        // ================= dual GAT path (512 threads, BM=128, BN=128, K=192) =========
        const int SA_L = 16384, SB = 32768, BUFSZ = 98304;
        int wid = tid >> 5;
        int m0 = blockIdx.x * 128;
        int wm = (wid & 3) * 32;
        int wn = (wid >> 2) * 32;

        uint32_t aAddr[2];
        int aSw[2];
#pragma unroll
        for (int mt = 0; mt < 2; mt++) {
            int r = wm + mt * 16 + (lane & 15);
            aAddr[mt] = sbase + r * 128;
            aSw[mt] = r & 7;
        }
        uint32_t bAddr[2];
        int bSw[2];
#pragma unroll
        for (int q = 0; q < 2; q++) {
            int nr = wn + (q * 2 + laneq) * 8 + (lane & 7);
            bAddr[q] = sbase + SB + nr * 128;
            bSw[q] = nr & 7;
        }

        auto fill = [&](int c, int buf) {
            uint32_t sb = sbase + buf * BUFSZ;
#pragma unroll
            for (int t = 0; t < 4; t++) {
                int s = tid + t * 512;
                int pl = s >> 10, w = s & 1023;
                int m = w >> 3, u = w & 7;
                const __nv_bfloat16* src =
                    (pl ? Al : Ah) + (size_t)(m0 + m) * 192 + c * 64 + u * 8;
                cp16(sb + pl * SA_L + m * 128 + ((u ^ (m & 7)) << 4), src);
            }
#pragma unroll
            for (int t = 0; t < 8; t++) {
                int s = tid + t * 512;
                int pl = s >> 10, w = s & 1023;
                const __nv_bfloat16* src = (pl & 1) ? wdl : wdh;
                src += (pl >> 1) * 24576 + c * 8192 + w * 8;
                cp16(sb + SB + pl * 16384 + w * 16, src);
            }
            cp_commit();
        };

        float acc[2][2][4][4];
#pragma unroll
        for (int c = 0; c < 2; c++)
#pragma unroll
            for (int mt = 0; mt < 2; mt++)
#pragma unroll
                for (int nt = 0; nt < 4; nt++)
#pragma unroll
                    for (int r = 0; r < 4; r++) acc[c][mt][nt][r] = 0.f;

        fill(0, 0);
#pragma unroll
        for (int c = 0; c < 3; c++) {
            int buf = c & 1;
            uint32_t bofs = buf * BUFSZ;
            if (c) __syncthreads();
            if (c < 2) fill(c + 1, (c + 1) & 1);
            if (c < 2)
                cp_wait<1>();
            else
                cp_wait<0>();
            __syncthreads();

#pragma unroll
            for (int kk = 0; kk < 4; kk++) {
                uint32_t ah[2][4], alr[2][4];
#pragma unroll
                for (int mt = 0; mt < 2; mt++) {
                    uint32_t ad = aAddr[mt] + bofs + (((2 * kk + laneq) ^ aSw[mt]) << 4);
                    ldsm4(ah[mt], ad);
                    ldsm4(alr[mt], ad + 16384);
                }
#pragma unroll
                for (int q = 0; q < 2; q++) {
                    uint32_t bd = bAddr[q] + bofs + (((2 * kk + lane8) ^ bSw[q]) << 4);
                    uint32_t f1h[4], f1l[4], f2h[4], f2l[4];
                    ldsm4(f1h, bd);
                    ldsm4(f1l, bd + 16384);
                    ldsm4(f2h, bd + 32768);
                    ldsm4(f2l, bd + 49152);
#pragma unroll
                    for (int t2 = 0; t2 < 2; t2++) {
                        int nt = q * 2 + t2;
#pragma unroll
                        for (int mt = 0; mt < 2; mt++) {
                            mma16816(acc[0][mt][nt], ah[mt], f1h[2 * t2], f1h[2 * t2 + 1]);
                            mma16816(acc[0][mt][nt], alr[mt], f1h[2 * t2], f1h[2 * t2 + 1]);
                            mma16816(acc[0][mt][nt], ah[mt], f1l[2 * t2], f1l[2 * t2 + 1]);
                            mma16816(acc[1][mt][nt], ah[mt], f2h[2 * t2], f2h[2 * t2 + 1]);
                            mma16816(acc[1][mt][nt], alr[mt], f2h[2 * t2], f2h[2 * t2 + 1]);
                            mma16816(acc[1][mt][nt], ah[mt], f2l[2 * t2], f2l[2 * t2 + 1]);
                        }
                    }
                }
            }
        }

#pragma unroll
        for (int c = 0; c < 2; c++) {
            float* C = c ? C2 : C1;
#pragma unroll
            for (int mt = 0; mt < 2; mt++) {
                int row0 = m0 + wm + mt * 16 + g;
                int row1 = row0 + 8;
#pragma unroll
                for (int nt = 0; nt < 4; nt++) {
                    int col = wn + nt * 8 + 2 * tg;
                    if (row0 < nrows)
                        *(float2*)(C + (size_t)row0 * 128 + col) =
                            make_float2(acc[c][mt][nt][0], acc[c][mt][nt][1]);
                    if (row1 < nrows)
                        *(float2*)(C + (size_t)row1 * 128 + col) =
                            make_float2(acc[c][mt][nt][2], acc[c][mt][nt][3]);
                }
            }
        }

        // fused attention logits from h (= acc[0]); head = col/64, D=64
        int head = (wn >= 64) ? 1 : 0;
        int cbase = wn & 63;
        float elpv[4] = {0.f, 0.f, 0.f, 0.f}, erpv[4] = {0.f, 0.f, 0.f, 0.f};
#pragma unroll
        for (int nt = 0; nt < 4; nt++) {
            int cih = cbase + nt * 8 + 2 * tg;
            float a0 = attLg[head * 64 + cih], a1 = attLg[head * 64 + cih + 1];
            float b0 = attRg[head * 64 + cih], b1 = attRg[head * 64 + cih + 1];
#pragma unroll
            for (int mt = 0; mt < 2; mt++) {
                elpv[mt * 2 + 0] += acc[0][mt][nt][0] * a0 + acc[0][mt][nt][1] * a1;
                erpv[mt * 2 + 0] += acc[0][mt][nt][0] * b0 + acc[0][mt][nt][1] * b1;
                elpv[mt * 2 + 1] += acc[0][mt][nt][2] * a0 + acc[0][mt][nt][3] * a1;
                erpv[mt * 2 + 1] += acc[0][mt][nt][2] * b0 + acc[0][mt][nt][3] * b1;
            }
        }
#pragma unroll
        for (int sl = 0; sl < 4; sl++) {
            float ev = elpv[sl], rv = erpv[sl];
            ev += __shfl_xor_sync(0xffffffffu, ev, 1);
            ev += __shfl_xor_sync(0xffffffffu, ev, 2);
            rv += __shfl_xor_sync(0xffffffffu, rv, 1);
            rv += __shfl_xor_sync(0xffffffffu, rv, 2);
            if (tg == 0) {
                int rl = wm + (sl >> 1) * 16 + g + (sl & 1) * 8;
                atomicAdd(&sEl[rl][head], ev);
                atomicAdd(&sEr[rl][head], rv);
            }
        }
        __syncthreads();
        if (tid < 128) {
            int row = m0 + tid;
            if (row < nrows) {
                ((float2*)elg)[row] = make_float2(sEl[tid][0], sEl[tid][1]);
                ((float2*)erg)[row] = make_float2(sEr[tid][0], sEr[tid][1]);
            }
        }
    } else {
        // ================= pg path: two independent 256-thread halves, BM=128 each ====
        const int SA_L = 16384, SB_H = 32768, SB_L = 40960;  // within 48KB half-partition
        int half = tid >> 8;
        int htid = tid & 255;
        int hwid = htid >> 5;
        int m0 = (blockIdx.x - nbdual) * 256 + half * 128;
        int m0base = (blockIdx.x - nbdual) * 256;
        uint32_t shalf = sbase + half * 49152;
        int wm = (hwid & 3) * 32;
        int wn = (hwid >> 2) * 32;

        uint32_t aAddr[2];
        int aSw[2];
#pragma unroll
        for (int mt = 0; mt < 2; mt++) {
            int r = wm + mt * 16 + (lane & 15);
            aAddr[mt] = shalf + r * 128;
            aSw[mt] = r & 7;
        }
        uint32_t bAddr[2];
        int bSw[2];
#pragma unroll
        for (int q = 0; q < 2; q++) {
            int nr = wn + (q * 2 + laneq) * 8 + (lane & 7);
            bAddr[q] = shalf + SB_H + nr * 128;
            bSw[q] = nr & 7;
        }

        float acc[2][4][4];
#pragma unroll
        for (int mt = 0; mt < 2; mt++)
#pragma unroll
            for (int nt = 0; nt < 4; nt++)
#pragma unroll
                for (int r = 0; r < 4; r++) acc[mt][nt][r] = 0.f;

        // fills (A from cols 128..191 of the 192-col buffer)
#pragma unroll
        for (int t = 0; t < 8; t++) {
            int s = htid + t * 256;
            int pl = s >> 10, w = s & 1023;
            int m = w >> 3, u = w & 7;
            const __nv_bfloat16* src = (pl ? Al : Ah) + (size_t)(m0 + m) * 192 + 128 + u * 8;
            cp16(shalf + pl * SA_L + m * 128 + ((u ^ (m & 7)) << 4), src);
        }
#pragma unroll
        for (int t = 0; t < 4; t++) {
            int s = htid + t * 256;
            int pl = s >> 9, w = s & 511;
            const __nv_bfloat16* src = (pl ? wpl : wph) + w * 8;
            cp16(shalf + (pl ? SB_L : SB_H) + w * 16, src);
        }
        cp_commit();
        cp_wait<0>();
        __syncthreads();

#pragma unroll
        for (int kk = 0; kk < 4; kk++) {
            uint32_t ah[2][4], alr[2][4];
#pragma unroll
            for (int mt = 0; mt < 2; mt++) {
                uint32_t ad = aAddr[mt] + (((2 * kk + laneq) ^ aSw[mt]) << 4);
                ldsm4(ah[mt], ad);
                ldsm4(alr[mt], ad + 16384);
            }
#pragma unroll
            for (int q = 0; q < 2; q++) {
                uint32_t bd = bAddr[q] + (((2 * kk + lane8) ^ bSw[q]) << 4);
                uint32_t fh[4], fl[4];
                ldsm4(fh, bd);
                ldsm4(fl, bd + 8192);
#pragma unroll
                for (int t2 = 0; t2 < 2; t2++) {
                    int nt = q * 2 + t2;
#pragma unroll
                    for (int mt = 0; mt < 2; mt++) {
                        mma16816(acc[mt][nt], ah[mt], fh[2 * t2], fh[2 * t2 + 1]);
                        mma16816(acc[mt][nt], alr[mt], fh[2 * t2], fh[2 * t2 + 1]);
                        mma16816(acc[mt][nt], ah[mt], fl[2 * t2], fl[2 * t2 + 1]);
                    }
                }
            }
        }

#pragma unroll
        for (int mt = 0; mt < 2; mt++) {
            int row0 = m0 + wm + mt * 16 + g;
            int row1 = row0 + 8;
#pragma unroll
            for (int nt = 0; nt < 4; nt++) {
                int col = wn + nt * 8 + 2 * tg;
                if (row0 < nrows)
                    *(float2*)(Cp + (size_t)row0 * 64 + col) =
                        make_float2(acc[mt][nt][0], acc[mt][nt][1]);
                if (row1 < nrows)
                    *(float2*)(Cp + (size_t)row1 * 64 + col) =
                        make_float2(acc[mt][nt][2], acc[mt][nt][3]);
            }
        }

        // fused attention logits: head = col/32, D=32
        int head = (wn >= 32) ? 1 : 0;
        int cbase = wn & 31;
        float elpv[4] = {0.f, 0.f, 0.f, 0.f}, erpv[4] = {0.f, 0.f, 0.f, 0.f};
#pragma unroll
        for (int nt = 0; nt < 4; nt++) {
            int cih = cbase + nt * 8 + 2 * tg;
            float a0 = attLp[head * 32 + cih], a1 = attLp[head * 32 + cih + 1];
            float b0 = attRp[head * 32 + cih], b1 = attRp[head * 32 + cih + 1];
#pragma unroll
            for (int mt = 0; mt < 2; mt++) {
                elpv[mt * 2 + 0] += acc[mt][nt][0] * a0 + acc[mt][nt][1] * a1;
                erpv[mt * 2 + 0] += acc[mt][nt][0] * b0 + acc[mt][nt][1] * b1;
                elpv[mt * 2 + 1] += acc[mt][nt][2] * a0 + acc[mt][nt][3] * a1;
                erpv[mt * 2 + 1] += acc[mt][nt][2] * b0 + acc[mt][nt][3] * b1;
            }
        }
#pragma unroll
        for (int sl = 0; sl < 4; sl++) {
            float ev = elpv[sl], rv = erpv[sl];
            ev += __shfl_xor_sync(0xffffffffu, ev, 1);
            ev += __shfl_xor_sync(0xffffffffu, ev, 2);
            rv += __shfl_xor_sync(0xffffffffu, rv, 1);
            rv += __shfl_xor_sync(0xffffffffu, rv, 2);
            if (tg == 0) {
                int rl = half * 128 + wm + (sl >> 1) * 16 + g + (sl & 1) * 8;
                atomicAdd(&sEl[rl][head], ev);
                atomicAdd(&sEr[rl][head], rv);
            }
        }
        __syncthreads();
        if (tid < 256) {
            int row = m0base + tid;
            if (row < nrows) {
                ((float2*)elp)[row] = make_float2(sEl[tid][0], sEl[tid][1]);
                ((float2*)erp)[row] = make_float2(sEr[tid][0], sEr[tid][1]);
            }
        }
    }
}

// ---------------- CSR scan + scatter ----------------
__global__ __launch_bounds__(1024) void scan_kernel(const int* __restrict__ deg,
                                                    int* __restrict__ off,
                                                    int* __restrict__ fill, int n) {
    __shared__ int sums[1024];
    int t = threadIdx.x;
    int chunk = (n + 1023) / 1024;
    int begin = t * chunk;
    int end = begin + chunk;
    if (end > n) end = n;
    if (begin > n) begin = n;
    int s = 0;
    for (int i = begin; i < end; i++) s += deg[i];
    sums[t] = s;
    __syncthreads();
    for (int d = 1; d < 1024; d <<= 1) {
        int v = (t >= d) ? sums[t - d] : 0;
        __syncthreads();
        sums[t] += v;
        __syncthreads();
    }
    int run = (t == 0) ? 0 : sums[t - 1];
    for (int i = begin; i < end; i++) {
        off[i] = run;
        fill[i] = run;
        run += deg[i];
    }
    if (t == 1023) off[n] = sums[1023];
}

__global__ void scatter_kernel(const int* __restrict__ src, const int* __restrict__ dst,
                               int* __restrict__ fill, int* __restrict__ csrsrc, int e) {
    for (int i = blockIdx.x * blockDim.x + threadIdx.x; i < e; i += gridDim.x * blockDim.x) {
        int pos = atomicAdd(&fill[dst[i]], 1);
        csrsrc[pos] = src[i];
    }
}

// ---------------- per-node fused edge-softmax + aggregation (device fn) ----------------
template <int VEC>
__device__ __forceinline__ void gather_step(float* acc, const float* row, float w) {
    if (VEC == 4) {
        float4 v = *(const float4*)row;
        acc[0] = fmaf(v.x, w, acc[0]);
        acc[1] = fmaf(v.y, w, acc[1]);
        acc[2] = fmaf(v.z, w, acc[2]);
        acc[3] = fmaf(v.w, w, acc[3]);
    } else {
        float2 v = *(const float2*)row;
        acc[0] = fmaf(v.x, w, acc[0]);
        acc[1] = fmaf(v.y, w, acc[1]);
    }
}

template <int HD, int ACT, int MEAN, int WB, int OF>
__device__ __forceinline__ void agg_node(
    int node, int lane, const float* __restrict__ hbuf, const float* __restrict__ el,
    const float* __restrict__ er, const int* __restrict__ off, const int* __restrict__ csr,
    const float* __restrict__ resbuf, float* __restrict__ out,
    __nv_bfloat16* __restrict__ bfh, __nv_bfloat16* __restrict__ bfl, int colofs) {
    constexpr int VEC = HD / 32;
    int start = off[node], end = off[node + 1];
    int deg = end - start;
    float2 erh = ((const float2*)er)[node];
    bool hi = lane >= 16;

    float acc[VEC];
#pragma unroll
    for (int d = 0; d < VEC; d++) acc[d] = 0.f;

    if (deg <= 32) {
        int i = start + lane;
        bool valid = i < end;
        int sv = 0;
        float e0 = -1e30f, e1 = -1e30f;
        if (valid) {
            sv = csr[i];
            float2 ev = ((const float2*)el)[sv];
            e0 = ev.x + erh.x;
            e0 = e0 > 0.f ? e0 : 0.2f * e0;
            e1 = ev.y + erh.y;
            e1 = e1 > 0.f ? e1 : 0.2f * e1;
        }
        float m0 = e0, s0 = valid ? 1.f : 0.f;
        float m1 = e1, s1 = valid ? 1.f : 0.f;
#pragma unroll
        for (int o = 16; o; o >>= 1) {
            float mo = __shfl_xor_sync(0xffffffffu, m0, o);
            float so = __shfl_xor_sync(0xffffffffu, s0, o);
            float M = fmaxf(m0, mo);
            s0 = s0 * __expf(m0 - M) + so * __expf(mo - M);
            m0 = M;
            mo = __shfl_xor_sync(0xffffffffu, m1, o);
            so = __shfl_xor_sync(0xffffffffu, s1, o);
            M = fmaxf(m1, mo);
            s1 = s1 * __expf(m1 - M) + so * __expf(mo - M);
            m1 = M;
        }
        float inv0 = (s0 > 0.f) ? 1.f / s0 : 0.f;
        float inv1 = (s1 > 0.f) ? 1.f / s1 : 0.f;
        float w0 = __expf(e0 - m0) * inv0;
        float w1 = __expf(e1 - m1) * inv1;

#pragma unroll 8
        for (int j = 0; j < deg; j++) {
            int sj = __shfl_sync(0xffffffffu, sv, j);
            float wj0 = __shfl_sync(0xffffffffu, w0, j);
            float wj1 = __shfl_sync(0xffffffffu, w1, j);
            gather_step<VEC>(acc, hbuf + (size_t)sj * HD + lane * VEC, hi ? wj1 : wj0);
        }
    } else {
        float m0 = -1e30f, s0 = 0.f, m1 = -1e30f, s1 = 0.f;
        for (int i = start + lane; i < end; i += 32) {
            float2 ev = ((const float2*)el)[csr[i]];
            float e0 = ev.x + erh.x;
            e0 = e0 > 0.f ? e0 : 0.2f * e0;
            float e1 = ev.y + erh.y;
            e1 = e1 > 0.f ? e1 : 0.2f * e1;
            float M0 = fmaxf(m0, e0);
            s0 = s0 * __expf(m0 - M0) + __expf(e0 - M0);
            m0 = M0;
            float M1 = fmaxf(m1, e1);
            s1 = s1 * __expf(m1 - M1) + __expf(e1 - M1);
            m1 = M1;
        }
#pragma unroll
        for (int o = 16; o; o >>= 1) {
            float mo = __shfl_xor_sync(0xffffffffu, m0, o);
            float so = __shfl_xor_sync(0xffffffffu, s0, o);
            float M = fmaxf(m0, mo);
            s0 = s0 * __expf(m0 - M) + so * __expf(mo - M);
            m0 = M;
            mo = __shfl_xor_sync(0xffffffffu, m1, o);
            so = __shfl_xor_sync(0xffffffffu, s1, o);
            M = fmaxf(m1, mo);
            s1 = s1 * __expf(m1 - M) + so * __expf(mo - M);
            m1 = M;
        }
        float inv0 = (s0 > 0.f) ? 1.f / s0 : 0.f;
        float inv1 = (s1 > 0.f) ? 1.f / s1 : 0.f;

        for (int t = start; t < end; t += 32) {
            int i = t + lane;
            int s = 0;
            float w0 = 0.f, w1 = 0.f;
            if (i < end) {
                s = csr[i];
                float2 ev = ((const float2*)el)[s];
                float e0 = ev.x + erh.x;
                e0 = e0 > 0.f ? e0 : 0.2f * e0;
                float e1 = ev.y + erh.y;
                e1 = e1 > 0.f ? e1 : 0.2f * e1;
                w0 = __expf(e0 - m0) * inv0;
                w1 = __expf(e1 - m1) * inv1;
            }
            int cnt = min(32, end - t);
#pragma unroll 8
            for (int j = 0; j < cnt; j++) {
                int sj = __shfl_sync(0xffffffffu, s, j);
                float wj0 = __shfl_sync(0xffffffffu, w0, j);
                float wj1 = __shfl_sync(0xffffffffu, w1, j);
                gather_step<VEC>(acc, hbuf + (size_t)sj * HD + lane * VEC, hi ? wj1 : wj0);
            }
        }
    }

    size_t base = (size_t)node * HD + lane * VEC;
    float v[4];
    if (VEC == 4) {
        float4 r = *(const float4*)(resbuf + base);
        v[0] = acc[0] + r.x;
        v[1] = acc[1] + r.y;
        v[2] = acc[2] + r.z;
        v[3] = acc[3] + r.w;
    } else {
        float2 r = *(const float2*)(resbuf + base);
        v[0] = acc[0] + r.x;
        v[1] = acc[1] + r.y;
    }
#pragma unroll
    for (int d = 0; d < VEC; d++)
        v[d] = (ACT == 0) ? (v[d] > 0.f ? v[d] : expm1f(v[d])) : tanhf(v[d]);

    if (MEAN) {
        float o[4];
#pragma unroll
        for (int d = 0; d < VEC; d++) {
            float vo = __shfl_xor_sync(0xffffffffu, v[d], 16);
            o[d] = 0.5f * (v[d] + vo);
        }
        if (lane < 16)
            *(float4*)(out + (size_t)node * 64 + lane * 4) = make_float4(o[0], o[1], o[2], o[3]);
    } else if (OF) {
        if (VEC == 4)
            *(float4*)(out + base) = make_float4(v[0], v[1], v[2], v[3]);
        else
            *(float2*)(out + base) = make_float2(v[0], v[1]);
    }
    if (WB) {
        __nv_bfloat16 hb[4], lb[4];
#pragma unroll
        for (int d = 0; d < VEC; d++) cvt_hilo(v[d], hb[d], lb[d]);
        size_t bo = (size_t)node * 192 + colofs + lane * VEC;
        if (VEC == 4) {
            *(uint2*)(bfh + bo) = make_uint2(pack2(hb[0], hb[1]), pack2(hb[2], hb[3]));
            *(uint2*)(bfl + bo) = make_uint2(pack2(lb[0], lb[1]), pack2(lb[2], lb[3]));
        } else {
            *(uint32_t*)(bfh + bo) = pack2(hb[0], hb[1]);
            *(uint32_t*)(bfl + bo) = pack2(lb[0], lb[1]);
        }
    }
}

// combined aggregation: warps [0,n) = gat (HD=128, ELU, bf16 col0); warps [n,2n) = pg
// (HD=64, tanh, fp32 out + bf16 col128).
__global__ __launch_bounds__(256) void agg_combo_kernel(
    const float* __restrict__ hg, const float* __restrict__ elg, const float* __restrict__ erg,
    const float* __restrict__ resg,
    const float* __restrict__ hp, const float* __restrict__ elp, const float* __restrict__ erp,
    const float* __restrict__ resp, float* __restrict__ outp,
    const int* __restrict__ off, const int* __restrict__ csr,
    __nv_bfloat16* __restrict__ bfh, __nv_bfloat16* __restrict__ bfl, int n) {
    int wg = (blockIdx.x * blockDim.x + threadIdx.x) >> 5;
    int lane = threadIdx.x & 31;
    if (wg < n) {
        agg_node<128, 0, 0, 1, 0>(wg, lane, hg, elg, erg, off, csr, resg, nullptr, bfh, bfl, 0);
    } else if (wg < 2 * n) {
        agg_node<64, 1, 0, 1, 1>(wg - n, lane, hp, elp, erp, off, csr, resp, outp, bfh, bfl,
                                 128);
    }
}

// final layer: gat aggregation + ELU + head-mean into d_out
__global__ __launch_bounds__(256) void agg_mean_kernel(
    const float* __restrict__ hg, const float* __restrict__ elg, const float* __restrict__ erg,
    const float* __restrict__ resg, float* __restrict__ out,
    const int* __restrict__ off, const int* __restrict__ csr, int n) {
    int wg = (blockIdx.x * blockDim.x + threadIdx.x) >> 5;
    int lane = threadIdx.x & 31;
    if (wg < n)
        agg_node<128, 0, 1, 0, 1>(wg, lane, hg, elg, erg, off, csr, resg, out, nullptr, nullptr,
                                  0);
}

// ---------------- host ----------------
template <typename T>
static T* symaddr(const void* sym) {
    void* p = nullptr;
    cudaGetSymbolAddress(&p, sym);
    return (T*)p;
}

extern "C" void kernel_launch(void* const* d_in, const int* in_sizes, int n_in,
                              void* d_out, int out_size) {
    const float* fvs = (const float*)d_in[0];
    const float* pos = (const float*)d_in[1];
    const int* src = (const int*)d_in[2];
    const int* dst = (const int*)d_in[3];
    const float* gW[3] = {(const float*)d_in[4], (const float*)d_in[8], (const float*)d_in[12]};
    const float* gal[3] = {(const float*)d_in[5], (const float*)d_in[9], (const float*)d_in[13]};
    const float* gar[3] = {(const float*)d_in[6], (const float*)d_in[10], (const float*)d_in[14]};
    const float* grW[3] = {(const float*)d_in[7], (const float*)d_in[11], (const float*)d_in[15]};
    const float* pW[2] = {(const float*)d_in[16], (const float*)d_in[19]};
    const float* pal[2] = {(const float*)d_in[17], (const float*)d_in[20]};
    const float* par[2] = {(const float*)d_in[18], (const float*)d_in[21]};

    int n = in_sizes[0] / 128;
    int e = in_sizes[2];
    float* out = (float*)d_out;
    float* out_hs = out;                   // [N,64]
    float* out_hp = out + (size_t)n * 64;  // [N,64]

    float* hB = symaddr<float>(g_h);
    float* resB = symaddr<float>(g_res);
    float* elB = symaddr<float>(g_el);
    float* erB = symaddr<float>(g_er);
    float* hpB = symaddr<float>(g_hp);
    float* elpB = symaddr<float>(g_elp);
    float* erpB = symaddr<float>(g_erp);
    float* p1B = symaddr<float>(g_p1);
    int* degB = symaddr<int>(g_deg);
    int* offB = symaddr<int>(g_off);
    int* fillB = symaddr<int>(g_fill);
    int* csrB = symaddr<int>(g_csrsrc);
    __nv_bfloat16* b0h = symaddr<__nv_bfloat16>(g_b0h);
    __nv_bfloat16* b0l = symaddr<__nv_bfloat16>(g_b0l);
    __nv_bfloat16* b1h = symaddr<__nv_bfloat16>(g_b1h);
    __nv_bfloat16* b1l = symaddr<__nv_bfloat16>(g_b1l);
    __nv_bfloat16* wh = symaddr<__nv_bfloat16>(g_wh);
    __nv_bfloat16* wl = symaddr<__nv_bfloat16>(g_wl);

    const int SMEM_COMBO = 196608;  // dual path: 2 x 96KB; pg path uses 96KB
    cudaFuncSetAttribute(gemm_combo_kernel, cudaFuncAttributeMaxDynamicSharedMemorySize,
                         SMEM_COMBO);

    const int TB = 256;
    int nbdual = (n + 127) / 128;           // 391
    int nbpg = (n + 255) / 256;             // 196
    int combo_grid = nbdual + nbpg;         // 587
    int aggc_blocks = (2 * n * 32 + TB - 1) / TB;  // 12500
    int aggm_blocks = (n * 32 + TB - 1) / TB;

    const __nv_bfloat16* wpg0h = wh + 6 * 24576;
    const __nv_bfloat16* wpg0l = wl + 6 * 24576;
    const __nv_bfloat16* wpg1h = wh + 6 * 24576 + 4096;
    const __nv_bfloat16* wpg1l = wl + 6 * 24576 + 4096;

    // ---- setup + CSR ----
    cudaMemsetAsync(degB, 0, (size_t)n * sizeof(int));
    fsetup<<<2048, TB>>>(fvs, pos, dst, degB, n, e);
    wsetup_dual<<<(18432 + TB - 1) / TB, TB>>>(gW[0], grW[0], gW[1], grW[1], gW[2], grW[2]);
    wsetup_pg<<<(1024 + TB - 1) / TB, TB>>>(pW[0], pW[1]);
    scan_kernel<<<1, 1024>>>(degB, offB, fillB, n);
    scatter_kernel<<<(e + TB - 1) / TB, TB>>>(src, dst, fillB, csrB, e);

    // ---- layer 0: gat0 + pg0 in one GEMM launch, one agg launch ----
    gemm_combo_kernel<<<combo_grid, 512, SMEM_COMBO>>>(
        b0h, b0l, wh, wl, gal[0], gar[0], hB, resB, elB, erB,
        wpg0h, wpg0l, pal[0], par[0], hpB, elpB, erpB, nbdual, n);
    agg_combo_kernel<<<aggc_blocks, TB>>>(hB, elB, erB, resB, hpB, elpB, erpB, pos, p1B, offB,
                                          csrB, b1h, b1l, n);

    // ---- layer 1: gat1 + pg1 ----
    gemm_combo_kernel<<<combo_grid, 512, SMEM_COMBO>>>(
        b1h, b1l, wh + 2 * 24576, wl + 2 * 24576, gal[1], gar[1], hB, resB, elB, erB,
        wpg1h, wpg1l, pal[1], par[1], hpB, elpB, erpB, nbdual, n);
    agg_combo_kernel<<<aggc_blocks, TB>>>(hB, elB, erB, resB, hpB, elpB, erpB, p1B, out_hp,
                                          offB, csrB, b0h, b0l, n);

    // ---- layer 2: gat2 only -> elu -> head mean ----
    gemm_combo_kernel<<<nbdual, 512, SMEM_COMBO>>>(
        b0h, b0l, wh + 4 * 24576, wl + 4 * 24576, gal[2], gar[2], hB, resB, elB, erB,
        wpg0h, wpg0l, pal[0], par[0], hpB, elpB, erpB, nbdual, n);
    agg_mean_kernel<<<aggm_blocks, TB>>>(hB, elB, erB, resB, out_hs, offB, csrB, n);
}

// round 15
// speedup vs baseline: 2.9749x; 1.1661x over previous
#include <cuda_runtime.h>
#include <cuda_bf16.h>
#include <math.h>
#include <cstdint>

// Problem-fixed maxima (setup_inputs: N=50000, E=800000)
#define NMAXC 50000
#define EMAXC 800000
#define NPAD 50176  // 196 * 256

// ---------------- scratch (static __device__ — no allocs allowed) ----------------
__device__ __align__(16) float g_h[NMAXC * 128];
__device__ __align__(16) float g_res[NMAXC * 128];
__device__ __align__(16) float g_el[NMAXC * 2];
__device__ __align__(16) float g_er[NMAXC * 2];
__device__ __align__(16) float g_hp[NMAXC * 64];
__device__ __align__(16) float g_elp[NMAXC * 2];
__device__ __align__(16) float g_erp[NMAXC * 2];
__device__ __align__(16) float g_p1[NMAXC * 64];
__device__ int g_deg[NMAXC];
__device__ int g_off[NMAXC + 1];
__device__ int g_fill[NMAXC];
__device__ int g_bsum[256];
__device__ int g_csrsrc[EMAXC];
// bf16 hi/lo activation buffers, 192 cols each (concat layout), padded rows
__device__ __align__(16) __nv_bfloat16 g_b0h[NPAD * 192];
__device__ __align__(16) __nv_bfloat16 g_b0l[NPAD * 192];
__device__ __align__(16) __nv_bfloat16 g_b1h[NPAD * 192];
__device__ __align__(16) __nv_bfloat16 g_b1l[NPAD * 192];
// preconverted weights: 6 dual mats (3 chunks x 128n x 64k = 24576) + 2 pg (64n x 64k = 4096)
__device__ __align__(16) __nv_bfloat16 g_wh[6 * 24576 + 2 * 4096];
__device__ __align__(16) __nv_bfloat16 g_wl[6 * 24576 + 2 * 4096];

// ---------------- helpers ----------------
__device__ __forceinline__ void mma16816(float* c, const uint32_t* a, uint32_t b0, uint32_t b1) {
    asm volatile(
        "mma.sync.aligned.m16n8k16.row.col.f32.bf16.bf16.f32 "
        "{%0,%1,%2,%3}, {%4,%5,%6,%7}, {%8,%9}, {%0,%1,%2,%3};"
        : "+f"(c[0]), "+f"(c[1]), "+f"(c[2]), "+f"(c[3])
        : "r"(a[0]), "r"(a[1]), "r"(a[2]), "r"(a[3]), "r"(b0), "r"(b1));
}
__device__ __forceinline__ void ldsm4(uint32_t* r, uint32_t a) {
    asm volatile("ldmatrix.sync.aligned.m8n8.x4.shared.b16 {%0,%1,%2,%3}, [%4];"
                 : "=r"(r[0]), "=r"(r[1]), "=r"(r[2]), "=r"(r[3]) : "r"(a));
}
__device__ __forceinline__ uint32_t smem_u32(const void* p) {
    uint32_t a;
    asm("{ .reg .u64 t; cvta.to.shared.u64 t, %1; cvt.u32.u64 %0, t; }" : "=r"(a) : "l"(p));
    return a;
}
__device__ __forceinline__ void cp16(uint32_t saddr, const void* g) {
    asm volatile("cp.async.cg.shared.global [%0], [%1], 16;" :: "r"(saddr), "l"(g));
}
__device__ __forceinline__ void cp_commit() { asm volatile("cp.async.commit_group;" ::: "memory"); }
template <int N>
__device__ __forceinline__ void cp_wait() {
    asm volatile("cp.async.wait_group %0;" :: "n"(N) : "memory");
}
__device__ __forceinline__ void cvt_hilo(float v, __nv_bfloat16& hi, __nv_bfloat16& lo) {
    hi = __float2bfloat16(v);
    lo = __float2bfloat16(v - __bfloat162float(hi));
}
__device__ __forceinline__ uint32_t pack2(__nv_bfloat16 a, __nv_bfloat16 b) {
    __nv_bfloat162 t = __halves2bfloat162(a, b);
    return *(uint32_t*)&t;
}

// ---------------- setup kernels ----------------
__global__ void wsetup_dual(const float* W0, const float* W1, const float* W2,
                            const float* W3, const float* W4, const float* W5) {
    int idx = blockIdx.x * blockDim.x + threadIdx.x;
    if (idx >= 6 * 3 * 1024) return;
    int mat = idx / 3072;
    int r = idx % 3072;
    int c = r >> 10;
    int w = r & 1023;
    int n = w & 127, u = w >> 7;
    const float* Ws[6] = {W0, W1, W2, W3, W4, W5};
    const float* W = Ws[mat];
    uint32_t hp[4], lp[4];
#pragma unroll
    for (int j2 = 0; j2 < 4; j2++) {
        __nv_bfloat16 h0, l0, h1, l1;
        cvt_hilo(W[(c * 64 + u * 8 + 2 * j2) * 128 + n], h0, l0);
        cvt_hilo(W[(c * 64 + u * 8 + 2 * j2 + 1) * 128 + n], h1, l1);
        hp[j2] = pack2(h0, h1);
        lp[j2] = pack2(l0, l1);
    }
    int off = mat * 24576 + c * 8192 + n * 64 + ((u ^ (n & 7)) * 8);
    *(uint4*)(g_wh + off) = make_uint4(hp[0], hp[1], hp[2], hp[3]);
    *(uint4*)(g_wl + off) = make_uint4(lp[0], lp[1], lp[2], lp[3]);
}

__global__ void wsetup_pg(const float* W0, const float* W1) {
    int idx = blockIdx.x * blockDim.x + threadIdx.x;
    if (idx >= 2 * 512) return;
    int mat = idx >> 9;
    int w = idx & 511;
    int n = w & 63, u = w >> 6;
    const float* W = mat ? W1 : W0;
    uint32_t hp[4], lp[4];
#pragma unroll
    for (int j2 = 0; j2 < 4; j2++) {
        __nv_bfloat16 h0, l0, h1, l1;
        cvt_hilo(W[(u * 8 + 2 * j2) * 64 + n], h0, l0);
        cvt_hilo(W[(u * 8 + 2 * j2 + 1) * 64 + n], h1, l1);
        hp[j2] = pack2(h0, h1);
        lp[j2] = pack2(l0, l1);
    }
    int off = 6 * 24576 + mat * 4096 + n * 64 + ((u ^ (n & 7)) * 8);
    *(uint4*)(g_wh + off) = make_uint4(hp[0], hp[1], hp[2], hp[3]);
    *(uint4*)(g_wl + off) = make_uint4(lp[0], lp[1], lp[2], lp[3]);
}

// fsetup: feature conversion + edge degree count (fused; deg must be pre-zeroed)
__global__ void fsetup(const float* __restrict__ fvs, const float* __restrict__ pos,
                       const int* __restrict__ dst, int* __restrict__ deg, int n, int e) {
    int stride = gridDim.x * blockDim.x;
    int total = n * 48;
    for (int idx = blockIdx.x * blockDim.x + threadIdx.x; idx < total; idx += stride) {
        int node, col;
        const float* src;
        if (idx < n * 32) {
            node = idx >> 5;
            col = (idx & 31) * 4;
            src = fvs + (size_t)node * 128 + col;
        } else {
            int t = idx - n * 32;
            node = t >> 4;
            col = (t & 15) * 4;
            src = pos + (size_t)node * 64 + col;
            col += 128;
        }
        float4 v = *(const float4*)src;
        __nv_bfloat16 h0, h1, h2, h3, l0, l1, l2, l3;
        cvt_hilo(v.x, h0, l0);
        cvt_hilo(v.y, h1, l1);
        cvt_hilo(v.z, h2, l2);
        cvt_hilo(v.w, h3, l3);
        size_t bo = (size_t)node * 192 + col;
        *(uint2*)(g_b0h + bo) = make_uint2(pack2(h0, h1), pack2(h2, h3));
        *(uint2*)(g_b0l + bo) = make_uint2(pack2(l0, l1), pack2(l2, l3));
    }
    for (int i = blockIdx.x * blockDim.x + threadIdx.x; i < e; i += stride)
        atomicAdd(&deg[dst[i]], 1);
}

// ---------------- parallel 3-phase scan ----------------
__global__ __launch_bounds__(256) void scan1_kernel(const int* __restrict__ deg,
                                                    int* __restrict__ bsum, int n) {
    __shared__ int sm[256];
    int i = blockIdx.x * 256 + threadIdx.x;
    sm[threadIdx.x] = (i < n) ? deg[i] : 0;
    __syncthreads();
#pragma unroll
    for (int d = 128; d; d >>= 1) {
        if (threadIdx.x < d) sm[threadIdx.x] += sm[threadIdx.x + d];
        __syncthreads();
    }
    if (threadIdx.x == 0) bsum[blockIdx.x] = sm[0];
}

__global__ __launch_bounds__(256) void scan2_kernel(int* __restrict__ bsum, int nb) {
    __shared__ int sm[256];
    int t = threadIdx.x;
    sm[t] = (t < nb) ? bsum[t] : 0;
    __syncthreads();
#pragma unroll
    for (int d = 1; d < 256; d <<= 1) {
        int v = (t >= d) ? sm[t - d] : 0;
        __syncthreads();
        sm[t] += v;
        __syncthreads();
    }
    if (t < nb) bsum[t] = sm[t];  // inclusive
}

__global__ __launch_bounds__(256) void scan3_kernel(const int* __restrict__ deg,
                                                    const int* __restrict__ bsum,
                                                    int* __restrict__ off,
                                                    int* __restrict__ fill, int n) {
    __shared__ int sm[256];
    int b = blockIdx.x;
    int t = threadIdx.x;
    int i = b * 256 + t;
    int v = (i < n) ? deg[i] : 0;
    sm[t] = v;
    __syncthreads();
#pragma unroll
    for (int d = 1; d < 256; d <<= 1) {
        int u = (t >= d) ? sm[t - d] : 0;
        __syncthreads();
        sm[t] += u;
        __syncthreads();
    }
    int base = (b > 0) ? bsum[b - 1] : 0;
    int excl = base + sm[t] - v;
    if (i < n) {
        off[i] = excl;
        fill[i] = excl;
        if (i == n - 1) off[n] = excl + v;
    }
}

__global__ void scatter_kernel(const int* __restrict__ src, const int* __restrict__ dst,
                               int* __restrict__ fill, int* __restrict__ csrsrc, int e) {
    for (int i = blockIdx.x * blockDim.x + threadIdx.x; i < e; i += gridDim.x * blockDim.x) {
        int pos = atomicAdd(&fill[dst[i]], 1);
        csrsrc[pos] = src[i];
    }
}

// ---------------- combined GEMM: dual-gat blocks + pg blocks in one grid ----------------
__global__ __launch_bounds__(512) void gemm_combo_kernel(
    const __nv_bfloat16* __restrict__ Ah, const __nv_bfloat16* __restrict__ Al,
    const __nv_bfloat16* __restrict__ wdh, const __nv_bfloat16* __restrict__ wdl,
    const float* __restrict__ attLg, const float* __restrict__ attRg,
    float* __restrict__ C1, float* __restrict__ C2,
    float* __restrict__ elg, float* __restrict__ erg,
    const __nv_bfloat16* __restrict__ wph, const __nv_bfloat16* __restrict__ wpl,
    const float* __restrict__ attLp, const float* __restrict__ attRp,
    float* __restrict__ Cp, float* __restrict__ elp, float* __restrict__ erp,
    int nbdual, int nrows) {
    extern __shared__ char smem[];
    uint32_t sbase = smem_u32(smem);
    __shared__ float sEl[256][2];
    __shared__ float sEr[256][2];

    int tid = threadIdx.x, lane = tid & 31;
    int g = lane >> 2, tg = lane & 3;
    int laneq = lane >> 4;
    int lane8 = (lane >> 3) & 1;

    if (tid < 256) {
        sEl[tid][0] = 0.f;
        sEl[tid][1] = 0.f;
        sEr[tid][0] = 0.f;
        sEr[tid][1] = 0.f;
    }

    if (blockIdx.x < nbdual) {
        // ================= dual GAT path (512 threads, BM=128, BN=128, K=192) =========
        const int SA_L = 16384, SB = 32768, BUFSZ = 98304;
        int wid = tid >> 5;
        int m0 = blockIdx.x * 128;
        int wm = (wid & 3) * 32;
        int wn = (wid >> 2) * 32;

        uint32_t aAddr[2];
        int aSw[2];
#pragma unroll
        for (int mt = 0; mt < 2; mt++) {
            int r = wm + mt * 16 + (lane & 15);
            aAddr[mt] = sbase + r * 128;
            aSw[mt] = r & 7;
        }
        uint32_t bAddr[2];
        int bSw[2];
#pragma unroll
        for (int q = 0; q < 2; q++) {
            int nr = wn + (q * 2 + laneq) * 8 + (lane & 7);
            bAddr[q] = sbase + SB + nr * 128;
            bSw[q] = nr & 7;
        }

        auto fill = [&](int c, int buf) {
            uint32_t sb = sbase + buf * BUFSZ;
#pragma unroll
            for (int t = 0; t < 4; t++) {
                int s = tid + t * 512;
                int pl = s >> 10, w = s & 1023;
                int m = w >> 3, u = w & 7;
                const __nv_bfloat16* src =
                    (pl ? Al : Ah) + (size_t)(m0 + m) * 192 + c * 64 + u * 8;
                cp16(sb + pl * SA_L + m * 128 + ((u ^ (m & 7)) << 4), src);
            }
#pragma unroll
            for (int t = 0; t < 8; t++) {
                int s = tid + t * 512;
                int pl = s >> 10, w = s & 1023;
                const __nv_bfloat16* src = (pl & 1) ? wdl : wdh;
                src += (pl >> 1) * 24576 + c * 8192 + w * 8;
                cp16(sb + SB + pl * 16384 + w * 16, src);
            }
            cp_commit();
        };

        float acc[2][2][4][4];
#pragma unroll
        for (int c = 0; c < 2; c++)
#pragma unroll
            for (int mt = 0; mt < 2; mt++)
#pragma unroll
                for (int nt = 0; nt < 4; nt++)
#pragma unroll
                    for (int r = 0; r < 4; r++) acc[c][mt][nt][r] = 0.f;

        fill(0, 0);
#pragma unroll
        for (int c = 0; c < 3; c++) {
            int buf = c & 1;
            uint32_t bofs = buf * BUFSZ;
            if (c) __syncthreads();
            if (c < 2) fill(c + 1, (c + 1) & 1);
            if (c < 2)
                cp_wait<1>();
            else
                cp_wait<0>();
            __syncthreads();

#pragma unroll
            for (int kk = 0; kk < 4; kk++) {
                uint32_t ah[2][4], alr[2][4];
#pragma unroll
                for (int mt = 0; mt < 2; mt++) {
                    uint32_t ad = aAddr[mt] + bofs + (((2 * kk + laneq) ^ aSw[mt]) << 4);
                    ldsm4(ah[mt], ad);
                    ldsm4(alr[mt], ad + 16384);
                }
#pragma unroll
                for (int q = 0; q < 2; q++) {
                    uint32_t bd = bAddr[q] + bofs + (((2 * kk + lane8) ^ bSw[q]) << 4);
                    uint32_t f1h[4], f1l[4], f2h[4], f2l[4];
                    ldsm4(f1h, bd);
                    ldsm4(f1l, bd + 16384);
                    ldsm4(f2h, bd + 32768);
                    ldsm4(f2l, bd + 49152);
#pragma unroll
                    for (int t2 = 0; t2 < 2; t2++) {
                        int nt = q * 2 + t2;
#pragma unroll
                        for (int mt = 0; mt < 2; mt++) {
                            mma16816(acc[0][mt][nt], ah[mt], f1h[2 * t2], f1h[2 * t2 + 1]);
                            mma16816(acc[0][mt][nt], alr[mt], f1h[2 * t2], f1h[2 * t2 + 1]);
                            mma16816(acc[0][mt][nt], ah[mt], f1l[2 * t2], f1l[2 * t2 + 1]);
                            mma16816(acc[1][mt][nt], ah[mt], f2h[2 * t2], f2h[2 * t2 + 1]);
                            mma16816(acc[1][mt][nt], alr[mt], f2h[2 * t2], f2h[2 * t2 + 1]);
                            mma16816(acc[1][mt][nt], ah[mt], f2l[2 * t2], f2l[2 * t2 + 1]);
                        }
                    }
                }
            }
        }

#pragma unroll
        for (int c = 0; c < 2; c++) {
            float* C = c ? C2 : C1;
#pragma unroll
            for (int mt = 0; mt < 2; mt++) {
                int row0 = m0 + wm + mt * 16 + g;
                int row1 = row0 + 8;
#pragma unroll
                for (int nt = 0; nt < 4; nt++) {
                    int col = wn + nt * 8 + 2 * tg;
                    if (row0 < nrows)
                        *(float2*)(C + (size_t)row0 * 128 + col) =
                            make_float2(acc[c][mt][nt][0], acc[c][mt][nt][1]);
                    if (row1 < nrows)
                        *(float2*)(C + (size_t)row1 * 128 + col) =
                            make_float2(acc[c][mt][nt][2], acc[c][mt][nt][3]);
                }
            }
        }

        // fused attention logits from h (= acc[0]); head = col/64, D=64
        int head = (wn >= 64) ? 1 : 0;
        int cbase = wn & 63;
        float elpv[4] = {0.f, 0.f, 0.f, 0.f}, erpv[4] = {0.f, 0.f, 0.f, 0.f};
#pragma unroll
        for (int nt = 0; nt < 4; nt++) {
            int cih = cbase + nt * 8 + 2 * tg;
            float a0 = attLg[head * 64 + cih], a1 = attLg[head * 64 + cih + 1];
            float b0 = attRg[head * 64 + cih], b1 = attRg[head * 64 + cih + 1];
#pragma unroll
            for (int mt = 0; mt < 2; mt++) {
                elpv[mt * 2 + 0] += acc[0][mt][nt][0] * a0 + acc[0][mt][nt][1] * a1;
                erpv[mt * 2 + 0] += acc[0][mt][nt][0] * b0 + acc[0][mt][nt][1] * b1;
                elpv[mt * 2 + 1] += acc[0][mt][nt][2] * a0 + acc[0][mt][nt][3] * a1;
                erpv[mt * 2 + 1] += acc[0][mt][nt][2] * b0 + acc[0][mt][nt][3] * b1;
            }
        }
#pragma unroll
        for (int sl = 0; sl < 4; sl++) {
            float ev = elpv[sl], rv = erpv[sl];
            ev += __shfl_xor_sync(0xffffffffu, ev, 1);
            ev += __shfl_xor_sync(0xffffffffu, ev, 2);
            rv += __shfl_xor_sync(0xffffffffu, rv, 1);
            rv += __shfl_xor_sync(0xffffffffu, rv, 2);
            if (tg == 0) {
                int rl = wm + (sl >> 1) * 16 + g + (sl & 1) * 8;
                atomicAdd(&sEl[rl][head], ev);
                atomicAdd(&sEr[rl][head], rv);
            }
        }
        __syncthreads();
        if (tid < 128) {
            int row = m0 + tid;
            if (row < nrows) {
                ((float2*)elg)[row] = make_float2(sEl[tid][0], sEl[tid][1]);
                ((float2*)erg)[row] = make_float2(sEr[tid][0], sEr[tid][1]);
            }
        }
    } else {
        // ================= pg path: two independent 256-thread halves, BM=128 each ====
        const int SA_L = 16384, SB_H = 32768, SB_L = 40960;
        int half = tid >> 8;
        int htid = tid & 255;
        int hwid = htid >> 5;
        int m0 = (blockIdx.x - nbdual) * 256 + half * 128;
        int m0base = (blockIdx.x - nbdual) * 256;
        uint32_t shalf = sbase + half * 49152;
        int wm = (hwid & 3) * 32;
        int wn = (hwid >> 2) * 32;

        uint32_t aAddr[2];
        int aSw[2];
#pragma unroll
        for (int mt = 0; mt < 2; mt++) {
            int r = wm + mt * 16 + (lane & 15);
            aAddr[mt] = shalf + r * 128;
            aSw[mt] = r & 7;
        }
        uint32_t bAddr[2];
        int bSw[2];
#pragma unroll
        for (int q = 0; q < 2; q++) {
            int nr = wn + (q * 2 + laneq) * 8 + (lane & 7);
            bAddr[q] = shalf + SB_H + nr * 128;
            bSw[q] = nr & 7;
        }

        float acc[2][4][4];
#pragma unroll
        for (int mt = 0; mt < 2; mt++)
#pragma unroll
            for (int nt = 0; nt < 4; nt++)
#pragma unroll
                for (int r = 0; r < 4; r++) acc[mt][nt][r] = 0.f;

#pragma unroll
        for (int t = 0; t < 8; t++) {
            int s = htid + t * 256;
            int pl = s >> 10, w = s & 1023;
            int m = w >> 3, u = w & 7;
            const __nv_bfloat16* src = (pl ? Al : Ah) + (size_t)(m0 + m) * 192 + 128 + u * 8;
            cp16(shalf + pl * SA_L + m * 128 + ((u ^ (m & 7)) << 4), src);
        }
#pragma unroll
        for (int t = 0; t < 4; t++) {
            int s = htid + t * 256;
            int pl = s >> 9, w = s & 511;
            const __nv_bfloat16* src = (pl ? wpl : wph) + w * 8;
            cp16(shalf + (pl ? SB_L : SB_H) + w * 16, src);
        }
        cp_commit();
        cp_wait<0>();
        __syncthreads();

#pragma unroll
        for (int kk = 0; kk < 4; kk++) {
            uint32_t ah[2][4], alr[2][4];
#pragma unroll
            for (int mt = 0; mt < 2; mt++) {
                uint32_t ad = aAddr[mt] + (((2 * kk + laneq) ^ aSw[mt]) << 4);
                ldsm4(ah[mt], ad);
                ldsm4(alr[mt], ad + 16384);
            }
#pragma unroll
            for (int q = 0; q < 2; q++) {
                uint32_t bd = bAddr[q] + (((2 * kk + lane8) ^ bSw[q]) << 4);
                uint32_t fh[4], fl[4];
                ldsm4(fh, bd);
                ldsm4(fl, bd + 8192);
#pragma unroll
                for (int t2 = 0; t2 < 2; t2++) {
                    int nt = q * 2 + t2;
#pragma unroll
                    for (int mt = 0; mt < 2; mt++) {
                        mma16816(acc[mt][nt], ah[mt], fh[2 * t2], fh[2 * t2 + 1]);
                        mma16816(acc[mt][nt], alr[mt], fh[2 * t2], fh[2 * t2 + 1]);
                        mma16816(acc[mt][nt], ah[mt], fl[2 * t2], fl[2 * t2 + 1]);
                    }
                }
            }
        }

#pragma unroll
        for (int mt = 0; mt < 2; mt++) {
            int row0 = m0 + wm + mt * 16 + g;
            int row1 = row0 + 8;
#pragma unroll
            for (int nt = 0; nt < 4; nt++) {
                int col = wn + nt * 8 + 2 * tg;
                if (row0 < nrows)
                    *(float2*)(Cp + (size_t)row0 * 64 + col) =
                        make_float2(acc[mt][nt][0], acc[mt][nt][1]);
                if (row1 < nrows)
                    *(float2*)(Cp + (size_t)row1 * 64 + col) =
                        make_float2(acc[mt][nt][2], acc[mt][nt][3]);
            }
        }

        int head = (wn >= 32) ? 1 : 0;
        int cbase = wn & 31;
        float elpv[4] = {0.f, 0.f, 0.f, 0.f}, erpv[4] = {0.f, 0.f, 0.f, 0.f};
#pragma unroll
        for (int nt = 0; nt < 4; nt++) {
            int cih = cbase + nt * 8 + 2 * tg;
            float a0 = attLp[head * 32 + cih], a1 = attLp[head * 32 + cih + 1];
            float b0 = attRp[head * 32 + cih], b1 = attRp[head * 32 + cih + 1];
#pragma unroll
            for (int mt = 0; mt < 2; mt++) {
                elpv[mt * 2 + 0] += acc[mt][nt][0] * a0 + acc[mt][nt][1] * a1;
                erpv[mt * 2 + 0] += acc[mt][nt][0] * b0 + acc[mt][nt][1] * b1;
                elpv[mt * 2 + 1] += acc[mt][nt][2] * a0 + acc[mt][nt][3] * a1;
                erpv[mt * 2 + 1] += acc[mt][nt][2] * b0 + acc[mt][nt][3] * b1;
            }
        }
#pragma unroll
        for (int sl = 0; sl < 4; sl++) {
            float ev = elpv[sl], rv = erpv[sl];
            ev += __shfl_xor_sync(0xffffffffu, ev, 1);
            ev += __shfl_xor_sync(0xffffffffu, ev, 2);
            rv += __shfl_xor_sync(0xffffffffu, rv, 1);
            rv += __shfl_xor_sync(0xffffffffu, rv, 2);
            if (tg == 0) {
                int rl = half * 128 + wm + (sl >> 1) * 16 + g + (sl & 1) * 8;
                atomicAdd(&sEl[rl][head], ev);
                atomicAdd(&sEr[rl][head], rv);
            }
        }
        __syncthreads();
        if (tid < 256) {
            int row = m0base + tid;
            if (row < nrows) {
                ((float2*)elp)[row] = make_float2(sEl[tid][0], sEl[tid][1]);
                ((float2*)erp)[row] = make_float2(sEr[tid][0], sEr[tid][1]);
            }
        }
    }
}

// ---------------- per-node fused edge-softmax + aggregation (device fn) ----------------
template <int VEC>
__device__ __forceinline__ void gather_step(float* acc, const float* row, float w) {
    if (VEC == 4) {
        float4 v = *(const float4*)row;
        acc[0] = fmaf(v.x, w, acc[0]);
        acc[1] = fmaf(v.y, w, acc[1]);
        acc[2] = fmaf(v.z, w, acc[2]);
        acc[3] = fmaf(v.w, w, acc[3]);
    } else {
        float2 v = *(const float2*)row;
        acc[0] = fmaf(v.x, w, acc[0]);
        acc[1] = fmaf(v.y, w, acc[1]);
    }
}

template <int HD, int ACT, int MEAN, int WB, int OF>
__device__ __forceinline__ void agg_node(
    int node, int lane, const float* __restrict__ hbuf, const float* __restrict__ el,
    const float* __restrict__ er, const int* __restrict__ off, const int* __restrict__ csr,
    const float* __restrict__ resbuf, float* __restrict__ out,
    __nv_bfloat16* __restrict__ bfh, __nv_bfloat16* __restrict__ bfl, int colofs) {
    constexpr int VEC = HD / 32;
    int start = off[node], end = off[node + 1];
    int deg = end - start;
    float2 erh = ((const float2*)er)[node];
    bool hi = lane >= 16;

    float acc[VEC];
#pragma unroll
    for (int d = 0; d < VEC; d++) acc[d] = 0.f;

    if (deg <= 32) {
        int i = start + lane;
        bool valid = i < end;
        int sv = 0;
        float e0 = -1e30f, e1 = -1e30f;
        if (valid) {
            sv = csr[i];
            float2 ev = ((const float2*)el)[sv];
            e0 = ev.x + erh.x;
            e0 = e0 > 0.f ? e0 : 0.2f * e0;
            e1 = ev.y + erh.y;
            e1 = e1 > 0.f ? e1 : 0.2f * e1;
        }
        float m0 = e0, s0 = valid ? 1.f : 0.f;
        float m1 = e1, s1 = valid ? 1.f : 0.f;
#pragma unroll
        for (int o = 16; o; o >>= 1) {
            float mo = __shfl_xor_sync(0xffffffffu, m0, o);
            float so = __shfl_xor_sync(0xffffffffu, s0, o);
            float M = fmaxf(m0, mo);
            s0 = s0 * __expf(m0 - M) + so * __expf(mo - M);
            m0 = M;
            mo = __shfl_xor_sync(0xffffffffu, m1, o);
            so = __shfl_xor_sync(0xffffffffu, s1, o);
            M = fmaxf(m1, mo);
            s1 = s1 * __expf(m1 - M) + so * __expf(mo - M);
            m1 = M;
        }
        float inv0 = (s0 > 0.f) ? 1.f / s0 : 0.f;
        float inv1 = (s1 > 0.f) ? 1.f / s1 : 0.f;
        float w0 = __expf(e0 - m0) * inv0;
        float w1 = __expf(e1 - m1) * inv1;

#pragma unroll 8
        for (int j = 0; j < deg; j++) {
            int sj = __shfl_sync(0xffffffffu, sv, j);
            float wj0 = __shfl_sync(0xffffffffu, w0, j);
            float wj1 = __shfl_sync(0xffffffffu, w1, j);
            gather_step<VEC>(acc, hbuf + (size_t)sj * HD + lane * VEC, hi ? wj1 : wj0);
        }
    } else {
        float m0 = -1e30f, s0 = 0.f, m1 = -1e30f, s1 = 0.f;
        for (int i = start + lane; i < end; i += 32) {
            float2 ev = ((const float2*)el)[csr[i]];
            float e0 = ev.x + erh.x;
            e0 = e0 > 0.f ? e0 : 0.2f * e0;
            float e1 = ev.y + erh.y;
            e1 = e1 > 0.f ? e1 : 0.2f * e1;
            float M0 = fmaxf(m0, e0);
            s0 = s0 * __expf(m0 - M0) + __expf(e0 - M0);
            m0 = M0;
            float M1 = fmaxf(m1, e1);
            s1 = s1 * __expf(m1 - M1) + __expf(e1 - M1);
            m1 = M1;
        }
#pragma unroll
        for (int o = 16; o; o >>= 1) {
            float mo = __shfl_xor_sync(0xffffffffu, m0, o);
            float so = __shfl_xor_sync(0xffffffffu, s0, o);
            float M = fmaxf(m0, mo);
            s0 = s0 * __expf(m0 - M) + so * __expf(mo - M);
            m0 = M;
            mo = __shfl_xor_sync(0xffffffffu, m1, o);
            so = __shfl_xor_sync(0xffffffffu, s1, o);
            M = fmaxf(m1, mo);
            s1 = s1 * __expf(m1 - M) + so * __expf(mo - M);
            m1 = M;
        }
        float inv0 = (s0 > 0.f) ? 1.f / s0 : 0.f;
        float inv1 = (s1 > 0.f) ? 1.f / s1 : 0.f;

        for (int t = start; t < end; t += 32) {
            int i = t + lane;
            int s = 0;
            float w0 = 0.f, w1 = 0.f;
            if (i < end) {
                s = csr[i];
                float2 ev = ((const float2*)el)[s];
                float e0 = ev.x + erh.x;
                e0 = e0 > 0.f ? e0 : 0.2f * e0;
                float e1 = ev.y + erh.y;
                e1 = e1 > 0.f ? e1 : 0.2f * e1;
                w0 = __expf(e0 - m0) * inv0;
                w1 = __expf(e1 - m1) * inv1;
            }
            int cnt = min(32, end - t);
#pragma unroll 8
            for (int j = 0; j < cnt; j++) {
                int sj = __shfl_sync(0xffffffffu, s, j);
                float wj0 = __shfl_sync(0xffffffffu, w0, j);
                float wj1 = __shfl_sync(0xffffffffu, w1, j);
                gather_step<VEC>(acc, hbuf + (size_t)sj * HD + lane * VEC, hi ? wj1 : wj0);
            }
        }
    }

    size_t base = (size_t)node * HD + lane * VEC;
    float v[4];
    if (VEC == 4) {
        float4 r = *(const float4*)(resbuf + base);
        v[0] = acc[0] + r.x;
        v[1] = acc[1] + r.y;
        v[2] = acc[2] + r.z;
        v[3] = acc[3] + r.w;
    } else {
        float2 r = *(const float2*)(resbuf + base);
        v[0] = acc[0] + r.x;
        v[1] = acc[1] + r.y;
    }
#pragma unroll
    for (int d = 0; d < VEC; d++)
        v[d] = (ACT == 0) ? (v[d] > 0.f ? v[d] : expm1f(v[d])) : tanhf(v[d]);

    if (MEAN) {
        float o[4];
#pragma unroll
        for (int d = 0; d < VEC; d++) {
            float vo = __shfl_xor_sync(0xffffffffu, v[d], 16);
            o[d] = 0.5f * (v[d] + vo);
        }
        if (lane < 16)
            *(float4*)(out + (size_t)node * 64 + lane * 4) = make_float4(o[0], o[1], o[2], o[3]);
    } else if (OF) {
        if (VEC == 4)
            *(float4*)(out + base) = make_float4(v[0], v[1], v[2], v[3]);
        else
            *(float2*)(out + base) = make_float2(v[0], v[1]);
    }
    if (WB) {
        __nv_bfloat16 hb[4], lb[4];
#pragma unroll
        for (int d = 0; d < VEC; d++) cvt_hilo(v[d], hb[d], lb[d]);
        size_t bo = (size_t)node * 192 + colofs + lane * VEC;
        if (VEC == 4) {
            *(uint2*)(bfh + bo) = make_uint2(pack2(hb[0], hb[1]), pack2(hb[2], hb[3]));
            *(uint2*)(bfl + bo) = make_uint2(pack2(lb[0], lb[1]), pack2(lb[2], lb[3]));
        } else {
            *(uint32_t*)(bfh + bo) = pack2(hb[0], hb[1]);
            *(uint32_t*)(bfl + bo) = pack2(lb[0], lb[1]);
        }
    }
}

// combined aggregation: warps [0,n) = gat (HD=128, ELU, bf16 col0); warps [n,2n) = pg
// (HD=64, tanh, fp32 out + bf16 col128).
__global__ __launch_bounds__(256) void agg_combo_kernel(
    const float* __restrict__ hg, const float* __restrict__ elg, const float* __restrict__ erg,
    const float* __restrict__ resg,
    const float* __restrict__ hp, const float* __restrict__ elp, const float* __restrict__ erp,
    const float* __restrict__ resp, float* __restrict__ outp,
    const int* __restrict__ off, const int* __restrict__ csr,
    __nv_bfloat16* __restrict__ bfh, __nv_bfloat16* __restrict__ bfl, int n) {
    int wg = (blockIdx.x * blockDim.x + threadIdx.x) >> 5;
    int lane = threadIdx.x & 31;
    if (wg < n) {
        agg_node<128, 0, 0, 1, 0>(wg, lane, hg, elg, erg, off, csr, resg, nullptr, bfh, bfl, 0);
    } else if (wg < 2 * n) {
        agg_node<64, 1, 0, 1, 1>(wg - n, lane, hp, elp, erp, off, csr, resp, outp, bfh, bfl,
                                 128);
    }
}

// final layer: gat aggregation + ELU + head-mean into d_out
__global__ __launch_bounds__(256) void agg_mean_kernel(
    const float* __restrict__ hg, const float* __restrict__ elg, const float* __restrict__ erg,
    const float* __restrict__ resg, float* __restrict__ out,
    const int* __restrict__ off, const int* __restrict__ csr, int n) {
    int wg = (blockIdx.x * blockDim.x + threadIdx.x) >> 5;
    int lane = threadIdx.x & 31;
    if (wg < n)
        agg_node<128, 0, 1, 0, 1>(wg, lane, hg, elg, erg, off, csr, resg, out, nullptr, nullptr,
                                  0);
}

// ---------------- host ----------------
template <typename T>
static T* symaddr(const void* sym) {
    void* p = nullptr;
    cudaGetSymbolAddress(&p, sym);
    return (T*)p;
}

extern "C" void kernel_launch(void* const* d_in, const int* in_sizes, int n_in,
                              void* d_out, int out_size) {
    const float* fvs = (const float*)d_in[0];
    const float* pos = (const float*)d_in[1];
    const int* src = (const int*)d_in[2];
    const int* dst = (const int*)d_in[3];
    const float* gW[3] = {(const float*)d_in[4], (const float*)d_in[8], (const float*)d_in[12]};
    const float* gal[3] = {(const float*)d_in[5], (const float*)d_in[9], (const float*)d_in[13]};
    const float* gar[3] = {(const float*)d_in[6], (const float*)d_in[10], (const float*)d_in[14]};
    const float* grW[3] = {(const float*)d_in[7], (const float*)d_in[11], (const float*)d_in[15]};
    const float* pW[2] = {(const float*)d_in[16], (const float*)d_in[19]};
    const float* pal[2] = {(const float*)d_in[17], (const float*)d_in[20]};
    const float* par[2] = {(const float*)d_in[18], (const float*)d_in[21]};

    int n = in_sizes[0] / 128;
    int e = in_sizes[2];
    float* out = (float*)d_out;
    float* out_hs = out;                   // [N,64]
    float* out_hp = out + (size_t)n * 64;  // [N,64]

    float* hB = symaddr<float>(g_h);
    float* resB = symaddr<float>(g_res);
    float* elB = symaddr<float>(g_el);
    float* erB = symaddr<float>(g_er);
    float* hpB = symaddr<float>(g_hp);
    float* elpB = symaddr<float>(g_elp);
    float* erpB = symaddr<float>(g_erp);
    float* p1B = symaddr<float>(g_p1);
    int* degB = symaddr<int>(g_deg);
    int* offB = symaddr<int>(g_off);
    int* fillB = symaddr<int>(g_fill);
    int* bsumB = symaddr<int>(g_bsum);
    int* csrB = symaddr<int>(g_csrsrc);
    __nv_bfloat16* b0h = symaddr<__nv_bfloat16>(g_b0h);
    __nv_bfloat16* b0l = symaddr<__nv_bfloat16>(g_b0l);
    __nv_bfloat16* b1h = symaddr<__nv_bfloat16>(g_b1h);
    __nv_bfloat16* b1l = symaddr<__nv_bfloat16>(g_b1l);
    __nv_bfloat16* wh = symaddr<__nv_bfloat16>(g_wh);
    __nv_bfloat16* wl = symaddr<__nv_bfloat16>(g_wl);

    const int SMEM_COMBO = 196608;
    cudaFuncSetAttribute(gemm_combo_kernel, cudaFuncAttributeMaxDynamicSharedMemorySize,
                         SMEM_COMBO);

    const int TB = 256;
    int nbdual = (n + 127) / 128;           // 391
    int nbpg = (n + 255) / 256;             // 196
    int combo_grid = nbdual + nbpg;         // 587
    int aggc_blocks = (2 * n * 32 + TB - 1) / TB;
    int aggm_blocks = (n * 32 + TB - 1) / TB;
    int nscan = (n + 255) / 256;            // 196

    const __nv_bfloat16* wpg0h = wh + 6 * 24576;
    const __nv_bfloat16* wpg0l = wl + 6 * 24576;
    const __nv_bfloat16* wpg1h = wh + 6 * 24576 + 4096;
    const __nv_bfloat16* wpg1l = wl + 6 * 24576 + 4096;

    // ---- setup + CSR ----
    cudaMemsetAsync(degB, 0, (size_t)n * sizeof(int));
    fsetup<<<2048, TB>>>(fvs, pos, dst, degB, n, e);
    wsetup_dual<<<(18432 + TB - 1) / TB, TB>>>(gW[0], grW[0], gW[1], grW[1], gW[2], grW[2]);
    wsetup_pg<<<(1024 + TB - 1) / TB, TB>>>(pW[0], pW[1]);
    scan1_kernel<<<nscan, 256>>>(degB, bsumB, n);
    scan2_kernel<<<1, 256>>>(bsumB, nscan);
    scan3_kernel<<<nscan, 256>>>(degB, bsumB, offB, fillB, n);
    scatter_kernel<<<(e + TB - 1) / TB, TB>>>(src, dst, fillB, csrB, e);

    // ---- layer 0: gat0 + pg0 in one GEMM launch, one agg launch ----
    gemm_combo_kernel<<<combo_grid, 512, SMEM_COMBO>>>(
        b0h, b0l, wh, wl, gal[0], gar[0], hB, resB, elB, erB,
        wpg0h, wpg0l, pal[0], par[0], hpB, elpB, erpB, nbdual, n);
    agg_combo_kernel<<<aggc_blocks, TB>>>(hB, elB, erB, resB, hpB, elpB, erpB, pos, p1B, offB,
                                          csrB, b1h, b1l, n);

    // ---- layer 1: gat1 + pg1 ----
    gemm_combo_kernel<<<combo_grid, 512, SMEM_COMBO>>>(
        b1h, b1l, wh + 2 * 24576, wl + 2 * 24576, gal[1], gar[1], hB, resB, elB, erB,
        wpg1h, wpg1l, pal[1], par[1], hpB, elpB, erpB, nbdual, n);
    agg_combo_kernel<<<aggc_blocks, TB>>>(hB, elB, erB, resB, hpB, elpB, erpB, p1B, out_hp,
                                          offB, csrB, b0h, b0l, n);

    // ---- layer 2: gat2 only -> elu -> head mean ----
    gemm_combo_kernel<<<nbdual, 512, SMEM_COMBO>>>(
        b0h, b0l, wh + 4 * 24576, wl + 4 * 24576, gal[2], gar[2], hB, resB, elB, erB,
        wpg0h, wpg0l, pal[0], par[0], hpB, elpB, erpB, nbdual, n);
    agg_mean_kernel<<<aggm_blocks, TB>>>(hB, elB, erB, resB, out_hs, offB, csrB, n);
}